// round 4
// baseline (speedup 1.0000x reference)
#include <cuda_runtime.h>
#include <math.h>

#define TT 32
#define BBATCH 32
#define HH 512
#define SS 400
#define VV 50000
#define EXTV 50050
#define TB 1024  // TT*BBATCH

// ---------------- scratch (static device arrays; no allocation) ----------------
__device__ float g_x[TB * HH];        // embedded inputs per (t,b)
__device__ float g_out[TB * HH];      // layer-1 h per step (== h[-1] per step)
__device__ float g_call[TB * HH];     // layer-1 c per step (== c[-1] per step)
__device__ float g_hbuf[2 * 2 * BBATCH * HH];  // [layer][parity][b][h]
__device__ float g_cbuf[2 * 2 * BBATCH * HH];
__device__ float g_gamma[TB * HH];
__device__ float g_attn[TB * SS];
__device__ float g_cat2[TB * 2 * HH]; // [c_t | out]
__device__ float g_hatt[TB * HH];
__device__ float g_pgen[TB];
__device__ float g_rmax[TB];
__device__ float g_rinv[TB];
__device__ float g_logits[(size_t)TB * VV];   // 200 MB

// ---------------- embedding + state init ----------------
__global__ void k_embed(const int* __restrict__ ids, const float* __restrict__ emb) {
    int gi = blockIdx.x * blockDim.x + threadIdx.x;   // 0..131071 (1024 rows * 128 float4)
    int r = gi >> 7, e4 = gi & 127;
    int id = ids[r];
    if (id >= VV) id = 1;   // UNK
    float4 v = *(const float4*)(emb + (size_t)id * HH + e4 * 4);
    *(float4*)(g_x + (size_t)r * HH + e4 * 4) = v;
}

__global__ void k_init_state(const float* __restrict__ h0, const float* __restrict__ c0) {
    int gi = blockIdx.x * blockDim.x + threadIdx.x;   // 0..8191 float4 (32768 floats)
    int flat = gi * 4;
    int l = flat >> 14, rem = flat & 16383;
    *(float4*)(g_hbuf + l * 32768 + rem) = *(const float4*)(h0 + flat);  // parity 0
    *(float4*)(g_cbuf + l * 32768 + rem) = *(const float4*)(c0 + flat);
}

// ---------------- LSTM layer: 128 blocks x 128 threads ----------------
// thread = (b = tid&31, jj = tid>>5); j = blockIdx.x*4 + jj; 4 gate dots of K=1024
__device__ __forceinline__ float sigf(float x) { return 1.0f / (1.0f + expf(-x)); }

__global__ void k_lstm(const float* __restrict__ xin,
                       const float* __restrict__ hprev, const float* __restrict__ cprev,
                       float* __restrict__ hnew, float* __restrict__ cnew,
                       const float* __restrict__ Wih, const float* __restrict__ bih,
                       const float* __restrict__ Whh, const float* __restrict__ bhh,
                       float* outp, float* catp, float* callp) {
    __shared__ float xs[128 * 33];
    int tid = threadIdx.x;
    int b = tid & 31, jj = tid >> 5;
    int j = blockIdx.x * 4 + jj;
    float acc0 = 0.f, acc1 = 0.f, acc2 = 0.f, acc3 = 0.f;

    for (int phase = 0; phase < 2; phase++) {
        const float* src = phase ? hprev : xin;
        const float* W = phase ? Whh : Wih;
        for (int kc = 0; kc < 512; kc += 128) {
            __syncthreads();
            // stage transposed chunk: xs[k][b], coalesced global reads
            #pragma unroll
            for (int i = 0; i < 32; i++) {
                // tid < 128: row b'=i, k'=tid
                xs[tid * 33 + i] = src[i * HH + kc + tid];
            }
            __syncthreads();
            const float* wbase = W + (size_t)j * 512 + kc;
            #pragma unroll 4
            for (int k = 0; k < 128; k += 4) {
                float x0 = xs[(k + 0) * 33 + b];
                float x1 = xs[(k + 1) * 33 + b];
                float x2 = xs[(k + 2) * 33 + b];
                float x3 = xs[(k + 3) * 33 + b];
                float4 w0 = *(const float4*)(wbase + k);
                float4 w1 = *(const float4*)(wbase + k + 512 * 512);
                float4 w2 = *(const float4*)(wbase + k + 1024 * 512);
                float4 w3 = *(const float4*)(wbase + k + 1536 * 512);
                acc0 += w0.x * x0 + w0.y * x1 + w0.z * x2 + w0.w * x3;
                acc1 += w1.x * x0 + w1.y * x1 + w1.z * x2 + w1.w * x3;
                acc2 += w2.x * x0 + w2.y * x1 + w2.z * x2 + w2.w * x3;
                acc3 += w3.x * x0 + w3.y * x1 + w3.z * x2 + w3.w * x3;
            }
        }
    }

    float gi_ = acc0 + bih[j]        + bhh[j];
    float gf_ = acc1 + bih[512 + j]  + bhh[512 + j];
    float gg_ = acc2 + bih[1024 + j] + bhh[1024 + j];
    float go_ = acc3 + bih[1536 + j] + bhh[1536 + j];
    float cp = cprev[b * HH + j];
    float cn = sigf(gf_) * cp + sigf(gi_) * tanhf(gg_);
    float hn = sigf(go_) * tanhf(cn);
    hnew[b * HH + j] = hn;
    cnew[b * HH + j] = cn;
    if (outp) {
        outp[b * HH + j] = hn;
        catp[b * 2 * HH + HH + j] = hn;   // cat2[.][512+j] = out
        callp[b * HH + j] = cn;
    }
}

// ---------------- generic tiled fp32 GEMM: C = A[M,K] * B^T + bias ----------------
// B element (n,k) at B + n*ldbn + k*ldbk. 64x64 tile, BK=16, 256 threads, 4x4 micro-tile.
__global__ void k_gemm(int M, int N, int K,
                       const float* __restrict__ A, int lda, long long sA,
                       const float* __restrict__ B, int ldbn, int ldbk, long long sB,
                       const float* __restrict__ bias,
                       float* __restrict__ C, int ldc, long long sC, int act) {
    A += (size_t)blockIdx.z * sA;
    B += (size_t)blockIdx.z * sB;
    C += (size_t)blockIdx.z * sC;
    __shared__ float As[16][64];
    __shared__ float Bs[16][64];
    int tid = threadIdx.x;
    int tx = tid & 15, ty = tid >> 4;
    int m0 = blockIdx.y * 64, n0 = blockIdx.x * 64;
    int ar = tid >> 2, ak = (tid & 3) * 4;
    float acc[4][4] = {};

    for (int k0 = 0; k0 < K; k0 += 16) {
        // stage A (k-contiguous, float4)
        float4 av = make_float4(0.f, 0.f, 0.f, 0.f);
        if (m0 + ar < M) av = *(const float4*)(A + (size_t)(m0 + ar) * lda + k0 + ak);
        As[ak + 0][ar] = av.x; As[ak + 1][ar] = av.y;
        As[ak + 2][ar] = av.z; As[ak + 3][ar] = av.w;
        // stage B
        if (ldbk == 1) {
            float4 bq = make_float4(0.f, 0.f, 0.f, 0.f);
            if (n0 + ar < N) bq = *(const float4*)(B + (size_t)(n0 + ar) * ldbn + k0 + ak);
            Bs[ak + 0][ar] = bq.x; Bs[ak + 1][ar] = bq.y;
            Bs[ak + 2][ar] = bq.z; Bs[ak + 3][ar] = bq.w;
        } else {
            #pragma unroll
            for (int e = tid; e < 1024; e += 256) {
                int n = e & 63, kk = e >> 6;
                float v = 0.f;
                if (n0 + n < N) v = B[(size_t)(n0 + n) * ldbn + (size_t)(k0 + kk) * ldbk];
                Bs[kk][n] = v;
            }
        }
        __syncthreads();
        #pragma unroll
        for (int kk = 0; kk < 16; kk++) {
            float4 a = *(const float4*)(&As[kk][ty * 4]);
            float4 bq = *(const float4*)(&Bs[kk][tx * 4]);
            acc[0][0] += a.x * bq.x; acc[0][1] += a.x * bq.y; acc[0][2] += a.x * bq.z; acc[0][3] += a.x * bq.w;
            acc[1][0] += a.y * bq.x; acc[1][1] += a.y * bq.y; acc[1][2] += a.y * bq.z; acc[1][3] += a.y * bq.w;
            acc[2][0] += a.z * bq.x; acc[2][1] += a.z * bq.y; acc[2][2] += a.z * bq.z; acc[2][3] += a.z * bq.w;
            acc[3][0] += a.w * bq.x; acc[3][1] += a.w * bq.y; acc[3][2] += a.w * bq.z; acc[3][3] += a.w * bq.w;
        }
        __syncthreads();
    }

    #pragma unroll
    for (int i = 0; i < 4; i++) {
        int m = m0 + ty * 4 + i;
        if (m >= M) continue;
        #pragma unroll
        for (int jc = 0; jc < 4; jc++) {
            int n = n0 + tx * 4 + jc;
            if (n >= N) continue;
            float v = acc[i][jc];
            if (bias) v += bias[n];
            if (act == 1) v = tanhf(v);
            C[(size_t)m * ldc + n] = v;
        }
    }
}

// ---------------- attention softmax over S=400 ----------------
__global__ void k_attnsoftmax() {
    int r = blockIdx.x, tid = threadIdx.x;   // 128 threads
    __shared__ float vals[SS];
    __shared__ float red[128];
    float m = -1e30f;
    for (int s = tid; s < SS; s += 128) { float v = g_attn[(size_t)r * SS + s]; vals[s] = v; m = fmaxf(m, v); }
    red[tid] = m; __syncthreads();
    for (int o = 64; o > 0; o >>= 1) { if (tid < o) red[tid] = fmaxf(red[tid], red[tid + o]); __syncthreads(); }
    m = red[0]; __syncthreads();
    float sum = 0.f;
    for (int s = tid; s < SS; s += 128) { float e = __expf(vals[s] - m); vals[s] = e; sum += e; }
    red[tid] = sum; __syncthreads();
    for (int o = 64; o > 0; o >>= 1) { if (tid < o) red[tid] += red[tid + o]; __syncthreads(); }
    float inv = 1.f / red[0];
    for (int s = tid; s < SS; s += 128) g_attn[(size_t)r * SS + s] = vals[s] * inv;
}

// ---------------- p_gen ----------------
__global__ void k_pgen(const float* __restrict__ Wg, const float* __restrict__ bg) {
    int warp = threadIdx.x >> 5, lane = threadIdx.x & 31;
    int r = blockIdx.x * 8 + warp;
    float acc = 0.f;
    for (int j = lane; j < 512; j += 32) {
        acc += g_hatt[(size_t)r * HH + j] * Wg[j]
             + g_out [(size_t)r * HH + j] * Wg[512 + j]
             + g_call[(size_t)r * HH + j] * Wg[1024 + j]
             + g_x   [(size_t)r * HH + j] * Wg[1536 + j];
    }
    for (int o = 16; o > 0; o >>= 1) acc += __shfl_down_sync(0xffffffffu, acc, o);
    if (lane == 0) g_pgen[r] = 1.f / (1.f + expf(-(acc + bg[0])));
}

// ---------------- vocab softmax reductions (max + sumexp per row) ----------------
__global__ void k_maxsum() {
    int r = blockIdx.x, tid = threadIdx.x;   // 256 threads
    __shared__ float red[256];
    const float* row = g_logits + (size_t)r * VV;
    float m = -1e30f;
    for (int v = tid; v < VV; v += 256) m = fmaxf(m, row[v]);
    red[tid] = m; __syncthreads();
    for (int o = 128; o > 0; o >>= 1) { if (tid < o) red[tid] = fmaxf(red[tid], red[tid + o]); __syncthreads(); }
    m = red[0]; __syncthreads();
    float s = 0.f;
    for (int v = tid; v < VV; v += 256) s += __expf(row[v] - m);
    red[tid] = s; __syncthreads();
    for (int o = 128; o > 0; o >>= 1) { if (tid < o) red[tid] += red[tid + o]; __syncthreads(); }
    if (tid == 0) { g_rmax[r] = m; g_rinv[r] = 1.f / red[0]; }
}

// ---------------- base scores: log(vocab_d * p_gen + eps), log(eps) beyond V ----------------
__global__ void k_scores(float* __restrict__ out) {
    int r = blockIdx.y;
    int v0 = (blockIdx.x * blockDim.x + threadIdx.x) * 4;
    float pg = g_pgen[r], m = g_rmax[r], inv = g_rinv[r];
    float* orow = out + (size_t)r * EXTV;
    const float* lrow = g_logits + (size_t)r * VV;
    #pragma unroll
    for (int i = 0; i < 4; i++) {
        int v = v0 + i;
        if (v >= EXTV) return;
        float sc;
        if (v < VV) {
            float p = __expf(lrow[v] - m) * inv;
            sc = __logf(p * pg + 1e-10f);
        } else {
            sc = __logf(1e-10f);
        }
        orow[v] = sc;
    }
}

// ---------------- copy fixup: overwrite src positions (last-write-wins) ----------------
__global__ void k_fixup(const int* __restrict__ src, float* __restrict__ out) {
    int r = blockIdx.x, b = r & 31;
    __shared__ int sid[SS];
    int s = threadIdx.x;   // 512 threads
    if (s < SS) sid[s] = src[s * BBATCH + b];
    __syncthreads();
    if (s >= SS) return;
    int v = sid[s];
    for (int s2 = s + 1; s2 < SS; s2++) if (sid[s2] == v) return;  // a later s wins
    float pg = g_pgen[r];
    float a = g_attn[(size_t)r * SS + s];
    float pv = 0.f;
    if (v < VV) pv = __expf(g_logits[(size_t)r * VV + v] - g_rmax[r]) * g_rinv[r];
    out[(size_t)r * EXTV + v] = __logf(pv * pg + a * (1.f - pg) + 1e-10f);
}

// ---------------- final h, c ----------------
__global__ void k_hc(float* __restrict__ out) {
    int gi = blockIdx.x * blockDim.x + threadIdx.x;   // 0..16383 float4
    float* dst = out + (size_t)TB * EXTV;
    int flat = gi * 4;
    if (gi < 8192) {                                  // h: parity 0 after 32 steps
        int l = flat >> 14, rem = flat & 16383;
        *(float4*)(dst + flat) = *(const float4*)(g_hbuf + l * 32768 + rem);
    } else {
        int f2 = flat - 32768;
        int l = f2 >> 14, rem = f2 & 16383;
        *(float4*)(dst + 32768 + f2) = *(const float4*)(g_cbuf + l * 32768 + rem);
    }
}

// ---------------- launch ----------------
extern "C" void kernel_launch(void* const* d_in, const int* in_sizes, int n_in,
                              void* d_out, int out_size) {
    const int*   ids = (const int*)d_in[0];
    const int*   src = (const int*)d_in[1];
    const float* h0  = (const float*)d_in[2];
    const float* c0  = (const float*)d_in[3];
    const float* ctx = (const float*)d_in[4];
    // num_oovs may or may not be present as a scalar input at index 5
    int base = (in_sizes[5] <= 4) ? 6 : 5;
    const float* emb = (const float*)d_in[base + 0];
    const float* Wih = (const float*)d_in[base + 1];
    const float* bih = (const float*)d_in[base + 2];
    const float* Whh = (const float*)d_in[base + 3];
    const float* bhh = (const float*)d_in[base + 4];
    const float* Wa  = (const float*)d_in[base + 5];
    const float* ba  = (const float*)d_in[base + 6];
    const float* Wo  = (const float*)d_in[base + 7];
    const float* bo  = (const float*)d_in[base + 8];
    const float* Wv  = (const float*)d_in[base + 9];
    const float* bv  = (const float*)d_in[base + 10];
    const float* Wg  = (const float*)d_in[base + 11];
    const float* bg  = (const float*)d_in[base + 12];
    float* out = (float*)d_out;

    float *px, *pout, *pcall, *phbuf, *pcbuf, *pgamma, *pattn, *pcat2, *phatt, *plogits;
    cudaGetSymbolAddress((void**)&px,      g_x);
    cudaGetSymbolAddress((void**)&pout,    g_out);
    cudaGetSymbolAddress((void**)&pcall,   g_call);
    cudaGetSymbolAddress((void**)&phbuf,   g_hbuf);
    cudaGetSymbolAddress((void**)&pcbuf,   g_cbuf);
    cudaGetSymbolAddress((void**)&pgamma,  g_gamma);
    cudaGetSymbolAddress((void**)&pattn,   g_attn);
    cudaGetSymbolAddress((void**)&pcat2,   g_cat2);
    cudaGetSymbolAddress((void**)&phatt,   g_hatt);
    cudaGetSymbolAddress((void**)&plogits, g_logits);

    // 1. embedding for all (t,b) + initial state
    k_embed<<<512, 256>>>(ids, emb);
    k_init_state<<<32, 256>>>(h0, c0);

    // 2. sequential LSTM: 2 layers x 32 steps
    for (int t = 0; t < TT; t++) {
        int p = t & 1, np = 1 - p;
        k_lstm<<<128, 128>>>(px + (size_t)t * BBATCH * HH,
                             phbuf + (0 * 2 + p) * 16384, pcbuf + (0 * 2 + p) * 16384,
                             phbuf + (0 * 2 + np) * 16384, pcbuf + (0 * 2 + np) * 16384,
                             Wih, bih, Whh, bhh,
                             nullptr, nullptr, nullptr);
        k_lstm<<<128, 128>>>(phbuf + (0 * 2 + np) * 16384,
                             phbuf + (2 + p) * 16384, pcbuf + (2 + p) * 16384,
                             phbuf + (2 + np) * 16384, pcbuf + (2 + np) * 16384,
                             Wih + 2048 * 512, bih + 2048, Whh + 2048 * 512, bhh + 2048,
                             pout + (size_t)t * BBATCH * HH,
                             pcat2 + (size_t)t * BBATCH * 2 * HH,
                             pcall + (size_t)t * BBATCH * HH);
    }

    // 3. gamma = out @ Wa^T + ba      [1024,512]
    k_gemm<<<dim3(8, 16, 1), 256>>>(TB, HH, HH, pout, HH, 0,
                                    Wa, HH, 1, 0, ba, pgamma, HH, 0, 0);

    // 4. attn logits[t,s] per b: gamma(rows t*32+b) @ contexts[b]^T   [32,400] x32
    k_gemm<<<dim3(7, 1, 32), 256>>>(BBATCH, SS, HH,
                                    pgamma, BBATCH * HH, HH,
                                    ctx, HH, 1, (long long)SS * HH,
                                    nullptr, pattn, BBATCH * SS, SS, 0);

    // 5. softmax over s
    k_attnsoftmax<<<TB, 128>>>();

    // 6. c_t = attn @ contexts[b]  -> cat2[:, 0:512]   (B accessed k-major)
    k_gemm<<<dim3(8, 1, 32), 256>>>(BBATCH, HH, SS,
                                    pattn, BBATCH * SS, SS,
                                    ctx, 1, HH, (long long)SS * HH,
                                    nullptr, pcat2, BBATCH * 2 * HH, 2 * HH, 0);

    // 7. h_att = tanh(cat2 @ Wo^T + bo)   [1024,512], K=1024
    k_gemm<<<dim3(8, 16, 1), 256>>>(TB, HH, 2 * HH, pcat2, 2 * HH, 0,
                                    Wo, 2 * HH, 1, 0, bo, phatt, HH, 0, 1);

    // 8. p_gen
    k_pgen<<<128, 256>>>(Wg, bg);

    // 9. vocab logits = h_att @ Wv^T + bv   [1024,50000]  (the big GEMM)
    k_gemm<<<dim3(782, 16, 1), 256>>>(TB, VV, HH, phatt, HH, 0,
                                      Wv, HH, 1, 0, bv, plogits, VV, 0, 0);

    // 10. softmax reductions, base scores, copy fixup
    k_maxsum<<<TB, 256>>>();
    k_scores<<<dim3(49, TB, 1), 256>>>(out);
    k_fixup<<<TB, 512>>>(src, out);

    // 11. final h, c
    k_hc<<<64, 256>>>(out);
}

// round 5
// speedup vs baseline: 2.0136x; 2.0136x over previous
#include <cuda_runtime.h>
#include <math.h>

#define TT 32
#define BBATCH 32
#define HH 512
#define SS 400
#define VV 50000
#define EXTV 50050
#define TB 1024  // TT*BBATCH
#define NBLK 128

// ---------------- scratch (static device arrays; no allocation) ----------------
__device__ float g_x[TB * HH];          // embedded inputs per (t,b)
__device__ float g_xw[2048 * TB];       // precomputed W_ih1 @ x^T : [gate_row][t*32+b]
__device__ float g_out[TB * HH];        // layer-2 h per step (== h[-1] per step)
__device__ float g_call[TB * HH];       // layer-2 c per step (== c[-1] per step)
__device__ float g_h1[BBATCH * HH];     // current layer-1 h  [b][512]
__device__ float g_h2[BBATCH * HH];     // current layer-2 h  [b][512]
__device__ float g_c1f[BBATCH * HH];    // final c layer 1
__device__ float g_c2f[BBATCH * HH];    // final c layer 2
__device__ float g_gamma[TB * HH];
__device__ float g_attn[TB * SS];
__device__ float g_cat2[TB * 2 * HH];   // [c_t | out]
__device__ float g_hatt[TB * HH];
__device__ float g_pgen[TB];
__device__ float g_rmax[TB];
__device__ float g_rinv[TB];
__device__ float g_logits[(size_t)TB * VV];   // 200 MB
__device__ unsigned g_barcnt;           // zero-init; returns to 0 after each barrier
__device__ unsigned g_bargen;           // monotonically grows; only relative values used

// ---------------- embedding ----------------
__global__ void k_embed(const int* __restrict__ ids, const float* __restrict__ emb) {
    int gi = blockIdx.x * blockDim.x + threadIdx.x;   // 1024 rows * 128 float4
    int r = gi >> 7, e4 = gi & 127;
    int id = ids[r];
    if (id >= VV) id = 1;   // UNK
    float4 v = *(const float4*)(emb + (size_t)id * HH + e4 * 4);
    *(float4*)(g_x + (size_t)r * HH + e4 * 4) = v;
}

// ---------------- persistent 2-layer LSTM ----------------
// 128 blocks x 256 threads, 1 block/SM (smem-bound) => all co-resident, spin
// barrier is safe. Block bid owns h-dims J = bid*4 .. bid*4+3 for BOTH layers.
// Gate-row local index r = jj*4 + g (jj in 0..3, g in {i,f,g,o}).
// Warp w (0..7): q = w&3 = jj it computes, half = w>>2 = K-half.
// Weights live in smem, transposed [k][16] so a warp fetches its 4 gate rows of
// one k with a single broadcast LDS.128. h is staged in smem swizzled
// hs[k*32 + ((b^k)&31)] (bank-conflict-free for both stage and compute).

__device__ __forceinline__ float sigf(float x) { return 1.0f / (1.0f + expf(-x)); }

__device__ __forceinline__ void gridbar(int tid) {
    __syncthreads();
    if (tid == 0) {
        __threadfence();
        unsigned gen = *(volatile unsigned*)&g_bargen;
        unsigned old = atomicAdd(&g_barcnt, 1u);
        if (old == NBLK - 1) {
            atomicExch(&g_barcnt, 0u);
            __threadfence();
            atomicAdd(&g_bargen, 1u);
        } else {
            while (*(volatile unsigned*)&g_bargen == gen) { }
        }
        __threadfence();
    }
    __syncthreads();
}

__global__ void __launch_bounds__(256, 1) k_persist(
    const float* __restrict__ Whh1, const float* __restrict__ Wih2,
    const float* __restrict__ Whh2,
    const float* __restrict__ bih, const float* __restrict__ bhh,
    const float* __restrict__ c0)
{
    extern __shared__ float sm[];
    float* wT1 = sm;                       // [512][16]   32 KB
    float* wT2 = sm + 512 * 16;            // [1024][16]  64 KB
    float* hs  = sm + 512 * 16 + 1024 * 16; // [1024][32] 128 KB (swizzled)
    float* gpart = hs + 512 * 32;          // 1024 floats, aliases hs rows 512..543

    __shared__ float c1s[4][32], c2s[4][32], bsum[2][16];

    const int tid = threadIdx.x;
    const int bid = blockIdx.x;
    const int w = tid >> 5, l = tid & 31;
    const int q = w & 3, half = w >> 2;

    // ---- one-time: load weight slices into smem (transposed) ----
    #pragma unroll 1
    for (int r = 0; r < 16; r++) {
        int g = r & 3, jj = r >> 2;
        int G = g * 512 + bid * 4 + jj;
        for (int k = tid; k < 512; k += 256) {
            wT1[k * 16 + r]         = Whh1[(size_t)G * 512 + k];
            wT2[k * 16 + r]         = Wih2[(size_t)G * 512 + k];
            wT2[(512 + k) * 16 + r] = Whh2[(size_t)G * 512 + k];
        }
    }
    if (tid < 32) {
        int layer = tid >> 4, r = tid & 15;
        int g = r & 3, jj = r >> 2;
        int G = layer * 2048 + g * 512 + bid * 4 + jj;
        bsum[layer][r] = bih[G] + bhh[G];
    }
    if (tid < 128) {
        int jj = tid >> 5, b = tid & 31, J = bid * 4 + jj;
        c1s[jj][b] = c0[b * 512 + J];
        c2s[jj][b] = c0[16384 + b * 512 + J];
    }
    // stage initial h1 (g_h1 = h0 layer0, copied by host memcpy)
    for (int i = tid; i < 16384; i += 256) {
        int b = i >> 9, k = i & 511;
        hs[(k << 5) | ((b ^ k) & 31)] = g_h1[i];
    }
    __syncthreads();

    for (int t = 0; t < TT; t++) {
        // ---- layer 1 inner: rows(jj=q) x 32 b, K-half of 512 ----
        float a0 = 0.f, a1 = 0.f, a2 = 0.f, a3 = 0.f;
        {
            const float* wp = wT1 + q * 4;
            int k0 = half * 256;
            #pragma unroll 8
            for (int k = k0; k < k0 + 256; k++) {
                float4 wv = *(const float4*)(wp + k * 16);
                float hv = hs[(k << 5) | ((k ^ l) & 31)];
                a0 += wv.x * hv; a1 += wv.y * hv; a2 += wv.z * hv; a3 += wv.w * hv;
            }
        }
        // gpart region (hs rows 512+) is unused during layer-1: safe to write now
        gpart[half * 512 + (q * 4 + 0) * 32 + l] = a0;
        gpart[half * 512 + (q * 4 + 1) * 32 + l] = a1;
        gpart[half * 512 + (q * 4 + 2) * 32 + l] = a2;
        gpart[half * 512 + (q * 4 + 3) * 32 + l] = a3;
        __syncthreads();
        if (tid < 128) {
            int jj = tid >> 5, b = tid & 31, J = bid * 4 + jj;
            float gv[4];
            #pragma unroll
            for (int g = 0; g < 4; g++) {
                int r = jj * 4 + g;
                gv[g] = gpart[r * 32 + b] + gpart[512 + r * 32 + b]
                      + g_xw[(size_t)(g * 512 + J) * 1024 + t * 32 + b]
                      + bsum[0][r];
            }
            float cn = sigf(gv[1]) * c1s[jj][b] + sigf(gv[0]) * tanhf(gv[2]);
            float hn = sigf(gv[3]) * tanhf(cn);
            c1s[jj][b] = cn;
            g_h1[b * 512 + J] = hn;
        }
        gridbar(tid);

        // ---- stage [h1_new ; h2_prev] into hs rows 0..1023 ----
        for (int i = tid; i < 32768; i += 256) {
            int b = (i >> 9) & 31, k = i & 511;
            int kk = (i < 16384) ? k : (512 + k);
            float v = (i < 16384) ? g_h1[i] : g_h2[i - 16384];
            hs[(kk << 5) | ((b ^ kk) & 31)] = v;
        }
        __syncthreads();

        // ---- layer 2 inner: K-half of 1024 ----
        a0 = a1 = a2 = a3 = 0.f;
        {
            const float* wp = wT2 + q * 4;
            int k0 = half * 512;
            #pragma unroll 8
            for (int k = k0; k < k0 + 512; k++) {
                float4 wv = *(const float4*)(wp + k * 16);
                float hv = hs[(k << 5) | ((k ^ l) & 31)];
                a0 += wv.x * hv; a1 += wv.y * hv; a2 += wv.z * hv; a3 += wv.w * hv;
            }
        }
        __syncthreads();   // all hs reads done before gpart alias overwrite
        gpart[half * 512 + (q * 4 + 0) * 32 + l] = a0;
        gpart[half * 512 + (q * 4 + 1) * 32 + l] = a1;
        gpart[half * 512 + (q * 4 + 2) * 32 + l] = a2;
        gpart[half * 512 + (q * 4 + 3) * 32 + l] = a3;
        __syncthreads();
        if (tid < 128) {
            int jj = tid >> 5, b = tid & 31, J = bid * 4 + jj;
            float gv[4];
            #pragma unroll
            for (int g = 0; g < 4; g++) {
                int r = jj * 4 + g;
                gv[g] = gpart[r * 32 + b] + gpart[512 + r * 32 + b] + bsum[1][r];
            }
            float cn = sigf(gv[1]) * c2s[jj][b] + sigf(gv[0]) * tanhf(gv[2]);
            float hn = sigf(gv[3]) * tanhf(cn);
            c2s[jj][b] = cn;
            g_h2[b * 512 + J] = hn;
            int row = t * 32 + b;
            g_out[(size_t)row * 512 + J] = hn;
            g_cat2[(size_t)row * 1024 + 512 + J] = hn;
            g_call[(size_t)row * 512 + J] = cn;
        }
        gridbar(tid);
        // hs rows 0..511 still hold this step's h1 -> reused by next step's layer 1
    }

    if (tid < 128) {
        int jj = tid >> 5, b = tid & 31, J = bid * 4 + jj;
        g_c1f[b * 512 + J] = c1s[jj][b];
        g_c2f[b * 512 + J] = c2s[jj][b];
    }
}

// ---------------- generic tiled fp32 GEMM: C = A[M,K] * B^T + bias ----------------
__global__ void k_gemm(int M, int N, int K,
                       const float* __restrict__ A, int lda, long long sA,
                       const float* __restrict__ B, int ldbn, int ldbk, long long sB,
                       const float* __restrict__ bias,
                       float* __restrict__ C, int ldc, long long sC, int act) {
    A += (size_t)blockIdx.z * sA;
    B += (size_t)blockIdx.z * sB;
    C += (size_t)blockIdx.z * sC;
    __shared__ float As[16][64];
    __shared__ float Bs[16][64];
    int tid = threadIdx.x;
    int tx = tid & 15, ty = tid >> 4;
    int m0 = blockIdx.y * 64, n0 = blockIdx.x * 64;
    int ar = tid >> 2, ak = (tid & 3) * 4;
    float acc[4][4] = {};

    for (int k0 = 0; k0 < K; k0 += 16) {
        float4 av = make_float4(0.f, 0.f, 0.f, 0.f);
        if (m0 + ar < M) av = *(const float4*)(A + (size_t)(m0 + ar) * lda + k0 + ak);
        As[ak + 0][ar] = av.x; As[ak + 1][ar] = av.y;
        As[ak + 2][ar] = av.z; As[ak + 3][ar] = av.w;
        if (ldbk == 1) {
            float4 bq = make_float4(0.f, 0.f, 0.f, 0.f);
            if (n0 + ar < N) bq = *(const float4*)(B + (size_t)(n0 + ar) * ldbn + k0 + ak);
            Bs[ak + 0][ar] = bq.x; Bs[ak + 1][ar] = bq.y;
            Bs[ak + 2][ar] = bq.z; Bs[ak + 3][ar] = bq.w;
        } else {
            #pragma unroll
            for (int e = tid; e < 1024; e += 256) {
                int n = e & 63, kk = e >> 6;
                float v = 0.f;
                if (n0 + n < N) v = B[(size_t)(n0 + n) * ldbn + (size_t)(k0 + kk) * ldbk];
                Bs[kk][n] = v;
            }
        }
        __syncthreads();
        #pragma unroll
        for (int kk = 0; kk < 16; kk++) {
            float4 a = *(const float4*)(&As[kk][ty * 4]);
            float4 bq = *(const float4*)(&Bs[kk][tx * 4]);
            acc[0][0] += a.x * bq.x; acc[0][1] += a.x * bq.y; acc[0][2] += a.x * bq.z; acc[0][3] += a.x * bq.w;
            acc[1][0] += a.y * bq.x; acc[1][1] += a.y * bq.y; acc[1][2] += a.y * bq.z; acc[1][3] += a.y * bq.w;
            acc[2][0] += a.z * bq.x; acc[2][1] += a.z * bq.y; acc[2][2] += a.z * bq.z; acc[2][3] += a.z * bq.w;
            acc[3][0] += a.w * bq.x; acc[3][1] += a.w * bq.y; acc[3][2] += a.w * bq.z; acc[3][3] += a.w * bq.w;
        }
        __syncthreads();
    }

    #pragma unroll
    for (int i = 0; i < 4; i++) {
        int m = m0 + ty * 4 + i;
        if (m >= M) continue;
        #pragma unroll
        for (int jc = 0; jc < 4; jc++) {
            int n = n0 + tx * 4 + jc;
            if (n >= N) continue;
            float v = acc[i][jc];
            if (bias) v += bias[n];
            if (act == 1) v = tanhf(v);
            C[(size_t)m * ldc + n] = v;
        }
    }
}

// ---------------- attention softmax over S=400 ----------------
__global__ void k_attnsoftmax() {
    int r = blockIdx.x, tid = threadIdx.x;
    __shared__ float vals[SS];
    __shared__ float red[128];
    float m = -1e30f;
    for (int s = tid; s < SS; s += 128) { float v = g_attn[(size_t)r * SS + s]; vals[s] = v; m = fmaxf(m, v); }
    red[tid] = m; __syncthreads();
    for (int o = 64; o > 0; o >>= 1) { if (tid < o) red[tid] = fmaxf(red[tid], red[tid + o]); __syncthreads(); }
    m = red[0]; __syncthreads();
    float sum = 0.f;
    for (int s = tid; s < SS; s += 128) { float e = __expf(vals[s] - m); vals[s] = e; sum += e; }
    red[tid] = sum; __syncthreads();
    for (int o = 64; o > 0; o >>= 1) { if (tid < o) red[tid] += red[tid + o]; __syncthreads(); }
    float inv = 1.f / red[0];
    for (int s = tid; s < SS; s += 128) g_attn[(size_t)r * SS + s] = vals[s] * inv;
}

// ---------------- p_gen ----------------
__global__ void k_pgen(const float* __restrict__ Wg, const float* __restrict__ bg) {
    int warp = threadIdx.x >> 5, lane = threadIdx.x & 31;
    int r = blockIdx.x * 8 + warp;
    float acc = 0.f;
    for (int j = lane; j < 512; j += 32) {
        acc += g_hatt[(size_t)r * HH + j] * Wg[j]
             + g_out [(size_t)r * HH + j] * Wg[512 + j]
             + g_call[(size_t)r * HH + j] * Wg[1024 + j]
             + g_x   [(size_t)r * HH + j] * Wg[1536 + j];
    }
    for (int o = 16; o > 0; o >>= 1) acc += __shfl_down_sync(0xffffffffu, acc, o);
    if (lane == 0) g_pgen[r] = 1.f / (1.f + expf(-(acc + bg[0])));
}

// ---------------- vocab softmax reductions ----------------
__global__ void k_maxsum() {
    int r = blockIdx.x, tid = threadIdx.x;
    __shared__ float red[256];
    const float* row = g_logits + (size_t)r * VV;
    float m = -1e30f;
    for (int v = tid; v < VV; v += 256) m = fmaxf(m, row[v]);
    red[tid] = m; __syncthreads();
    for (int o = 128; o > 0; o >>= 1) { if (tid < o) red[tid] = fmaxf(red[tid], red[tid + o]); __syncthreads(); }
    m = red[0]; __syncthreads();
    float s = 0.f;
    for (int v = tid; v < VV; v += 256) s += __expf(row[v] - m);
    red[tid] = s; __syncthreads();
    for (int o = 128; o > 0; o >>= 1) { if (tid < o) red[tid] += red[tid + o]; __syncthreads(); }
    if (tid == 0) { g_rmax[r] = m; g_rinv[r] = 1.f / red[0]; }
}

// ---------------- base scores ----------------
__global__ void k_scores(float* __restrict__ out) {
    int r = blockIdx.y;
    int v0 = (blockIdx.x * blockDim.x + threadIdx.x) * 4;
    float pg = g_pgen[r], m = g_rmax[r], inv = g_rinv[r];
    float* orow = out + (size_t)r * EXTV;
    const float* lrow = g_logits + (size_t)r * VV;
    #pragma unroll
    for (int i = 0; i < 4; i++) {
        int v = v0 + i;
        if (v >= EXTV) return;
        float sc;
        if (v < VV) {
            float p = __expf(lrow[v] - m) * inv;
            sc = __logf(p * pg + 1e-10f);
        } else {
            sc = __logf(1e-10f);
        }
        orow[v] = sc;
    }
}

// ---------------- copy fixup (last-write-wins) ----------------
__global__ void k_fixup(const int* __restrict__ src, float* __restrict__ out) {
    int r = blockIdx.x, b = r & 31;
    __shared__ int sid[SS];
    int s = threadIdx.x;
    if (s < SS) sid[s] = src[s * BBATCH + b];
    __syncthreads();
    if (s >= SS) return;
    int v = sid[s];
    for (int s2 = s + 1; s2 < SS; s2++) if (sid[s2] == v) return;
    float pg = g_pgen[r];
    float a = g_attn[(size_t)r * SS + s];
    float pv = 0.f;
    if (v < VV) pv = __expf(g_logits[(size_t)r * VV + v] - g_rmax[r]) * g_rinv[r];
    out[(size_t)r * EXTV + v] = __logf(pv * pg + a * (1.f - pg) + 1e-10f);
}

// ---------------- final h, c ----------------
__global__ void k_hc(float* __restrict__ out) {
    int i = blockIdx.x * blockDim.x + threadIdx.x;   // 16384 threads
    float* dst = out + (size_t)TB * EXTV;
    dst[i]          = g_h1[i];
    dst[16384 + i]  = g_h2[i];
    dst[32768 + i]  = g_c1f[i];
    dst[49152 + i]  = g_c2f[i];
}

// ---------------- launch ----------------
extern "C" void kernel_launch(void* const* d_in, const int* in_sizes, int n_in,
                              void* d_out, int out_size) {
    const int*   ids = (const int*)d_in[0];
    const int*   src = (const int*)d_in[1];
    const float* h0  = (const float*)d_in[2];
    const float* c0  = (const float*)d_in[3];
    const float* ctx = (const float*)d_in[4];
    int base = (in_sizes[5] <= 4) ? 6 : 5;
    const float* emb = (const float*)d_in[base + 0];
    const float* Wih = (const float*)d_in[base + 1];
    const float* bih = (const float*)d_in[base + 2];
    const float* Whh = (const float*)d_in[base + 3];
    const float* bhh = (const float*)d_in[base + 4];
    const float* Wa  = (const float*)d_in[base + 5];
    const float* ba  = (const float*)d_in[base + 6];
    const float* Wo  = (const float*)d_in[base + 7];
    const float* bo  = (const float*)d_in[base + 8];
    const float* Wv  = (const float*)d_in[base + 9];
    const float* bv  = (const float*)d_in[base + 10];
    const float* Wg  = (const float*)d_in[base + 11];
    const float* bg  = (const float*)d_in[base + 12];
    float* out = (float*)d_out;

    float *px, *pxw, *pout, *pcall, *ph1, *ph2, *pgamma, *pattn, *pcat2, *phatt, *plogits;
    cudaGetSymbolAddress((void**)&px,      g_x);
    cudaGetSymbolAddress((void**)&pxw,     g_xw);
    cudaGetSymbolAddress((void**)&pout,    g_out);
    cudaGetSymbolAddress((void**)&pcall,   g_call);
    cudaGetSymbolAddress((void**)&ph1,     g_h1);
    cudaGetSymbolAddress((void**)&ph2,     g_h2);
    cudaGetSymbolAddress((void**)&pgamma,  g_gamma);
    cudaGetSymbolAddress((void**)&pattn,   g_attn);
    cudaGetSymbolAddress((void**)&pcat2,   g_cat2);
    cudaGetSymbolAddress((void**)&phatt,   g_hatt);
    cudaGetSymbolAddress((void**)&plogits, g_logits);

    const int SMEM_PERSIST = (512 * 16 + 1024 * 16 + 1024 * 32) * 4;  // 229376 B
    cudaFuncSetAttribute(k_persist, cudaFuncAttributeMaxDynamicSharedMemorySize, SMEM_PERSIST);

    // 1. embedding for all (t,b)
    k_embed<<<512, 256>>>(ids, emb);

    // 2. hoist x-contribution of layer 1: g_xw = W_ih1 @ x^T  [2048,1024]
    k_gemm<<<dim3(16, 32, 1), 256>>>(2048, TB, HH, Wih, HH, 0,
                                     px, HH, 1, 0, nullptr, pxw, TB, 0, 0);

    // 3. initial hidden state
    cudaMemcpyAsync(ph1, h0,          16384 * sizeof(float), cudaMemcpyDeviceToDevice, 0);
    cudaMemcpyAsync(ph2, h0 + 16384,  16384 * sizeof(float), cudaMemcpyDeviceToDevice, 0);

    // 4. persistent 2-layer LSTM over all 32 steps
    k_persist<<<NBLK, 256, SMEM_PERSIST>>>(Whh, Wih + 2048 * 512, Whh + 2048 * 512,
                                           bih, bhh, c0);

    // 5. gamma = out @ Wa^T + ba      [1024,512]
    k_gemm<<<dim3(8, 16, 1), 256>>>(TB, HH, HH, pout, HH, 0,
                                    Wa, HH, 1, 0, ba, pgamma, HH, 0, 0);

    // 6. attn logits per b: gamma @ contexts[b]^T   [32,400] x32
    k_gemm<<<dim3(7, 1, 32), 256>>>(BBATCH, SS, HH,
                                    pgamma, BBATCH * HH, HH,
                                    ctx, HH, 1, (long long)SS * HH,
                                    nullptr, pattn, BBATCH * SS, SS, 0);

    // 7. softmax over s
    k_attnsoftmax<<<TB, 128>>>();

    // 8. c_t = attn @ contexts[b]  -> cat2[:, 0:512]
    k_gemm<<<dim3(8, 1, 32), 256>>>(BBATCH, HH, SS,
                                    pattn, BBATCH * SS, SS,
                                    ctx, 1, HH, (long long)SS * HH,
                                    nullptr, pcat2, BBATCH * 2 * HH, 2 * HH, 0);

    // 9. h_att = tanh(cat2 @ Wo^T + bo)   [1024,512], K=1024
    k_gemm<<<dim3(8, 16, 1), 256>>>(TB, HH, 2 * HH, pcat2, 2 * HH, 0,
                                    Wo, 2 * HH, 1, 0, bo, phatt, HH, 0, 1);

    // 10. p_gen
    k_pgen<<<128, 256>>>(Wg, bg);

    // 11. vocab logits = h_att @ Wv^T + bv   [1024,50000]
    k_gemm<<<dim3(782, 16, 1), 256>>>(TB, VV, HH, phatt, HH, 0,
                                      Wv, HH, 1, 0, bv, plogits, VV, 0, 0);

    // 12. softmax reductions, base scores, copy fixup
    k_maxsum<<<TB, 256>>>();
    k_scores<<<dim3(49, TB, 1), 256>>>(out);
    k_fixup<<<TB, 512>>>(src, out);

    // 13. final h, c
    k_hc<<<64, 256>>>(out);
}

// round 8
// speedup vs baseline: 3.6870x; 1.8311x over previous
#include <cuda_runtime.h>
#include <cuda_bf16.h>
#include <cstdint>
#include <math.h>

#define TT 32
#define BBATCH 32
#define HH 512
#define SS 400
#define VV 50000
#define EXTV 50050
#define TB 1024  // TT*BBATCH
#define NBLK 128

// ---------------- scratch (static device arrays; no allocation) ----------------
__device__ float g_x[TB * HH];          // embedded inputs per (t,b)
__device__ float g_xw[2048 * TB];       // precomputed W_ih1 @ x^T : [gate_row][t*32+b]
__device__ float g_out[TB * HH];        // layer-2 h per step (== h[-1] per step)
__device__ float g_call[TB * HH];       // layer-2 c per step (== c[-1] per step)
__device__ float g_h1[BBATCH * HH];     // current layer-1 h  [b][512]
__device__ float g_h2[BBATCH * HH];     // current layer-2 h  [b][512]
__device__ float g_c1f[BBATCH * HH];    // final c layer 1
__device__ float g_c2f[BBATCH * HH];    // final c layer 2
__device__ float g_gamma[TB * HH];
__device__ float g_attn[TB * SS];
__device__ float g_cat2[TB * 2 * HH];   // [c_t | out]
__device__ float g_hatt[TB * HH];
__device__ float g_pgen[TB];
__device__ float g_rmax[TB];
__device__ float g_rinv[TB];
__device__ float g_logits[(size_t)TB * VV];          // 200 MB
__device__ __nv_bfloat16 g_hattb[TB * HH];           // bf16 h_att
__device__ __nv_bfloat16 g_wvb[(size_t)VV * HH];     // bf16 Wv (51 MB)
__device__ unsigned g_barcnt;
__device__ unsigned g_bargen;

__device__ __forceinline__ uint32_t smem_u32(const void* p) {
    uint32_t a;
    asm("{ .reg .u64 t; cvta.to.shared.u64 t, %1; cvt.u32.u64 %0, t; }" : "=r"(a) : "l"(p));
    return a;
}

// ---------------- embedding ----------------
__global__ void k_embed(const int* __restrict__ ids, const float* __restrict__ emb) {
    int gi = blockIdx.x * blockDim.x + threadIdx.x;
    int r = gi >> 7, e4 = gi & 127;
    int id = ids[r];
    if (id >= VV) id = 1;   // UNK
    float4 v = *(const float4*)(emb + (size_t)id * HH + e4 * 4);
    *(float4*)(g_x + (size_t)r * HH + e4 * 4) = v;
}

// ---------------- fp32 -> bf16 convert ----------------
__global__ void k_cvt(const float* __restrict__ src, __nv_bfloat16* __restrict__ dst, int n4) {
    int i = blockIdx.x * blockDim.x + threadIdx.x;
    if (i >= n4) return;
    float4 v = ((const float4*)src)[i];
    __nv_bfloat162 a = __floats2bfloat162_rn(v.x, v.y);
    __nv_bfloat162 b = __floats2bfloat162_rn(v.z, v.w);
    ((__nv_bfloat162*)dst)[i * 2]     = a;
    ((__nv_bfloat162*)dst)[i * 2 + 1] = b;
}

// ---------------- persistent 2-layer LSTM (unchanged from R4) ----------------
__device__ __forceinline__ float sigf(float x) { return 1.0f / (1.0f + expf(-x)); }

__device__ __forceinline__ void gridbar(int tid) {
    __syncthreads();
    if (tid == 0) {
        __threadfence();
        unsigned gen = *(volatile unsigned*)&g_bargen;
        unsigned old = atomicAdd(&g_barcnt, 1u);
        if (old == NBLK - 1) {
            atomicExch(&g_barcnt, 0u);
            __threadfence();
            atomicAdd(&g_bargen, 1u);
        } else {
            while (*(volatile unsigned*)&g_bargen == gen) { }
        }
        __threadfence();
    }
    __syncthreads();
}

__global__ void __launch_bounds__(256, 1) k_persist(
    const float* __restrict__ Whh1, const float* __restrict__ Wih2,
    const float* __restrict__ Whh2,
    const float* __restrict__ bih, const float* __restrict__ bhh,
    const float* __restrict__ c0)
{
    extern __shared__ float sm[];
    float* wT1 = sm;                        // [512][16]   32 KB
    float* wT2 = sm + 512 * 16;             // [1024][16]  64 KB
    float* hs  = sm + 512 * 16 + 1024 * 16; // [1024][32] 128 KB (swizzled)
    float* gpart = hs + 512 * 32;           // aliases hs rows 512..543

    __shared__ float c1s[4][32], c2s[4][32], bsum[2][16];

    const int tid = threadIdx.x;
    const int bid = blockIdx.x;
    const int w = tid >> 5, l = tid & 31;
    const int q = w & 3, half = w >> 2;

    #pragma unroll 1
    for (int r = 0; r < 16; r++) {
        int g = r & 3, jj = r >> 2;
        int G = g * 512 + bid * 4 + jj;
        for (int k = tid; k < 512; k += 256) {
            wT1[k * 16 + r]         = Whh1[(size_t)G * 512 + k];
            wT2[k * 16 + r]         = Wih2[(size_t)G * 512 + k];
            wT2[(512 + k) * 16 + r] = Whh2[(size_t)G * 512 + k];
        }
    }
    if (tid < 32) {
        int layer = tid >> 4, r = tid & 15;
        int g = r & 3, jj = r >> 2;
        int G = layer * 2048 + g * 512 + bid * 4 + jj;
        bsum[layer][r] = bih[G] + bhh[G];
    }
    if (tid < 128) {
        int jj = tid >> 5, b = tid & 31, J = bid * 4 + jj;
        c1s[jj][b] = c0[b * 512 + J];
        c2s[jj][b] = c0[16384 + b * 512 + J];
    }
    for (int i = tid; i < 16384; i += 256) {
        int b = i >> 9, k = i & 511;
        hs[(k << 5) | ((b ^ k) & 31)] = g_h1[i];
    }
    __syncthreads();

    for (int t = 0; t < TT; t++) {
        float a0 = 0.f, a1 = 0.f, a2 = 0.f, a3 = 0.f;
        {
            const float* wp = wT1 + q * 4;
            int k0 = half * 256;
            #pragma unroll 8
            for (int k = k0; k < k0 + 256; k++) {
                float4 wv = *(const float4*)(wp + k * 16);
                float hv = hs[(k << 5) | ((k ^ l) & 31)];
                a0 += wv.x * hv; a1 += wv.y * hv; a2 += wv.z * hv; a3 += wv.w * hv;
            }
        }
        gpart[half * 512 + (q * 4 + 0) * 32 + l] = a0;
        gpart[half * 512 + (q * 4 + 1) * 32 + l] = a1;
        gpart[half * 512 + (q * 4 + 2) * 32 + l] = a2;
        gpart[half * 512 + (q * 4 + 3) * 32 + l] = a3;
        __syncthreads();
        if (tid < 128) {
            int jj = tid >> 5, b = tid & 31, J = bid * 4 + jj;
            float gv[4];
            #pragma unroll
            for (int g = 0; g < 4; g++) {
                int r = jj * 4 + g;
                gv[g] = gpart[r * 32 + b] + gpart[512 + r * 32 + b]
                      + g_xw[(size_t)(g * 512 + J) * 1024 + t * 32 + b]
                      + bsum[0][r];
            }
            float cn = sigf(gv[1]) * c1s[jj][b] + sigf(gv[0]) * tanhf(gv[2]);
            float hn = sigf(gv[3]) * tanhf(cn);
            c1s[jj][b] = cn;
            g_h1[b * 512 + J] = hn;
        }
        gridbar(tid);

        for (int i = tid; i < 32768; i += 256) {
            int b = (i >> 9) & 31, k = i & 511;
            int kk = (i < 16384) ? k : (512 + k);
            float v = (i < 16384) ? g_h1[i] : g_h2[i - 16384];
            hs[(kk << 5) | ((b ^ kk) & 31)] = v;
        }
        __syncthreads();

        a0 = a1 = a2 = a3 = 0.f;
        {
            const float* wp = wT2 + q * 4;
            int k0 = half * 512;
            #pragma unroll 8
            for (int k = k0; k < k0 + 512; k++) {
                float4 wv = *(const float4*)(wp + k * 16);
                float hv = hs[(k << 5) | ((k ^ l) & 31)];
                a0 += wv.x * hv; a1 += wv.y * hv; a2 += wv.z * hv; a3 += wv.w * hv;
            }
        }
        __syncthreads();
        gpart[half * 512 + (q * 4 + 0) * 32 + l] = a0;
        gpart[half * 512 + (q * 4 + 1) * 32 + l] = a1;
        gpart[half * 512 + (q * 4 + 2) * 32 + l] = a2;
        gpart[half * 512 + (q * 4 + 3) * 32 + l] = a3;
        __syncthreads();
        if (tid < 128) {
            int jj = tid >> 5, b = tid & 31, J = bid * 4 + jj;
            float gv[4];
            #pragma unroll
            for (int g = 0; g < 4; g++) {
                int r = jj * 4 + g;
                gv[g] = gpart[r * 32 + b] + gpart[512 + r * 32 + b] + bsum[1][r];
            }
            float cn = sigf(gv[1]) * c2s[jj][b] + sigf(gv[0]) * tanhf(gv[2]);
            float hn = sigf(gv[3]) * tanhf(cn);
            c2s[jj][b] = cn;
            g_h2[b * 512 + J] = hn;
            int row = t * 32 + b;
            g_out[(size_t)row * 512 + J] = hn;
            g_cat2[(size_t)row * 1024 + 512 + J] = hn;
            g_call[(size_t)row * 512 + J] = cn;
        }
        gridbar(tid);
    }

    if (tid < 128) {
        int jj = tid >> 5, b = tid & 31, J = bid * 4 + jj;
        g_c1f[b * 512 + J] = c1s[jj][b];
        g_c2f[b * 512 + J] = c2s[jj][b];
    }
}

// ---------------- generic tiled fp32 GEMM (small GEMMs only) ----------------
__global__ void k_gemm(int M, int N, int K,
                       const float* __restrict__ A, int lda, long long sA,
                       const float* __restrict__ B, int ldbn, int ldbk, long long sB,
                       const float* __restrict__ bias,
                       float* __restrict__ C, int ldc, long long sC, int act) {
    A += (size_t)blockIdx.z * sA;
    B += (size_t)blockIdx.z * sB;
    C += (size_t)blockIdx.z * sC;
    __shared__ float As[16][64];
    __shared__ float Bs[16][64];
    int tid = threadIdx.x;
    int tx = tid & 15, ty = tid >> 4;
    int m0 = blockIdx.y * 64, n0 = blockIdx.x * 64;
    int ar = tid >> 2, ak = (tid & 3) * 4;
    float acc[4][4] = {};

    for (int k0 = 0; k0 < K; k0 += 16) {
        float4 av = make_float4(0.f, 0.f, 0.f, 0.f);
        if (m0 + ar < M) av = *(const float4*)(A + (size_t)(m0 + ar) * lda + k0 + ak);
        As[ak + 0][ar] = av.x; As[ak + 1][ar] = av.y;
        As[ak + 2][ar] = av.z; As[ak + 3][ar] = av.w;
        if (ldbk == 1) {
            float4 bq = make_float4(0.f, 0.f, 0.f, 0.f);
            if (n0 + ar < N) bq = *(const float4*)(B + (size_t)(n0 + ar) * ldbn + k0 + ak);
            Bs[ak + 0][ar] = bq.x; Bs[ak + 1][ar] = bq.y;
            Bs[ak + 2][ar] = bq.z; Bs[ak + 3][ar] = bq.w;
        } else {
            #pragma unroll
            for (int e = tid; e < 1024; e += 256) {
                int n = e & 63, kk = e >> 6;
                float v = 0.f;
                if (n0 + n < N) v = B[(size_t)(n0 + n) * ldbn + (size_t)(k0 + kk) * ldbk];
                Bs[kk][n] = v;
            }
        }
        __syncthreads();
        #pragma unroll
        for (int kk = 0; kk < 16; kk++) {
            float4 a = *(const float4*)(&As[kk][ty * 4]);
            float4 bq = *(const float4*)(&Bs[kk][tx * 4]);
            acc[0][0] += a.x * bq.x; acc[0][1] += a.x * bq.y; acc[0][2] += a.x * bq.z; acc[0][3] += a.x * bq.w;
            acc[1][0] += a.y * bq.x; acc[1][1] += a.y * bq.y; acc[1][2] += a.y * bq.z; acc[1][3] += a.y * bq.w;
            acc[2][0] += a.z * bq.x; acc[2][1] += a.z * bq.y; acc[2][2] += a.z * bq.z; acc[2][3] += a.z * bq.w;
            acc[3][0] += a.w * bq.x; acc[3][1] += a.w * bq.y; acc[3][2] += a.w * bq.z; acc[3][3] += a.w * bq.w;
        }
        __syncthreads();
    }

    #pragma unroll
    for (int i = 0; i < 4; i++) {
        int m = m0 + ty * 4 + i;
        if (m >= M) continue;
        #pragma unroll
        for (int jc = 0; jc < 4; jc++) {
            int n = n0 + tx * 4 + jc;
            if (n >= N) continue;
            float v = acc[i][jc];
            if (bias) v += bias[n];
            if (act == 1) v = tanhf(v);
            C[(size_t)m * ldc + n] = v;
        }
    }
}

// ---------------- bf16 HMMA vocab GEMM: logits = h_att @ Wv^T + bv ----------------
// Block tile 128x128, 8 warps (warp tile 64x32), K chunks of 64, smem pad +8.
#define VPAD 72   // 64 + 8 bf16 pad per row

__global__ void __launch_bounds__(256) k_vgemm(
    const __nv_bfloat16* __restrict__ A,   // [1024, 512] bf16 row-major
    const __nv_bfloat16* __restrict__ B,   // [50000, 512] bf16 row-major (n,k)
    const float* __restrict__ bias,
    float* __restrict__ C)                 // [1024, 50000] fp32
{
    __shared__ __nv_bfloat16 As[128 * VPAD];
    __shared__ __nv_bfloat16 Bs[128 * VPAD];

    const int tid = threadIdx.x;
    const int wid = tid >> 5, lane = tid & 31;
    const int m0 = blockIdx.y * 128, n0 = blockIdx.x * 128;
    const int wr = wid >> 2, wc = wid & 3;            // warp tile: (wr*64, wc*32)

    float acc[4][4][4] = {};

    const uint32_t sA = smem_u32(As), sB = smem_u32(Bs);

    for (int kc = 0; kc < 8; kc++) {
        // stage A: 128 rows x 64 bf16 = 1024 uint4; 4 per thread
        #pragma unroll
        for (int it = 0; it < 4; it++) {
            int idx = tid + it * 256;
            int row = idx >> 3, qv = idx & 7;
            uint4 v = *(const uint4*)(A + (size_t)(m0 + row) * HH + kc * 64 + qv * 8);
            *(uint4*)(As + row * VPAD + qv * 8) = v;
        }
        // stage B with n guard
        #pragma unroll
        for (int it = 0; it < 4; it++) {
            int idx = tid + it * 256;
            int row = idx >> 3, qv = idx & 7;
            int n = n0 + row;
            uint4 v = make_uint4(0u, 0u, 0u, 0u);
            if (n < VV) v = *(const uint4*)(B + (size_t)n * HH + kc * 64 + qv * 8);
            *(uint4*)(Bs + row * VPAD + qv * 8) = v;
        }
        __syncthreads();

        #pragma unroll
        for (int ks = 0; ks < 4; ks++) {
            uint32_t af[4][4];
            uint32_t bf[4][2];
            // A fragments: 16x16 at (wr*64 + fm*16, ks*16)
            #pragma unroll
            for (int fm = 0; fm < 4; fm++) {
                int row = wr * 64 + fm * 16 + (lane & 15);
                int col = ks * 16 + ((lane >> 4) << 3);
                uint32_t addr = sA + (row * VPAD + col) * 2;
                asm volatile("ldmatrix.sync.aligned.m8n8.x4.shared.b16 {%0,%1,%2,%3}, [%4];"
                    : "=r"(af[fm][0]), "=r"(af[fm][1]), "=r"(af[fm][2]), "=r"(af[fm][3])
                    : "r"(addr));
            }
            // B fragments: k16 x n8 at (wc*32 + fn*8, ks*16)
            #pragma unroll
            for (int fn = 0; fn < 4; fn++) {
                int row = wc * 32 + fn * 8 + (lane & 7);
                int col = ks * 16 + (((lane >> 3) & 1) << 3);
                uint32_t addr = sB + (row * VPAD + col) * 2;
                asm volatile("ldmatrix.sync.aligned.m8n8.x2.shared.b16 {%0,%1}, [%2];"
                    : "=r"(bf[fn][0]), "=r"(bf[fn][1]) : "r"(addr));
            }
            #pragma unroll
            for (int fm = 0; fm < 4; fm++) {
                #pragma unroll
                for (int fn = 0; fn < 4; fn++) {
                    asm volatile(
                        "mma.sync.aligned.m16n8k16.row.col.f32.bf16.bf16.f32 "
                        "{%0,%1,%2,%3}, {%4,%5,%6,%7}, {%8,%9}, {%0,%1,%2,%3};"
                        : "+f"(acc[fm][fn][0]), "+f"(acc[fm][fn][1]),
                          "+f"(acc[fm][fn][2]), "+f"(acc[fm][fn][3])
                        : "r"(af[fm][0]), "r"(af[fm][1]), "r"(af[fm][2]), "r"(af[fm][3]),
                          "r"(bf[fn][0]), "r"(bf[fn][1]));
                }
            }
        }
        __syncthreads();
    }

    // epilogue: acc layout per mma: d0,d1 -> (row g, col c,c+1); d2,d3 -> (row g+8)
    int gr = lane >> 2, gc = (lane & 3) * 2;
    #pragma unroll
    for (int fm = 0; fm < 4; fm++) {
        int r0 = m0 + wr * 64 + fm * 16 + gr;
        float* crow0 = C + (size_t)r0 * VV;
        float* crow1 = C + (size_t)(r0 + 8) * VV;
        #pragma unroll
        for (int fn = 0; fn < 4; fn++) {
            int c = n0 + wc * 32 + fn * 8 + gc;
            if (c + 1 < VV) {
                float b0 = bias[c], b1 = bias[c + 1];
                crow0[c]     = acc[fm][fn][0] + b0;
                crow0[c + 1] = acc[fm][fn][1] + b1;
                crow1[c]     = acc[fm][fn][2] + b0;
                crow1[c + 1] = acc[fm][fn][3] + b1;
            } else if (c < VV) {
                float b0 = bias[c];
                crow0[c] = acc[fm][fn][0] + b0;
                crow1[c] = acc[fm][fn][2] + b0;
            }
        }
    }
}

// ---------------- attention softmax over S=400 ----------------
__global__ void k_attnsoftmax() {
    int r = blockIdx.x, tid = threadIdx.x;
    __shared__ float vals[SS];
    __shared__ float red[128];
    float m = -1e30f;
    for (int s = tid; s < SS; s += 128) { float v = g_attn[(size_t)r * SS + s]; vals[s] = v; m = fmaxf(m, v); }
    red[tid] = m; __syncthreads();
    for (int o = 64; o > 0; o >>= 1) { if (tid < o) red[tid] = fmaxf(red[tid], red[tid + o]); __syncthreads(); }
    m = red[0]; __syncthreads();
    float sum = 0.f;
    for (int s = tid; s < SS; s += 128) { float e = __expf(vals[s] - m); vals[s] = e; sum += e; }
    red[tid] = sum; __syncthreads();
    for (int o = 64; o > 0; o >>= 1) { if (tid < o) red[tid] += red[tid + o]; __syncthreads(); }
    float inv = 1.f / red[0];
    for (int s = tid; s < SS; s += 128) g_attn[(size_t)r * SS + s] = vals[s] * inv;
}

// ---------------- p_gen ----------------
__global__ void k_pgen(const float* __restrict__ Wg, const float* __restrict__ bg) {
    int warp = threadIdx.x >> 5, lane = threadIdx.x & 31;
    int r = blockIdx.x * 8 + warp;
    float acc = 0.f;
    for (int j = lane; j < 512; j += 32) {
        acc += g_hatt[(size_t)r * HH + j] * Wg[j]
             + g_out [(size_t)r * HH + j] * Wg[512 + j]
             + g_call[(size_t)r * HH + j] * Wg[1024 + j]
             + g_x   [(size_t)r * HH + j] * Wg[1536 + j];
    }
    for (int o = 16; o > 0; o >>= 1) acc += __shfl_down_sync(0xffffffffu, acc, o);
    if (lane == 0) g_pgen[r] = 1.f / (1.f + expf(-(acc + bg[0])));
}

// ---------------- vocab softmax reductions ----------------
__global__ void k_maxsum() {
    int r = blockIdx.x, tid = threadIdx.x;
    __shared__ float red[256];
    const float* row = g_logits + (size_t)r * VV;
    float m = -1e30f;
    for (int v = tid; v < VV; v += 256) m = fmaxf(m, row[v]);
    red[tid] = m; __syncthreads();
    for (int o = 128; o > 0; o >>= 1) { if (tid < o) red[tid] = fmaxf(red[tid], red[tid + o]); __syncthreads(); }
    m = red[0]; __syncthreads();
    float s = 0.f;
    for (int v = tid; v < VV; v += 256) s += __expf(row[v] - m);
    red[tid] = s; __syncthreads();
    for (int o = 128; o > 0; o >>= 1) { if (tid < o) red[tid] += red[tid + o]; __syncthreads(); }
    if (tid == 0) { g_rmax[r] = m; g_rinv[r] = 1.f / red[0]; }
}

// ---------------- base scores ----------------
__global__ void k_scores(float* __restrict__ out) {
    int r = blockIdx.y;
    int v0 = (blockIdx.x * blockDim.x + threadIdx.x) * 4;
    float pg = g_pgen[r], m = g_rmax[r], inv = g_rinv[r];
    float* orow = out + (size_t)r * EXTV;
    const float* lrow = g_logits + (size_t)r * VV;
    #pragma unroll
    for (int i = 0; i < 4; i++) {
        int v = v0 + i;
        if (v >= EXTV) return;
        float sc;
        if (v < VV) {
            float p = __expf(lrow[v] - m) * inv;
            sc = __logf(p * pg + 1e-10f);
        } else {
            sc = __logf(1e-10f);
        }
        orow[v] = sc;
    }
}

// ---------------- copy fixup (last-write-wins) ----------------
__global__ void k_fixup(const int* __restrict__ src, float* __restrict__ out) {
    int r = blockIdx.x, b = r & 31;
    __shared__ int sid[SS];
    int s = threadIdx.x;
    if (s < SS) sid[s] = src[s * BBATCH + b];
    __syncthreads();
    if (s >= SS) return;
    int v = sid[s];
    for (int s2 = s + 1; s2 < SS; s2++) if (sid[s2] == v) return;
    float pg = g_pgen[r];
    float a = g_attn[(size_t)r * SS + s];
    float pv = 0.f;
    if (v < VV) pv = __expf(g_logits[(size_t)r * VV + v] - g_rmax[r]) * g_rinv[r];
    out[(size_t)r * EXTV + v] = __logf(pv * pg + a * (1.f - pg) + 1e-10f);
}

// ---------------- final h, c ----------------
__global__ void k_hc(float* __restrict__ out) {
    int i = blockIdx.x * blockDim.x + threadIdx.x;
    float* dst = out + (size_t)TB * EXTV;
    dst[i]          = g_h1[i];
    dst[16384 + i]  = g_h2[i];
    dst[32768 + i]  = g_c1f[i];
    dst[49152 + i]  = g_c2f[i];
}

// ---------------- launch ----------------
extern "C" void kernel_launch(void* const* d_in, const int* in_sizes, int n_in,
                              void* d_out, int out_size) {
    const int*   ids = (const int*)d_in[0];
    const int*   src = (const int*)d_in[1];
    const float* h0  = (const float*)d_in[2];
    const float* c0  = (const float*)d_in[3];
    const float* ctx = (const float*)d_in[4];
    int base = (in_sizes[5] <= 4) ? 6 : 5;
    const float* emb = (const float*)d_in[base + 0];
    const float* Wih = (const float*)d_in[base + 1];
    const float* bih = (const float*)d_in[base + 2];
    const float* Whh = (const float*)d_in[base + 3];
    const float* bhh = (const float*)d_in[base + 4];
    const float* Wa  = (const float*)d_in[base + 5];
    const float* ba  = (const float*)d_in[base + 6];
    const float* Wo  = (const float*)d_in[base + 7];
    const float* bo  = (const float*)d_in[base + 8];
    const float* Wv  = (const float*)d_in[base + 9];
    const float* bv  = (const float*)d_in[base + 10];
    const float* Wg  = (const float*)d_in[base + 11];
    const float* bg  = (const float*)d_in[base + 12];
    float* out = (float*)d_out;

    float *px, *pxw, *pout, *ph1, *ph2, *pgamma, *pattn, *pcat2, *phatt, *plogits;
    __nv_bfloat16 *phattb, *pwvb;
    cudaGetSymbolAddress((void**)&px,      g_x);
    cudaGetSymbolAddress((void**)&pxw,     g_xw);
    cudaGetSymbolAddress((void**)&pout,    g_out);
    cudaGetSymbolAddress((void**)&ph1,     g_h1);
    cudaGetSymbolAddress((void**)&ph2,     g_h2);
    cudaGetSymbolAddress((void**)&pgamma,  g_gamma);
    cudaGetSymbolAddress((void**)&pattn,   g_attn);
    cudaGetSymbolAddress((void**)&pcat2,   g_cat2);
    cudaGetSymbolAddress((void**)&phatt,   g_hatt);
    cudaGetSymbolAddress((void**)&plogits, g_logits);
    cudaGetSymbolAddress((void**)&phattb,  g_hattb);
    cudaGetSymbolAddress((void**)&pwvb,    g_wvb);

    const int SMEM_PERSIST = (512 * 16 + 1024 * 16 + 1024 * 32) * 4;  // 229376 B
    cudaFuncSetAttribute(k_persist, cudaFuncAttributeMaxDynamicSharedMemorySize, SMEM_PERSIST);

    // 1. embedding + Wv->bf16 (independent)
    k_embed<<<512, 256>>>(ids, emb);
    k_cvt<<<(VV * HH / 4 + 255) / 256, 256>>>(Wv, pwvb, VV * HH / 4);

    // 2. hoist x-contribution of layer 1: g_xw = W_ih1 @ x^T  [2048,1024]
    k_gemm<<<dim3(16, 32, 1), 256>>>(2048, TB, HH, Wih, HH, 0,
                                     px, HH, 1, 0, nullptr, pxw, TB, 0, 0);

    // 3. initial hidden state
    cudaMemcpyAsync(ph1, h0,          16384 * sizeof(float), cudaMemcpyDeviceToDevice, 0);
    cudaMemcpyAsync(ph2, h0 + 16384,  16384 * sizeof(float), cudaMemcpyDeviceToDevice, 0);

    // 4. persistent 2-layer LSTM over all 32 steps
    k_persist<<<NBLK, 256, SMEM_PERSIST>>>(Whh, Wih + 2048 * 512, Whh + 2048 * 512,
                                           bih, bhh, c0);

    // 5. gamma = out @ Wa^T + ba      [1024,512]
    k_gemm<<<dim3(8, 16, 1), 256>>>(TB, HH, HH, pout, HH, 0,
                                    Wa, HH, 1, 0, ba, pgamma, HH, 0, 0);

    // 6. attn logits per b: gamma @ contexts[b]^T   [32,400] x32
    k_gemm<<<dim3(7, 1, 32), 256>>>(BBATCH, SS, HH,
                                    pgamma, BBATCH * HH, HH,
                                    ctx, HH, 1, (long long)SS * HH,
                                    nullptr, pattn, BBATCH * SS, SS, 0);

    // 7. softmax over s
    k_attnsoftmax<<<TB, 128>>>();

    // 8. c_t = attn @ contexts[b]  -> cat2[:, 0:512]
    k_gemm<<<dim3(8, 1, 32), 256>>>(BBATCH, HH, SS,
                                    pattn, BBATCH * SS, SS,
                                    ctx, 1, HH, (long long)SS * HH,
                                    nullptr, pcat2, BBATCH * 2 * HH, 2 * HH, 0);

    // 9. h_att = tanh(cat2 @ Wo^T + bo)   [1024,512], K=1024
    k_gemm<<<dim3(8, 16, 1), 256>>>(TB, HH, 2 * HH, pcat2, 2 * HH, 0,
                                    Wo, 2 * HH, 1, 0, bo, phatt, HH, 0, 1);

    // 10. p_gen + h_att -> bf16
    k_pgen<<<128, 256>>>(Wg, bg);
    k_cvt<<<512, 256>>>(phatt, phattb, TB * HH / 4);

    // 11. vocab logits via bf16 HMMA GEMM   [1024, 50000]
    k_vgemm<<<dim3(391, 8, 1), 256>>>(phattb, pwvb, bv, plogits);

    // 12. softmax reductions, base scores, copy fixup
    k_maxsum<<<TB, 256>>>();
    k_scores<<<dim3(49, TB, 1), 256>>>(out);
    k_fixup<<<TB, 512>>>(src, out);

    // 13. final h, c
    k_hc<<<64, 256>>>(out);
}

// round 9
// speedup vs baseline: 4.8174x; 1.3066x over previous
#include <cuda_runtime.h>
#include <cuda_bf16.h>
#include <cstdint>
#include <math.h>

#define TT 32
#define BBATCH 32
#define HH 512
#define SS 400
#define VV 50000
#define EXTV 50050
#define TB 1024  // TT*BBATCH
#define NBLK 128

// ---------------- scratch (static device arrays; no allocation) ----------------
__device__ float g_x[TB * HH];          // embedded inputs per (t,b)
__device__ float g_xw[2048 * TB];       // precomputed W_ih1 @ x^T : [gate_row][t*32+b]
__device__ float g_out[TB * HH];        // layer-2 h per step (== h[-1] per step)
__device__ float g_call[TB * HH];       // layer-2 c per step (== c[-1] per step)
__device__ float g_h1T[HH * BBATCH];    // current layer-1 h TRANSPOSED [J][b]
__device__ float g_h2T[HH * BBATCH];    // current layer-2 h TRANSPOSED [J][b]
__device__ float g_c1f[BBATCH * HH];    // final c layer 1 [b][J]
__device__ float g_c2f[BBATCH * HH];    // final c layer 2 [b][J]
__device__ float g_gamma[TB * HH];
__device__ float g_attn[TB * SS];
__device__ float g_cat2[TB * 2 * HH];   // [c_t | out]
__device__ float g_hatt[TB * HH];
__device__ float g_pgen[TB];
__device__ float g_rmax[TB];
__device__ float g_rinv[TB];
__device__ float g_logits[(size_t)TB * VV];          // 200 MB
__device__ __nv_bfloat16 g_hattb[TB * HH];           // bf16 h_att
__device__ __nv_bfloat16 g_wvb[(size_t)VV * HH];     // bf16 Wv (51 MB)
__device__ unsigned g_barcnt;
__device__ unsigned g_bargen;

__device__ __forceinline__ uint32_t smem_u32(const void* p) {
    uint32_t a;
    asm("{ .reg .u64 t; cvta.to.shared.u64 t, %1; cvt.u32.u64 %0, t; }" : "=r"(a) : "l"(p));
    return a;
}

// ---------------- embedding ----------------
__global__ void k_embed(const int* __restrict__ ids, const float* __restrict__ emb) {
    int gi = blockIdx.x * blockDim.x + threadIdx.x;
    int r = gi >> 7, e4 = gi & 127;
    int id = ids[r];
    if (id >= VV) id = 1;   // UNK
    float4 v = *(const float4*)(emb + (size_t)id * HH + e4 * 4);
    *(float4*)(g_x + (size_t)r * HH + e4 * 4) = v;
}

// ---------------- fp32 -> bf16 convert ----------------
__global__ void k_cvt(const float* __restrict__ src, __nv_bfloat16* __restrict__ dst, int n4) {
    int i = blockIdx.x * blockDim.x + threadIdx.x;
    if (i >= n4) return;
    float4 v = ((const float4*)src)[i];
    __nv_bfloat162 a = __floats2bfloat162_rn(v.x, v.y);
    __nv_bfloat162 b = __floats2bfloat162_rn(v.z, v.w);
    ((__nv_bfloat162*)dst)[i * 2]     = a;
    ((__nv_bfloat162*)dst)[i * 2 + 1] = b;
}

// ---------------- transpose h0 into g_h1T / g_h2T ----------------
__global__ void k_tr(const float* __restrict__ h0) {
    int i = blockIdx.x * blockDim.x + threadIdx.x;   // 0..32767
    if (i >= 32768) return;
    int layer = i >> 14, rem = i & 16383;
    int J = rem >> 5, b = rem & 31;
    float v = h0[layer * 16384 + b * 512 + J];
    (layer ? g_h2T : g_h1T)[rem] = v;
}

// ---------------- persistent 2-layer LSTM (rebuilt) ----------------
// 128 blocks x 512 threads, 1 block/SM. Block owns h-dims J = bid*4..bid*4+3
// (16 gate rows, local r = jj*4+g) for BOTH layers.
// Warp w: rg = w>>3 (gate-row group: rows rg*8..rg*8+7), oct = w&7 (K-eighth).
// h exchanged in TRANSPOSED gmem layout [J][b] -> staging is a straight
// coalesced float4 copy; hs[k][b] plain layout is conflict-free everywhere.

__device__ __forceinline__ float sigf(float x) { return 1.0f / (1.0f + expf(-x)); }

__device__ __forceinline__ void gridbar(int tid) {
    __syncthreads();
    if (tid == 0) {
        __threadfence();
        unsigned gen = *(volatile unsigned*)&g_bargen;
        unsigned old = atomicAdd(&g_barcnt, 1u);
        if (old == NBLK - 1) {
            atomicExch(&g_barcnt, 0u);
            __threadfence();
            atomicAdd(&g_bargen, 1u);
        } else {
            while (*(volatile unsigned*)&g_bargen == gen) { }
        }
        __threadfence();
    }
    __syncthreads();
}

__global__ void __launch_bounds__(512, 1) k_persist(
    const float* __restrict__ Whh1, const float* __restrict__ Wih2,
    const float* __restrict__ Whh2,
    const float* __restrict__ bih, const float* __restrict__ bhh,
    const float* __restrict__ c0)
{
    extern __shared__ float sm[];
    float* wT1 = sm;                         // [512][16]   32 KB
    float* wT2 = sm + 512 * 16;              // [1024][16]  64 KB
    float* hs  = sm + 512 * 16 + 1024 * 16;  // [1024][32] 128 KB (plain [k][b])
    float* gpart = hs + 512 * 32;            // 8*16*32 = 4096 floats, alias hs rows 512..639

    __shared__ float c1s[4][32], c2s[4][32], bsum[2][16];

    const int tid = threadIdx.x;
    const int bid = blockIdx.x;
    const int w = tid >> 5, l = tid & 31;
    const int rg = w >> 3;          // 0..1 : rows rg*8 .. rg*8+7
    const int oct = w & 7;          // 0..7 : K-eighth

    // ---- one-time: weight slices into smem, transposed [k][16] ----
    #pragma unroll 1
    for (int r = 0; r < 16; r++) {
        int g = r & 3, jj = r >> 2;
        int G = g * 512 + bid * 4 + jj;
        int k = tid;   // 512 threads cover 512 k
        wT1[k * 16 + r]         = Whh1[(size_t)G * 512 + k];
        wT2[k * 16 + r]         = Wih2[(size_t)G * 512 + k];
        wT2[(512 + k) * 16 + r] = Whh2[(size_t)G * 512 + k];
    }
    if (tid < 32) {
        int layer = tid >> 4, r = tid & 15;
        int g = r & 3, jj = r >> 2;
        int G = layer * 2048 + g * 512 + bid * 4 + jj;
        bsum[layer][r] = bih[G] + bhh[G];
    }
    if (tid < 128) {
        int jj = tid >> 5, b = tid & 31, J = bid * 4 + jj;
        c1s[jj][b] = c0[b * 512 + J];
        c2s[jj][b] = c0[16384 + b * 512 + J];
    }
    // initial stage: hs rows 0..511 <- g_h1T (straight copy)
    {
        float4* dst4 = (float4*)hs;
        const float4* s1 = (const float4*)g_h1T;
        #pragma unroll
        for (int j = 0; j < 8; j++) dst4[tid + j * 512] = s1[tid + j * 512];
    }
    __syncthreads();

    for (int t = 0; t < TT; t++) {
        // ---- layer 1 inner: rows rg*8..+7, k in [oct*64, oct*64+64) ----
        {
            float a0 = 0.f, a1 = 0.f, a2 = 0.f, a3 = 0.f;
            float a4 = 0.f, a5 = 0.f, a6 = 0.f, a7 = 0.f;
            const float* wp = wT1 + rg * 8;
            const int k0 = oct * 64;
            #pragma unroll 8
            for (int k = k0; k < k0 + 64; k++) {
                float4 w0 = *(const float4*)(wp + k * 16);
                float4 w1 = *(const float4*)(wp + k * 16 + 4);
                float hv = hs[k * 32 + l];
                a0 += w0.x * hv; a1 += w0.y * hv; a2 += w0.z * hv; a3 += w0.w * hv;
                a4 += w1.x * hv; a5 += w1.y * hv; a6 += w1.z * hv; a7 += w1.w * hv;
            }
            float* gp = gpart + oct * 512 + rg * 8 * 32 + l;
            gp[0] = a0; gp[32] = a1; gp[64] = a2; gp[96] = a3;
            gp[128] = a4; gp[160] = a5; gp[192] = a6; gp[224] = a7;
        }
        __syncthreads();
        if (tid < 128) {
            int jj = tid >> 5, b = tid & 31, J = bid * 4 + jj;
            float gv[4];
            #pragma unroll
            for (int g = 0; g < 4; g++) {
                int r = jj * 4 + g;
                float s = bsum[0][r] + g_xw[(size_t)(g * 512 + J) * 1024 + t * 32 + b];
                #pragma unroll
                for (int o = 0; o < 8; o++) s += gpart[o * 512 + r * 32 + b];
                gv[g] = s;
            }
            float cn = sigf(gv[1]) * c1s[jj][b] + sigf(gv[0]) * tanhf(gv[2]);
            float hn = sigf(gv[3]) * tanhf(cn);
            c1s[jj][b] = cn;
            g_h1T[J * 32 + b] = hn;
        }
        gridbar(tid);

        // ---- stage [h1new ; h2prev] into hs rows 0..1023 (straight copy) ----
        {
            float4* dst4 = (float4*)hs;
            const float4* s1 = (const float4*)g_h1T;
            const float4* s2 = (const float4*)g_h2T;
            #pragma unroll
            for (int j = 0; j < 8; j++)  dst4[tid + j * 512] = __ldcg(s1 + tid + j * 512);
            #pragma unroll
            for (int j = 8; j < 16; j++) dst4[tid + j * 512] = __ldcg(s2 + tid + (j - 8) * 512);
        }
        __syncthreads();

        // ---- layer 2 inner: k in [oct*128, oct*128+128) over 1024 ----
        {
            float a0 = 0.f, a1 = 0.f, a2 = 0.f, a3 = 0.f;
            float a4 = 0.f, a5 = 0.f, a6 = 0.f, a7 = 0.f;
            const float* wp = wT2 + rg * 8;
            const int k0 = oct * 128;
            #pragma unroll 8
            for (int k = k0; k < k0 + 128; k++) {
                float4 w0 = *(const float4*)(wp + k * 16);
                float4 w1 = *(const float4*)(wp + k * 16 + 4);
                float hv = hs[k * 32 + l];
                a0 += w0.x * hv; a1 += w0.y * hv; a2 += w0.z * hv; a3 += w0.w * hv;
                a4 += w1.x * hv; a5 += w1.y * hv; a6 += w1.z * hv; a7 += w1.w * hv;
            }
            __syncthreads();   // all hs reads done before gpart alias overwrite
            float* gp = gpart + oct * 512 + rg * 8 * 32 + l;
            gp[0] = a0; gp[32] = a1; gp[64] = a2; gp[96] = a3;
            gp[128] = a4; gp[160] = a5; gp[192] = a6; gp[224] = a7;
        }
        __syncthreads();
        if (tid < 128) {
            int jj = tid >> 5, b = tid & 31, J = bid * 4 + jj;
            float gv[4];
            #pragma unroll
            for (int g = 0; g < 4; g++) {
                int r = jj * 4 + g;
                float s = bsum[1][r];
                #pragma unroll
                for (int o = 0; o < 8; o++) s += gpart[o * 512 + r * 32 + b];
                gv[g] = s;
            }
            float cn = sigf(gv[1]) * c2s[jj][b] + sigf(gv[0]) * tanhf(gv[2]);
            float hn = sigf(gv[3]) * tanhf(cn);
            c2s[jj][b] = cn;
            g_h2T[J * 32 + b] = hn;
            int row = t * 32 + b;
            g_out[(size_t)row * 512 + J] = hn;
            g_cat2[(size_t)row * 1024 + 512 + J] = hn;
            g_call[(size_t)row * 512 + J] = cn;
        }
        gridbar(tid);
        // hs rows 0..511 keep this step's h1 -> reused by next step's layer 1
    }

    if (tid < 128) {
        int jj = tid >> 5, b = tid & 31, J = bid * 4 + jj;
        g_c1f[b * 512 + J] = c1s[jj][b];
        g_c2f[b * 512 + J] = c2s[jj][b];
    }
}

// ---------------- generic tiled fp32 GEMM (small GEMMs only) ----------------
__global__ void k_gemm(int M, int N, int K,
                       const float* __restrict__ A, int lda, long long sA,
                       const float* __restrict__ B, int ldbn, int ldbk, long long sB,
                       const float* __restrict__ bias,
                       float* __restrict__ C, int ldc, long long sC, int act) {
    A += (size_t)blockIdx.z * sA;
    B += (size_t)blockIdx.z * sB;
    C += (size_t)blockIdx.z * sC;
    __shared__ float As[16][64];
    __shared__ float Bs[16][64];
    int tid = threadIdx.x;
    int tx = tid & 15, ty = tid >> 4;
    int m0 = blockIdx.y * 64, n0 = blockIdx.x * 64;
    int ar = tid >> 2, ak = (tid & 3) * 4;
    float acc[4][4] = {};

    for (int k0 = 0; k0 < K; k0 += 16) {
        float4 av = make_float4(0.f, 0.f, 0.f, 0.f);
        if (m0 + ar < M) av = *(const float4*)(A + (size_t)(m0 + ar) * lda + k0 + ak);
        As[ak + 0][ar] = av.x; As[ak + 1][ar] = av.y;
        As[ak + 2][ar] = av.z; As[ak + 3][ar] = av.w;
        if (ldbk == 1) {
            float4 bq = make_float4(0.f, 0.f, 0.f, 0.f);
            if (n0 + ar < N) bq = *(const float4*)(B + (size_t)(n0 + ar) * ldbn + k0 + ak);
            Bs[ak + 0][ar] = bq.x; Bs[ak + 1][ar] = bq.y;
            Bs[ak + 2][ar] = bq.z; Bs[ak + 3][ar] = bq.w;
        } else {
            #pragma unroll
            for (int e = tid; e < 1024; e += 256) {
                int n = e & 63, kk = e >> 6;
                float v = 0.f;
                if (n0 + n < N) v = B[(size_t)(n0 + n) * ldbn + (size_t)(k0 + kk) * ldbk];
                Bs[kk][n] = v;
            }
        }
        __syncthreads();
        #pragma unroll
        for (int kk = 0; kk < 16; kk++) {
            float4 a = *(const float4*)(&As[kk][ty * 4]);
            float4 bq = *(const float4*)(&Bs[kk][tx * 4]);
            acc[0][0] += a.x * bq.x; acc[0][1] += a.x * bq.y; acc[0][2] += a.x * bq.z; acc[0][3] += a.x * bq.w;
            acc[1][0] += a.y * bq.x; acc[1][1] += a.y * bq.y; acc[1][2] += a.y * bq.z; acc[1][3] += a.y * bq.w;
            acc[2][0] += a.z * bq.x; acc[2][1] += a.z * bq.y; acc[2][2] += a.z * bq.z; acc[2][3] += a.z * bq.w;
            acc[3][0] += a.w * bq.x; acc[3][1] += a.w * bq.y; acc[3][2] += a.w * bq.z; acc[3][3] += a.w * bq.w;
        }
        __syncthreads();
    }

    #pragma unroll
    for (int i = 0; i < 4; i++) {
        int m = m0 + ty * 4 + i;
        if (m >= M) continue;
        #pragma unroll
        for (int jc = 0; jc < 4; jc++) {
            int n = n0 + tx * 4 + jc;
            if (n >= N) continue;
            float v = acc[i][jc];
            if (bias) v += bias[n];
            if (act == 1) v = tanhf(v);
            C[(size_t)m * ldc + n] = v;
        }
    }
}

// ---------------- bf16 HMMA vocab GEMM (register-prefetch double-buffered) ----------------
#define VPAD 72   // 64 + 8 bf16 pad per row

__global__ void __launch_bounds__(256) k_vgemm(
    const __nv_bfloat16* __restrict__ A,   // [1024, 512] bf16 row-major
    const __nv_bfloat16* __restrict__ B,   // [50000, 512] bf16 row-major (n,k)
    const float* __restrict__ bias,
    float* __restrict__ C)                 // [1024, 50000] fp32
{
    __shared__ __nv_bfloat16 As[128 * VPAD];
    __shared__ __nv_bfloat16 Bs[128 * VPAD];

    const int tid = threadIdx.x;
    const int wid = tid >> 5, lane = tid & 31;
    const int m0 = blockIdx.y * 128, n0 = blockIdx.x * 128;
    const int wr = wid >> 2, wc = wid & 3;

    float acc[4][4][4] = {};
    const uint32_t sA = smem_u32(As), sB = smem_u32(Bs);

    uint4 pa[4], pb[4];
    // prefetch chunk 0
    #pragma unroll
    for (int it = 0; it < 4; it++) {
        int idx = tid + it * 256;
        int row = idx >> 3, qv = idx & 7;
        pa[it] = *(const uint4*)(A + (size_t)(m0 + row) * HH + qv * 8);
        int n = n0 + row;
        pb[it] = make_uint4(0u, 0u, 0u, 0u);
        if (n < VV) pb[it] = *(const uint4*)(B + (size_t)n * HH + qv * 8);
    }

    for (int kc = 0; kc < 8; kc++) {
        // commit prefetched chunk to smem
        #pragma unroll
        for (int it = 0; it < 4; it++) {
            int idx = tid + it * 256;
            int row = idx >> 3, qv = idx & 7;
            *(uint4*)(As + row * VPAD + qv * 8) = pa[it];
            *(uint4*)(Bs + row * VPAD + qv * 8) = pb[it];
        }
        __syncthreads();
        // prefetch next chunk (overlaps with MMA below)
        if (kc < 7) {
            #pragma unroll
            for (int it = 0; it < 4; it++) {
                int idx = tid + it * 256;
                int row = idx >> 3, qv = idx & 7;
                pa[it] = *(const uint4*)(A + (size_t)(m0 + row) * HH + (kc + 1) * 64 + qv * 8);
                int n = n0 + row;
                pb[it] = make_uint4(0u, 0u, 0u, 0u);
                if (n < VV) pb[it] = *(const uint4*)(B + (size_t)n * HH + (kc + 1) * 64 + qv * 8);
            }
        }

        #pragma unroll
        for (int ks = 0; ks < 4; ks++) {
            uint32_t af[4][4];
            uint32_t bf[4][2];
            #pragma unroll
            for (int fm = 0; fm < 4; fm++) {
                int row = wr * 64 + fm * 16 + (lane & 15);
                int col = ks * 16 + ((lane >> 4) << 3);
                uint32_t addr = sA + (row * VPAD + col) * 2;
                asm volatile("ldmatrix.sync.aligned.m8n8.x4.shared.b16 {%0,%1,%2,%3}, [%4];"
                    : "=r"(af[fm][0]), "=r"(af[fm][1]), "=r"(af[fm][2]), "=r"(af[fm][3])
                    : "r"(addr));
            }
            #pragma unroll
            for (int fn = 0; fn < 4; fn++) {
                int row = wc * 32 + fn * 8 + (lane & 7);
                int col = ks * 16 + (((lane >> 3) & 1) << 3);
                uint32_t addr = sB + (row * VPAD + col) * 2;
                asm volatile("ldmatrix.sync.aligned.m8n8.x2.shared.b16 {%0,%1}, [%2];"
                    : "=r"(bf[fn][0]), "=r"(bf[fn][1]) : "r"(addr));
            }
            #pragma unroll
            for (int fm = 0; fm < 4; fm++) {
                #pragma unroll
                for (int fn = 0; fn < 4; fn++) {
                    asm volatile(
                        "mma.sync.aligned.m16n8k16.row.col.f32.bf16.bf16.f32 "
                        "{%0,%1,%2,%3}, {%4,%5,%6,%7}, {%8,%9}, {%0,%1,%2,%3};"
                        : "+f"(acc[fm][fn][0]), "+f"(acc[fm][fn][1]),
                          "+f"(acc[fm][fn][2]), "+f"(acc[fm][fn][3])
                        : "r"(af[fm][0]), "r"(af[fm][1]), "r"(af[fm][2]), "r"(af[fm][3]),
                          "r"(bf[fn][0]), "r"(bf[fn][1]));
                }
            }
        }
        __syncthreads();
    }

    int gr = lane >> 2, gc = (lane & 3) * 2;
    #pragma unroll
    for (int fm = 0; fm < 4; fm++) {
        int r0 = m0 + wr * 64 + fm * 16 + gr;
        float* crow0 = C + (size_t)r0 * VV;
        float* crow1 = C + (size_t)(r0 + 8) * VV;
        #pragma unroll
        for (int fn = 0; fn < 4; fn++) {
            int c = n0 + wc * 32 + fn * 8 + gc;
            if (c + 1 < VV) {
                float b0 = bias[c], b1 = bias[c + 1];
                crow0[c]     = acc[fm][fn][0] + b0;
                crow0[c + 1] = acc[fm][fn][1] + b1;
                crow1[c]     = acc[fm][fn][2] + b0;
                crow1[c + 1] = acc[fm][fn][3] + b1;
            } else if (c < VV) {
                float b0 = bias[c];
                crow0[c] = acc[fm][fn][0] + b0;
                crow1[c] = acc[fm][fn][2] + b0;
            }
        }
    }
}

// ---------------- attention softmax over S=400 ----------------
__global__ void k_attnsoftmax() {
    int r = blockIdx.x, tid = threadIdx.x;
    __shared__ float vals[SS];
    __shared__ float red[128];
    float m = -1e30f;
    for (int s = tid; s < SS; s += 128) { float v = g_attn[(size_t)r * SS + s]; vals[s] = v; m = fmaxf(m, v); }
    red[tid] = m; __syncthreads();
    for (int o = 64; o > 0; o >>= 1) { if (tid < o) red[tid] = fmaxf(red[tid], red[tid + o]); __syncthreads(); }
    m = red[0]; __syncthreads();
    float sum = 0.f;
    for (int s = tid; s < SS; s += 128) { float e = __expf(vals[s] - m); vals[s] = e; sum += e; }
    red[tid] = sum; __syncthreads();
    for (int o = 64; o > 0; o >>= 1) { if (tid < o) red[tid] += red[tid + o]; __syncthreads(); }
    float inv = 1.f / red[0];
    for (int s = tid; s < SS; s += 128) g_attn[(size_t)r * SS + s] = vals[s] * inv;
}

// ---------------- p_gen ----------------
__global__ void k_pgen(const float* __restrict__ Wg, const float* __restrict__ bg) {
    int warp = threadIdx.x >> 5, lane = threadIdx.x & 31;
    int r = blockIdx.x * 8 + warp;
    float acc = 0.f;
    for (int j = lane; j < 512; j += 32) {
        acc += g_hatt[(size_t)r * HH + j] * Wg[j]
             + g_out [(size_t)r * HH + j] * Wg[512 + j]
             + g_call[(size_t)r * HH + j] * Wg[1024 + j]
             + g_x   [(size_t)r * HH + j] * Wg[1536 + j];
    }
    for (int o = 16; o > 0; o >>= 1) acc += __shfl_down_sync(0xffffffffu, acc, o);
    if (lane == 0) g_pgen[r] = 1.f / (1.f + expf(-(acc + bg[0])));
}

// ---------------- vocab softmax reductions ----------------
__global__ void k_maxsum() {
    int r = blockIdx.x, tid = threadIdx.x;
    __shared__ float red[256];
    const float* row = g_logits + (size_t)r * VV;
    float m = -1e30f;
    for (int v = tid; v < VV; v += 256) m = fmaxf(m, row[v]);
    red[tid] = m; __syncthreads();
    for (int o = 128; o > 0; o >>= 1) { if (tid < o) red[tid] = fmaxf(red[tid], red[tid + o]); __syncthreads(); }
    m = red[0]; __syncthreads();
    float s = 0.f;
    for (int v = tid; v < VV; v += 256) s += __expf(row[v] - m);
    red[tid] = s; __syncthreads();
    for (int o = 128; o > 0; o >>= 1) { if (tid < o) red[tid] += red[tid + o]; __syncthreads(); }
    if (tid == 0) { g_rmax[r] = m; g_rinv[r] = 1.f / red[0]; }
}

// ---------------- base scores ----------------
__global__ void k_scores(float* __restrict__ out) {
    int r = blockIdx.y;
    int v0 = (blockIdx.x * blockDim.x + threadIdx.x) * 4;
    float pg = g_pgen[r], m = g_rmax[r], inv = g_rinv[r];
    float* orow = out + (size_t)r * EXTV;
    const float* lrow = g_logits + (size_t)r * VV;
    #pragma unroll
    for (int i = 0; i < 4; i++) {
        int v = v0 + i;
        if (v >= EXTV) return;
        float sc;
        if (v < VV) {
            float p = __expf(lrow[v] - m) * inv;
            sc = __logf(p * pg + 1e-10f);
        } else {
            sc = __logf(1e-10f);
        }
        orow[v] = sc;
    }
}

// ---------------- copy fixup (last-write-wins) ----------------
__global__ void k_fixup(const int* __restrict__ src, float* __restrict__ out) {
    int r = blockIdx.x, b = r & 31;
    __shared__ int sid[SS];
    int s = threadIdx.x;
    if (s < SS) sid[s] = src[s * BBATCH + b];
    __syncthreads();
    if (s >= SS) return;
    int v = sid[s];
    for (int s2 = s + 1; s2 < SS; s2++) if (sid[s2] == v) return;
    float pg = g_pgen[r];
    float a = g_attn[(size_t)r * SS + s];
    float pv = 0.f;
    if (v < VV) pv = __expf(g_logits[(size_t)r * VV + v] - g_rmax[r]) * g_rinv[r];
    out[(size_t)r * EXTV + v] = __logf(pv * pg + a * (1.f - pg) + 1e-10f);
}

// ---------------- final h, c ----------------
__global__ void k_hc(float* __restrict__ out) {
    int i = blockIdx.x * blockDim.x + threadIdx.x;   // 16384 threads
    float* dst = out + (size_t)TB * EXTV;
    int b = i >> 9, J = i & 511;
    dst[i]          = g_h1T[J * 32 + b];
    dst[16384 + i]  = g_h2T[J * 32 + b];
    dst[32768 + i]  = g_c1f[i];
    dst[49152 + i]  = g_c2f[i];
}

// ---------------- launch ----------------
extern "C" void kernel_launch(void* const* d_in, const int* in_sizes, int n_in,
                              void* d_out, int out_size) {
    const int*   ids = (const int*)d_in[0];
    const int*   src = (const int*)d_in[1];
    const float* h0  = (const float*)d_in[2];
    const float* c0  = (const float*)d_in[3];
    const float* ctx = (const float*)d_in[4];
    int base = (in_sizes[5] <= 4) ? 6 : 5;
    const float* emb = (const float*)d_in[base + 0];
    const float* Wih = (const float*)d_in[base + 1];
    const float* bih = (const float*)d_in[base + 2];
    const float* Whh = (const float*)d_in[base + 3];
    const float* bhh = (const float*)d_in[base + 4];
    const float* Wa  = (const float*)d_in[base + 5];
    const float* ba  = (const float*)d_in[base + 6];
    const float* Wo  = (const float*)d_in[base + 7];
    const float* bo  = (const float*)d_in[base + 8];
    const float* Wv  = (const float*)d_in[base + 9];
    const float* bv  = (const float*)d_in[base + 10];
    const float* Wg  = (const float*)d_in[base + 11];
    const float* bg  = (const float*)d_in[base + 12];
    float* out = (float*)d_out;

    float *px, *pxw, *pout, *pgamma, *pattn, *pcat2, *phatt, *plogits;
    __nv_bfloat16 *phattb, *pwvb;
    cudaGetSymbolAddress((void**)&px,      g_x);
    cudaGetSymbolAddress((void**)&pxw,     g_xw);
    cudaGetSymbolAddress((void**)&pout,    g_out);
    cudaGetSymbolAddress((void**)&pgamma,  g_gamma);
    cudaGetSymbolAddress((void**)&pattn,   g_attn);
    cudaGetSymbolAddress((void**)&pcat2,   g_cat2);
    cudaGetSymbolAddress((void**)&phatt,   g_hatt);
    cudaGetSymbolAddress((void**)&plogits, g_logits);
    cudaGetSymbolAddress((void**)&phattb,  g_hattb);
    cudaGetSymbolAddress((void**)&pwvb,    g_wvb);

    const int SMEM_PERSIST = (512 * 16 + 1024 * 16 + 1024 * 32) * 4;  // 229376 B
    cudaFuncSetAttribute(k_persist, cudaFuncAttributeMaxDynamicSharedMemorySize, SMEM_PERSIST);

    // 1. embedding + Wv->bf16 + h0 transpose (independent)
    k_embed<<<512, 256>>>(ids, emb);
    k_cvt<<<(VV * HH / 4 + 255) / 256, 256>>>(Wv, pwvb, VV * HH / 4);
    k_tr<<<64, 512>>>(h0);

    // 2. hoist x-contribution of layer 1: g_xw = W_ih1 @ x^T  [2048,1024]
    k_gemm<<<dim3(16, 32, 1), 256>>>(2048, TB, HH, Wih, HH, 0,
                                     px, HH, 1, 0, nullptr, pxw, TB, 0, 0);

    // 3. persistent 2-layer LSTM over all 32 steps
    k_persist<<<NBLK, 512, SMEM_PERSIST>>>(Whh, Wih + 2048 * 512, Whh + 2048 * 512,
                                           bih, bhh, c0);

    // 4. gamma = out @ Wa^T + ba      [1024,512]
    k_gemm<<<dim3(8, 16, 1), 256>>>(TB, HH, HH, pout, HH, 0,
                                    Wa, HH, 1, 0, ba, pgamma, HH, 0, 0);

    // 5. attn logits per b: gamma @ contexts[b]^T   [32,400] x32
    k_gemm<<<dim3(7, 1, 32), 256>>>(BBATCH, SS, HH,
                                    pgamma, BBATCH * HH, HH,
                                    ctx, HH, 1, (long long)SS * HH,
                                    nullptr, pattn, BBATCH * SS, SS, 0);

    // 6. softmax over s
    k_attnsoftmax<<<TB, 128>>>();

    // 7. c_t = attn @ contexts[b]  -> cat2[:, 0:512]
    k_gemm<<<dim3(8, 1, 32), 256>>>(BBATCH, HH, SS,
                                    pattn, BBATCH * SS, SS,
                                    ctx, 1, HH, (long long)SS * HH,
                                    nullptr, pcat2, BBATCH * 2 * HH, 2 * HH, 0);

    // 8. h_att = tanh(cat2 @ Wo^T + bo)   [1024,512], K=1024
    k_gemm<<<dim3(8, 16, 1), 256>>>(TB, HH, 2 * HH, pcat2, 2 * HH, 0,
                                    Wo, 2 * HH, 1, 0, bo, phatt, HH, 0, 1);

    // 9. p_gen + h_att -> bf16
    k_pgen<<<128, 256>>>(Wg, bg);
    k_cvt<<<512, 256>>>(phatt, phattb, TB * HH / 4);

    // 10. vocab logits via bf16 HMMA GEMM   [1024, 50000]
    k_vgemm<<<dim3(391, 8, 1), 256>>>(phattb, pwvb, bv, plogits);

    // 11. softmax reductions, base scores, copy fixup
    k_maxsum<<<TB, 256>>>();
    k_scores<<<dim3(49, TB, 1), 256>>>(out);
    k_fixup<<<TB, 512>>>(src, out);

    // 12. final h, c
    k_hc<<<64, 256>>>(out);
}

// round 10
// speedup vs baseline: 5.4634x; 1.1341x over previous
#include <cuda_runtime.h>
#include <cuda_bf16.h>
#include <cstdint>
#include <math.h>

#define TT 32
#define BBATCH 32
#define HH 512
#define SS 400
#define VV 50000
#define EXTV 50050
#define TB 1024  // TT*BBATCH
#define NBLK 128
#define NBX_V 391   // vocab n-tiles

// ---------------- scratch (static device arrays; no allocation) ----------------
__device__ float g_x[TB * HH];          // embedded inputs per (t,b)
__device__ float g_xw[2048 * TB];       // precomputed W_ih1 @ x^T : [gate_row][t*32+b]
__device__ float g_out[TB * HH];        // layer-2 h per step
__device__ float g_call[TB * HH];       // layer-2 c per step
__device__ float g_h1T[HH * BBATCH];    // current layer-1 h TRANSPOSED [J][b]
__device__ float g_h2T[HH * BBATCH];    // current layer-2 h TRANSPOSED [J][b]
__device__ float g_c1f[BBATCH * HH];
__device__ float g_c2f[BBATCH * HH];
__device__ float g_gamma[TB * HH];
__device__ float g_attn[TB * SS];
__device__ float g_cat2[TB * 2 * HH];   // [c_t | out]
__device__ float g_hatt[TB * HH];
__device__ float g_pgen[TB];
__device__ float g_rinv[TB];
__device__ float g_sumpart[TB * NBX_V]; // per-(row, n-tile) exp-sum partials
__device__ float g_logits[(size_t)TB * VV];          // 200 MB
__device__ __nv_bfloat16 g_hattb[TB * HH];
__device__ __nv_bfloat16 g_wvb[(size_t)VV * HH];     // bf16 Wv
__device__ __nv_bfloat16 g_xb[TB * HH];              // bf16 x
__device__ __nv_bfloat16 g_wi1b[2048 * HH];          // bf16 W_ih layer 1
__device__ __nv_bfloat16 g_cat2b[TB * 2 * HH];       // bf16 cat2
__device__ __nv_bfloat16 g_wob[HH * 2 * HH];         // bf16 Wo
__device__ unsigned g_barcnt;
__device__ unsigned g_bargen;

__device__ __forceinline__ uint32_t smem_u32(const void* p) {
    uint32_t a;
    asm("{ .reg .u64 t; cvta.to.shared.u64 t, %1; cvt.u32.u64 %0, t; }" : "=r"(a) : "l"(p));
    return a;
}

// ---------------- embedding ----------------
__global__ void k_embed(const int* __restrict__ ids, const float* __restrict__ emb) {
    int gi = blockIdx.x * blockDim.x + threadIdx.x;
    int r = gi >> 7, e4 = gi & 127;
    int id = ids[r];
    if (id >= VV) id = 1;   // UNK
    float4 v = *(const float4*)(emb + (size_t)id * HH + e4 * 4);
    *(float4*)(g_x + (size_t)r * HH + e4 * 4) = v;
}

// ---------------- fp32 -> bf16 convert ----------------
__global__ void k_cvt(const float* __restrict__ src, __nv_bfloat16* __restrict__ dst, int n4) {
    int i = blockIdx.x * blockDim.x + threadIdx.x;
    if (i >= n4) return;
    float4 v = ((const float4*)src)[i];
    __nv_bfloat162 a = __floats2bfloat162_rn(v.x, v.y);
    __nv_bfloat162 b = __floats2bfloat162_rn(v.z, v.w);
    ((__nv_bfloat162*)dst)[i * 2]     = a;
    ((__nv_bfloat162*)dst)[i * 2 + 1] = b;
}

// ---------------- transpose h0 into g_h1T / g_h2T ----------------
__global__ void k_tr(const float* __restrict__ h0) {
    int i = blockIdx.x * blockDim.x + threadIdx.x;
    if (i >= 32768) return;
    int layer = i >> 14, rem = i & 16383;
    int J = rem >> 5, b = rem & 31;
    float v = h0[layer * 16384 + b * 512 + J];
    (layer ? g_h2T : g_h1T)[rem] = v;
}

// ---------------- persistent 2-layer LSTM ----------------
__device__ __forceinline__ float sigf(float x) { return 1.0f / (1.0f + expf(-x)); }

__device__ __forceinline__ void gridbar(int tid) {
    __syncthreads();
    if (tid == 0) {
        __threadfence();
        unsigned gen = *(volatile unsigned*)&g_bargen;
        unsigned old = atomicAdd(&g_barcnt, 1u);
        if (old == NBLK - 1) {
            atomicExch(&g_barcnt, 0u);
            __threadfence();
            atomicAdd(&g_bargen, 1u);
        } else {
            while (*(volatile unsigned*)&g_bargen == gen) { }
        }
        __threadfence();
    }
    __syncthreads();
}

__global__ void __launch_bounds__(512, 1) k_persist(
    const float* __restrict__ Whh1, const float* __restrict__ Wih2,
    const float* __restrict__ Whh2,
    const float* __restrict__ bih, const float* __restrict__ bhh,
    const float* __restrict__ c0)
{
    extern __shared__ float sm[];
    float* wT1 = sm;                         // [512][16]   32 KB
    float* wT2 = sm + 512 * 16;              // [1024][16]  64 KB
    float* hs  = sm + 512 * 16 + 1024 * 16;  // [1024][32] 128 KB
    float* gpart = hs + 512 * 32;            // alias hs rows 512..639

    __shared__ float c1s[4][32], c2s[4][32], bsum[2][16];

    const int tid = threadIdx.x;
    const int bid = blockIdx.x;
    const int w = tid >> 5, l = tid & 31;
    const int rg = w >> 3;
    const int oct = w & 7;

    #pragma unroll 1
    for (int r = 0; r < 16; r++) {
        int g = r & 3, jj = r >> 2;
        int G = g * 512 + bid * 4 + jj;
        int k = tid;
        wT1[k * 16 + r]         = Whh1[(size_t)G * 512 + k];
        wT2[k * 16 + r]         = Wih2[(size_t)G * 512 + k];
        wT2[(512 + k) * 16 + r] = Whh2[(size_t)G * 512 + k];
    }
    if (tid < 32) {
        int layer = tid >> 4, r = tid & 15;
        int g = r & 3, jj = r >> 2;
        int G = layer * 2048 + g * 512 + bid * 4 + jj;
        bsum[layer][r] = bih[G] + bhh[G];
    }
    if (tid < 128) {
        int jj = tid >> 5, b = tid & 31, J = bid * 4 + jj;
        c1s[jj][b] = c0[b * 512 + J];
        c2s[jj][b] = c0[16384 + b * 512 + J];
    }
    {
        float4* dst4 = (float4*)hs;
        const float4* s1 = (const float4*)g_h1T;
        #pragma unroll
        for (int j = 0; j < 8; j++) dst4[tid + j * 512] = s1[tid + j * 512];
    }
    __syncthreads();

    for (int t = 0; t < TT; t++) {
        // prefetch h2prev into registers (stable since previous gridbar)
        float4 ph2[8];
        {
            const float4* s2 = (const float4*)g_h2T;
            #pragma unroll
            for (int j = 0; j < 8; j++) ph2[j] = __ldcg(s2 + tid + j * 512);
        }

        // ---- layer 1 inner ----
        {
            float a0 = 0.f, a1 = 0.f, a2 = 0.f, a3 = 0.f;
            float a4 = 0.f, a5 = 0.f, a6 = 0.f, a7 = 0.f;
            const float* wp = wT1 + rg * 8;
            const int k0 = oct * 64;
            #pragma unroll 8
            for (int k = k0; k < k0 + 64; k++) {
                float4 w0 = *(const float4*)(wp + k * 16);
                float4 w1 = *(const float4*)(wp + k * 16 + 4);
                float hv = hs[k * 32 + l];
                a0 += w0.x * hv; a1 += w0.y * hv; a2 += w0.z * hv; a3 += w0.w * hv;
                a4 += w1.x * hv; a5 += w1.y * hv; a6 += w1.z * hv; a7 += w1.w * hv;
            }
            float* gp = gpart + oct * 512 + rg * 8 * 32 + l;
            gp[0] = a0; gp[32] = a1; gp[64] = a2; gp[96] = a3;
            gp[128] = a4; gp[160] = a5; gp[192] = a6; gp[224] = a7;
        }
        __syncthreads();
        if (tid < 128) {
            int jj = tid >> 5, b = tid & 31, J = bid * 4 + jj;
            float gv[4];
            #pragma unroll
            for (int g = 0; g < 4; g++) {
                int r = jj * 4 + g;
                float s = bsum[0][r] + g_xw[(size_t)(g * 512 + J) * 1024 + t * 32 + b];
                #pragma unroll
                for (int o = 0; o < 8; o++) s += gpart[o * 512 + r * 32 + b];
                gv[g] = s;
            }
            float cn = sigf(gv[1]) * c1s[jj][b] + sigf(gv[0]) * tanhf(gv[2]);
            float hn = sigf(gv[3]) * tanhf(cn);
            c1s[jj][b] = cn;
            g_h1T[J * 32 + b] = hn;
        }
        gridbar(tid);

        // ---- stage [h1new ; h2prev(from regs)] ----
        {
            float4* dst4 = (float4*)hs;
            const float4* s1 = (const float4*)g_h1T;
            #pragma unroll
            for (int j = 0; j < 8; j++)  dst4[tid + j * 512] = __ldcg(s1 + tid + j * 512);
            #pragma unroll
            for (int j = 0; j < 8; j++)  dst4[tid + (j + 8) * 512] = ph2[j];
        }
        __syncthreads();

        // ---- layer 2 inner ----
        {
            float a0 = 0.f, a1 = 0.f, a2 = 0.f, a3 = 0.f;
            float a4 = 0.f, a5 = 0.f, a6 = 0.f, a7 = 0.f;
            const float* wp = wT2 + rg * 8;
            const int k0 = oct * 128;
            #pragma unroll 8
            for (int k = k0; k < k0 + 128; k++) {
                float4 w0 = *(const float4*)(wp + k * 16);
                float4 w1 = *(const float4*)(wp + k * 16 + 4);
                float hv = hs[k * 32 + l];
                a0 += w0.x * hv; a1 += w0.y * hv; a2 += w0.z * hv; a3 += w0.w * hv;
                a4 += w1.x * hv; a5 += w1.y * hv; a6 += w1.z * hv; a7 += w1.w * hv;
            }
            __syncthreads();
            float* gp = gpart + oct * 512 + rg * 8 * 32 + l;
            gp[0] = a0; gp[32] = a1; gp[64] = a2; gp[96] = a3;
            gp[128] = a4; gp[160] = a5; gp[192] = a6; gp[224] = a7;
        }
        __syncthreads();
        if (tid < 128) {
            int jj = tid >> 5, b = tid & 31, J = bid * 4 + jj;
            float gv[4];
            #pragma unroll
            for (int g = 0; g < 4; g++) {
                int r = jj * 4 + g;
                float s = bsum[1][r];
                #pragma unroll
                for (int o = 0; o < 8; o++) s += gpart[o * 512 + r * 32 + b];
                gv[g] = s;
            }
            float cn = sigf(gv[1]) * c2s[jj][b] + sigf(gv[0]) * tanhf(gv[2]);
            float hn = sigf(gv[3]) * tanhf(cn);
            c2s[jj][b] = cn;
            g_h2T[J * 32 + b] = hn;
            int row = t * 32 + b;
            g_out[(size_t)row * 512 + J] = hn;
            g_cat2[(size_t)row * 1024 + 512 + J] = hn;
            g_call[(size_t)row * 512 + J] = cn;
        }
        gridbar(tid);
    }

    if (tid < 128) {
        int jj = tid >> 5, b = tid & 31, J = bid * 4 + jj;
        g_c1f[b * 512 + J] = c1s[jj][b];
        g_c2f[b * 512 + J] = c2s[jj][b];
    }
}

// ---------------- generic tiled fp32 GEMM (attention path only) ----------------
__global__ void k_gemm(int M, int N, int K,
                       const float* __restrict__ A, int lda, long long sA,
                       const float* __restrict__ B, int ldbn, int ldbk, long long sB,
                       const float* __restrict__ bias,
                       float* __restrict__ C, int ldc, long long sC, int act) {
    A += (size_t)blockIdx.z * sA;
    B += (size_t)blockIdx.z * sB;
    C += (size_t)blockIdx.z * sC;
    __shared__ float As[16][64];
    __shared__ float Bs[16][64];
    int tid = threadIdx.x;
    int tx = tid & 15, ty = tid >> 4;
    int m0 = blockIdx.y * 64, n0 = blockIdx.x * 64;
    int ar = tid >> 2, ak = (tid & 3) * 4;
    float acc[4][4] = {};

    for (int k0 = 0; k0 < K; k0 += 16) {
        float4 av = make_float4(0.f, 0.f, 0.f, 0.f);
        if (m0 + ar < M) av = *(const float4*)(A + (size_t)(m0 + ar) * lda + k0 + ak);
        As[ak + 0][ar] = av.x; As[ak + 1][ar] = av.y;
        As[ak + 2][ar] = av.z; As[ak + 3][ar] = av.w;
        if (ldbk == 1) {
            float4 bq = make_float4(0.f, 0.f, 0.f, 0.f);
            if (n0 + ar < N) bq = *(const float4*)(B + (size_t)(n0 + ar) * ldbn + k0 + ak);
            Bs[ak + 0][ar] = bq.x; Bs[ak + 1][ar] = bq.y;
            Bs[ak + 2][ar] = bq.z; Bs[ak + 3][ar] = bq.w;
        } else {
            #pragma unroll
            for (int e = tid; e < 1024; e += 256) {
                int n = e & 63, kk = e >> 6;
                float v = 0.f;
                if (n0 + n < N) v = B[(size_t)(n0 + n) * ldbn + (size_t)(k0 + kk) * ldbk];
                Bs[kk][n] = v;
            }
        }
        __syncthreads();
        #pragma unroll
        for (int kk = 0; kk < 16; kk++) {
            float4 a = *(const float4*)(&As[kk][ty * 4]);
            float4 bq = *(const float4*)(&Bs[kk][tx * 4]);
            acc[0][0] += a.x * bq.x; acc[0][1] += a.x * bq.y; acc[0][2] += a.x * bq.z; acc[0][3] += a.x * bq.w;
            acc[1][0] += a.y * bq.x; acc[1][1] += a.y * bq.y; acc[1][2] += a.y * bq.z; acc[1][3] += a.y * bq.w;
            acc[2][0] += a.z * bq.x; acc[2][1] += a.z * bq.y; acc[2][2] += a.z * bq.z; acc[2][3] += a.z * bq.w;
            acc[3][0] += a.w * bq.x; acc[3][1] += a.w * bq.y; acc[3][2] += a.w * bq.z; acc[3][3] += a.w * bq.w;
        }
        __syncthreads();
    }

    #pragma unroll
    for (int i = 0; i < 4; i++) {
        int m = m0 + ty * 4 + i;
        if (m >= M) continue;
        #pragma unroll
        for (int jc = 0; jc < 4; jc++) {
            int n = n0 + tx * 4 + jc;
            if (n >= N) continue;
            float v = acc[i][jc];
            if (bias) v += bias[n];
            if (act == 1) v = tanhf(v);
            C[(size_t)m * ldc + n] = v;
        }
    }
}

// ---------------- generalized bf16 HMMA GEMM: C = A @ B^T (+bias)(tanh)(expsum) ----------------
// Block tile 128x128, 8 warps (warp tile 64x32), K chunks of 64, register prefetch.
#define VPAD 72

__global__ void __launch_bounds__(256) k_hgemm(
    const __nv_bfloat16* __restrict__ A,   // [M, K] bf16 row-major (M = gridDim.y*128)
    const __nv_bfloat16* __restrict__ B,   // [>=nbound, K] bf16 row-major
    const float* __restrict__ bias,        // [nbound] or null
    float* __restrict__ C,                 // [M, ldc] fp32
    int K, int ldc, int nbound, int act,
    float* __restrict__ sumpart, int nbx)  // optional per-(row, n-tile) exp sums
{
    __shared__ __nv_bfloat16 As[128 * VPAD];
    __shared__ __nv_bfloat16 Bs[128 * VPAD];
    __shared__ float srow[128 * 17];       // [localrow][16 contributors + pad]

    const int tid = threadIdx.x;
    const int wid = tid >> 5, lane = tid & 31;
    const int m0 = blockIdx.y * 128, n0 = blockIdx.x * 128;
    const int wr = wid >> 2, wc = wid & 3;

    float acc[4][4][4] = {};
    const uint32_t sA = smem_u32(As), sB = smem_u32(Bs);
    const int nkc = K >> 6;

    uint4 pa[4], pb[4];
    #pragma unroll
    for (int it = 0; it < 4; it++) {
        int idx = tid + it * 256;
        int row = idx >> 3, qv = idx & 7;
        pa[it] = *(const uint4*)(A + (size_t)(m0 + row) * K + qv * 8);
        int n = n0 + row;
        pb[it] = make_uint4(0u, 0u, 0u, 0u);
        if (n < nbound) pb[it] = *(const uint4*)(B + (size_t)n * K + qv * 8);
    }

    for (int kc = 0; kc < nkc; kc++) {
        #pragma unroll
        for (int it = 0; it < 4; it++) {
            int idx = tid + it * 256;
            int row = idx >> 3, qv = idx & 7;
            *(uint4*)(As + row * VPAD + qv * 8) = pa[it];
            *(uint4*)(Bs + row * VPAD + qv * 8) = pb[it];
        }
        __syncthreads();
        if (kc + 1 < nkc) {
            #pragma unroll
            for (int it = 0; it < 4; it++) {
                int idx = tid + it * 256;
                int row = idx >> 3, qv = idx & 7;
                pa[it] = *(const uint4*)(A + (size_t)(m0 + row) * K + (kc + 1) * 64 + qv * 8);
                int n = n0 + row;
                pb[it] = make_uint4(0u, 0u, 0u, 0u);
                if (n < nbound) pb[it] = *(const uint4*)(B + (size_t)n * K + (kc + 1) * 64 + qv * 8);
            }
        }

        #pragma unroll
        for (int ks = 0; ks < 4; ks++) {
            uint32_t af[4][4];
            uint32_t bf[4][2];
            #pragma unroll
            for (int fm = 0; fm < 4; fm++) {
                int row = wr * 64 + fm * 16 + (lane & 15);
                int col = ks * 16 + ((lane >> 4) << 3);
                uint32_t addr = sA + (row * VPAD + col) * 2;
                asm volatile("ldmatrix.sync.aligned.m8n8.x4.shared.b16 {%0,%1,%2,%3}, [%4];"
                    : "=r"(af[fm][0]), "=r"(af[fm][1]), "=r"(af[fm][2]), "=r"(af[fm][3])
                    : "r"(addr));
            }
            #pragma unroll
            for (int fn = 0; fn < 4; fn++) {
                int row = wc * 32 + fn * 8 + (lane & 7);
                int col = ks * 16 + (((lane >> 3) & 1) << 3);
                uint32_t addr = sB + (row * VPAD + col) * 2;
                asm volatile("ldmatrix.sync.aligned.m8n8.x2.shared.b16 {%0,%1}, [%2];"
                    : "=r"(bf[fn][0]), "=r"(bf[fn][1]) : "r"(addr));
            }
            #pragma unroll
            for (int fm = 0; fm < 4; fm++) {
                #pragma unroll
                for (int fn = 0; fn < 4; fn++) {
                    asm volatile(
                        "mma.sync.aligned.m16n8k16.row.col.f32.bf16.bf16.f32 "
                        "{%0,%1,%2,%3}, {%4,%5,%6,%7}, {%8,%9}, {%0,%1,%2,%3};"
                        : "+f"(acc[fm][fn][0]), "+f"(acc[fm][fn][1]),
                          "+f"(acc[fm][fn][2]), "+f"(acc[fm][fn][3])
                        : "r"(af[fm][0]), "r"(af[fm][1]), "r"(af[fm][2]), "r"(af[fm][3]),
                          "r"(bf[fn][0]), "r"(bf[fn][1]));
                }
            }
        }
        __syncthreads();
    }

    int gr = lane >> 2, gc = (lane & 3) * 2;
    int slot = wc * 4 + (lane & 3);
    #pragma unroll
    for (int fm = 0; fm < 4; fm++) {
        int lr0 = wr * 64 + fm * 16 + gr;
        int r0 = m0 + lr0;
        float* crow0 = C + (size_t)r0 * ldc;
        float* crow1 = C + (size_t)(r0 + 8) * ldc;
        float es0 = 0.f, es1 = 0.f;
        #pragma unroll
        for (int fn = 0; fn < 4; fn++) {
            int c = n0 + wc * 32 + fn * 8 + gc;
            if (c + 1 < nbound) {
                float b0 = bias ? bias[c] : 0.f, b1 = bias ? bias[c + 1] : 0.f;
                float v0 = acc[fm][fn][0] + b0, v1 = acc[fm][fn][1] + b1;
                float v2 = acc[fm][fn][2] + b0, v3 = acc[fm][fn][3] + b1;
                if (act == 1) { v0 = tanhf(v0); v1 = tanhf(v1); v2 = tanhf(v2); v3 = tanhf(v3); }
                crow0[c] = v0; crow0[c + 1] = v1;
                crow1[c] = v2; crow1[c + 1] = v3;
                if (sumpart) {
                    es0 += __expf(v0) + __expf(v1);
                    es1 += __expf(v2) + __expf(v3);
                }
            } else if (c < nbound) {
                float b0 = bias ? bias[c] : 0.f;
                float v0 = acc[fm][fn][0] + b0, v2 = acc[fm][fn][2] + b0;
                if (act == 1) { v0 = tanhf(v0); v2 = tanhf(v2); }
                crow0[c] = v0; crow1[c] = v2;
                if (sumpart) { es0 += __expf(v0); es1 += __expf(v2); }
            }
        }
        if (sumpart) {
            srow[lr0 * 17 + slot] = es0;
            srow[(lr0 + 8) * 17 + slot] = es1;
        }
    }
    if (sumpart) {
        __syncthreads();
        if (tid < 128) {
            float s = 0.f;
            #pragma unroll
            for (int i = 0; i < 16; i++) s += srow[tid * 17 + i];
            sumpart[(size_t)(m0 + tid) * nbx + blockIdx.x] = s;
        }
    }
}

// ---------------- row-sum reduce -> 1/sum ----------------
__global__ void k_rowsum() {
    int r = blockIdx.x, tid = threadIdx.x;   // 1024 blocks x 128
    __shared__ float red[128];
    float s = 0.f;
    for (int i = tid; i < NBX_V; i += 128) s += g_sumpart[(size_t)r * NBX_V + i];
    red[tid] = s; __syncthreads();
    for (int o = 64; o > 0; o >>= 1) { if (tid < o) red[tid] += red[tid + o]; __syncthreads(); }
    if (tid == 0) g_rinv[r] = 1.f / red[0];
}

// ---------------- attention softmax over S=400 ----------------
__global__ void k_attnsoftmax() {
    int r = blockIdx.x, tid = threadIdx.x;
    __shared__ float vals[SS];
    __shared__ float red[128];
    float m = -1e30f;
    for (int s = tid; s < SS; s += 128) { float v = g_attn[(size_t)r * SS + s]; vals[s] = v; m = fmaxf(m, v); }
    red[tid] = m; __syncthreads();
    for (int o = 64; o > 0; o >>= 1) { if (tid < o) red[tid] = fmaxf(red[tid], red[tid + o]); __syncthreads(); }
    m = red[0]; __syncthreads();
    float sum = 0.f;
    for (int s = tid; s < SS; s += 128) { float e = __expf(vals[s] - m); vals[s] = e; sum += e; }
    red[tid] = sum; __syncthreads();
    for (int o = 64; o > 0; o >>= 1) { if (tid < o) red[tid] += red[tid + o]; __syncthreads(); }
    float inv = 1.f / red[0];
    for (int s = tid; s < SS; s += 128) g_attn[(size_t)r * SS + s] = vals[s] * inv;
}

// ---------------- p_gen ----------------
__global__ void k_pgen(const float* __restrict__ Wg, const float* __restrict__ bg) {
    int warp = threadIdx.x >> 5, lane = threadIdx.x & 31;
    int r = blockIdx.x * 8 + warp;
    float acc = 0.f;
    for (int j = lane; j < 512; j += 32) {
        acc += g_hatt[(size_t)r * HH + j] * Wg[j]
             + g_out [(size_t)r * HH + j] * Wg[512 + j]
             + g_call[(size_t)r * HH + j] * Wg[1024 + j]
             + g_x   [(size_t)r * HH + j] * Wg[1536 + j];
    }
    for (int o = 16; o > 0; o >>= 1) acc += __shfl_down_sync(0xffffffffu, acc, o);
    if (lane == 0) g_pgen[r] = 1.f / (1.f + expf(-(acc + bg[0])));
}

// ---------------- base scores (no-max softmax; logits are tiny) ----------------
__global__ void k_scores(float* __restrict__ out) {
    int r = blockIdx.y;
    int v0 = (blockIdx.x * blockDim.x + threadIdx.x) * 4;
    float pg = g_pgen[r], inv = g_rinv[r];
    float* orow = out + (size_t)r * EXTV;
    const float* lrow = g_logits + (size_t)r * VV;
    #pragma unroll
    for (int i = 0; i < 4; i++) {
        int v = v0 + i;
        if (v >= EXTV) return;
        float sc;
        if (v < VV) {
            float p = __expf(lrow[v]) * inv;
            sc = __logf(p * pg + 1e-10f);
        } else {
            sc = __logf(1e-10f);
        }
        orow[v] = sc;
    }
}

// ---------------- copy fixup (last-write-wins) ----------------
__global__ void k_fixup(const int* __restrict__ src, float* __restrict__ out) {
    int r = blockIdx.x, b = r & 31;
    __shared__ int sid[SS];
    int s = threadIdx.x;
    if (s < SS) sid[s] = src[s * BBATCH + b];
    __syncthreads();
    if (s >= SS) return;
    int v = sid[s];
    for (int s2 = s + 1; s2 < SS; s2++) if (sid[s2] == v) return;
    float pg = g_pgen[r];
    float a = g_attn[(size_t)r * SS + s];
    float pv = 0.f;
    if (v < VV) pv = __expf(g_logits[(size_t)r * VV + v]) * g_rinv[r];
    out[(size_t)r * EXTV + v] = __logf(pv * pg + a * (1.f - pg) + 1e-10f);
}

// ---------------- final h, c ----------------
__global__ void k_hc(float* __restrict__ out) {
    int i = blockIdx.x * blockDim.x + threadIdx.x;
    float* dst = out + (size_t)TB * EXTV;
    int b = i >> 9, J = i & 511;
    dst[i]          = g_h1T[J * 32 + b];
    dst[16384 + i]  = g_h2T[J * 32 + b];
    dst[32768 + i]  = g_c1f[i];
    dst[49152 + i]  = g_c2f[i];
}

// ---------------- launch ----------------
extern "C" void kernel_launch(void* const* d_in, const int* in_sizes, int n_in,
                              void* d_out, int out_size) {
    const int*   ids = (const int*)d_in[0];
    const int*   src = (const int*)d_in[1];
    const float* h0  = (const float*)d_in[2];
    const float* c0  = (const float*)d_in[3];
    const float* ctx = (const float*)d_in[4];
    int base = (in_sizes[5] <= 4) ? 6 : 5;
    const float* emb = (const float*)d_in[base + 0];
    const float* Wih = (const float*)d_in[base + 1];
    const float* bih = (const float*)d_in[base + 2];
    const float* Whh = (const float*)d_in[base + 3];
    const float* bhh = (const float*)d_in[base + 4];
    const float* Wa  = (const float*)d_in[base + 5];
    const float* ba  = (const float*)d_in[base + 6];
    const float* Wo  = (const float*)d_in[base + 7];
    const float* bo  = (const float*)d_in[base + 8];
    const float* Wv  = (const float*)d_in[base + 9];
    const float* bv  = (const float*)d_in[base + 10];
    const float* Wg  = (const float*)d_in[base + 11];
    const float* bg  = (const float*)d_in[base + 12];
    float* out = (float*)d_out;

    float *px, *pxw, *pout, *pgamma, *pattn, *pcat2, *phatt, *plogits, *psum;
    __nv_bfloat16 *phattb, *pwvb, *pxb, *pwi1b, *pcat2b, *pwob;
    cudaGetSymbolAddress((void**)&px,      g_x);
    cudaGetSymbolAddress((void**)&pxw,     g_xw);
    cudaGetSymbolAddress((void**)&pout,    g_out);
    cudaGetSymbolAddress((void**)&pgamma,  g_gamma);
    cudaGetSymbolAddress((void**)&pattn,   g_attn);
    cudaGetSymbolAddress((void**)&pcat2,   g_cat2);
    cudaGetSymbolAddress((void**)&phatt,   g_hatt);
    cudaGetSymbolAddress((void**)&plogits, g_logits);
    cudaGetSymbolAddress((void**)&psum,    g_sumpart);
    cudaGetSymbolAddress((void**)&phattb,  g_hattb);
    cudaGetSymbolAddress((void**)&pwvb,    g_wvb);
    cudaGetSymbolAddress((void**)&pxb,     g_xb);
    cudaGetSymbolAddress((void**)&pwi1b,   g_wi1b);
    cudaGetSymbolAddress((void**)&pcat2b,  g_cat2b);
    cudaGetSymbolAddress((void**)&pwob,    g_wob);

    const int SMEM_PERSIST = (512 * 16 + 1024 * 16 + 1024 * 32) * 4;  // 229376 B
    cudaFuncSetAttribute(k_persist, cudaFuncAttributeMaxDynamicSharedMemorySize, SMEM_PERSIST);

    // 1. embedding + weight converts + h0 transpose
    k_embed<<<512, 256>>>(ids, emb);
    k_cvt<<<25000, 256>>>(Wv, pwvb, VV * HH / 4);
    k_cvt<<<1024, 256>>>(Wih, pwi1b, 2048 * HH / 4);
    k_cvt<<<512, 256>>>(Wo, pwob, HH * 2 * HH / 4);
    k_tr<<<64, 512>>>(h0);
    k_cvt<<<512, 256>>>(px, pxb, TB * HH / 4);

    // 2. xw hoist via HMMA: g_xw[2048][1024] = W_ih1 @ x^T
    k_hgemm<<<dim3(8, 16), 256>>>(pwi1b, pxb, nullptr, pxw,
                                  HH, TB, TB, 0, nullptr, 0);

    // 3. persistent 2-layer LSTM
    k_persist<<<NBLK, 512, SMEM_PERSIST>>>(Whh, Wih + 2048 * 512, Whh + 2048 * 512,
                                           bih, bhh, c0);

    // 4. gamma = out @ Wa^T + ba (fp32 — precision-critical via attention)
    k_gemm<<<dim3(8, 16, 1), 256>>>(TB, HH, HH, pout, HH, 0,
                                    Wa, HH, 1, 0, ba, pgamma, HH, 0, 0);

    // 5. attn logits per b: gamma @ contexts[b]^T
    k_gemm<<<dim3(7, 1, 32), 256>>>(BBATCH, SS, HH,
                                    pgamma, BBATCH * HH, HH,
                                    ctx, HH, 1, (long long)SS * HH,
                                    nullptr, pattn, BBATCH * SS, SS, 0);

    // 6. softmax over s
    k_attnsoftmax<<<TB, 128>>>();

    // 7. c_t = attn @ contexts[b]
    k_gemm<<<dim3(8, 1, 32), 256>>>(BBATCH, HH, SS,
                                    pattn, BBATCH * SS, SS,
                                    ctx, 1, HH, (long long)SS * HH,
                                    nullptr, pcat2, BBATCH * 2 * HH, 2 * HH, 0);

    // 8. h_att = tanh(cat2 @ Wo^T + bo) via HMMA
    k_cvt<<<1024, 256>>>(pcat2, pcat2b, TB * 2 * HH / 4);
    k_hgemm<<<dim3(4, 8), 256>>>(pcat2b, pwob, bo, phatt,
                                 2 * HH, HH, HH, 1, nullptr, 0);

    // 9. p_gen + h_att -> bf16
    k_pgen<<<128, 256>>>(Wg, bg);
    k_cvt<<<512, 256>>>(phatt, phattb, TB * HH / 4);

    // 10. vocab logits via HMMA with fused exp-sum partials
    k_hgemm<<<dim3(NBX_V, 8), 256>>>(phattb, pwvb, bv, plogits,
                                     HH, VV, VV, 0, psum, NBX_V);
    k_rowsum<<<TB, 128>>>();

    // 11. scores + copy fixup
    k_scores<<<dim3(49, TB, 1), 256>>>(out);
    k_fixup<<<TB, 512>>>(src, out);

    // 12. final h, c
    k_hc<<<64, 256>>>(out);
}

// round 11
// speedup vs baseline: 5.7091x; 1.0450x over previous
#include <cuda_runtime.h>
#include <cuda_bf16.h>
#include <cstdint>
#include <math.h>

#define TT 32
#define BBATCH 32
#define HH 512
#define SS 400
#define VV 50000
#define EXTV 50050
#define TB 1024  // TT*BBATCH
#define NBLK 128
#define NBX_V 391   // vocab n-tiles

// ---------------- scratch (static device arrays; no allocation) ----------------
__device__ float g_x[TB * HH];          // embedded inputs per (t,b)
__device__ float g_xw[2048 * TB];       // precomputed W_ih1 @ x^T : [gate_row][t*32+b]
__device__ float g_out[TB * HH];        // layer-2 h per step
__device__ float g_call[TB * HH];       // layer-2 c per step
__device__ float g_h1T[2 * HH * BBATCH];  // parity-buffered layer-1 h TRANSPOSED [p][J][b]
__device__ float g_h2T[2 * HH * BBATCH];  // parity-buffered layer-2 h TRANSPOSED [p][J][b]
__device__ float g_c1f[BBATCH * HH];
__device__ float g_c2f[BBATCH * HH];
__device__ float g_gamma[TB * HH];
__device__ float g_attn[TB * SS];
__device__ float g_cat2[TB * 2 * HH];   // [c_t | out]
__device__ float g_hatt[TB * HH];
__device__ float g_pgen[TB];
__device__ float g_rinv[TB];
__device__ float g_sumpart[TB * NBX_V];
__device__ float g_logits[(size_t)TB * VV];          // 200 MB
__device__ __nv_bfloat16 g_hattb[TB * HH];
__device__ __nv_bfloat16 g_wvb[(size_t)VV * HH];     // bf16 Wv
__device__ __nv_bfloat16 g_wi1p[2048 * 3 * HH];      // split-packed W_ih1 [hi|hi|lo]
__device__ __nv_bfloat16 g_xp[TB * 3 * HH];          // split-packed x     [hi|lo|hi]
__device__ __nv_bfloat16 g_cat2p[TB * 3 * 2 * HH];   // split-packed cat2  [hi|lo|hi]
__device__ __nv_bfloat16 g_wop[HH * 3 * 2 * HH];     // split-packed Wo    [hi|hi|lo]
__device__ unsigned g_barcnt;
__device__ unsigned g_bargen;

__device__ __forceinline__ uint32_t smem_u32(const void* p) {
    uint32_t a;
    asm("{ .reg .u64 t; cvta.to.shared.u64 t, %1; cvt.u32.u64 %0, t; }" : "=r"(a) : "l"(p));
    return a;
}

// ---------------- embedding ----------------
__global__ void k_embed(const int* __restrict__ ids, const float* __restrict__ emb) {
    int gi = blockIdx.x * blockDim.x + threadIdx.x;
    int r = gi >> 7, e4 = gi & 127;
    int id = ids[r];
    if (id >= VV) id = 1;   // UNK
    float4 v = *(const float4*)(emb + (size_t)id * HH + e4 * 4);
    *(float4*)(g_x + (size_t)r * HH + e4 * 4) = v;
}

// ---------------- fp32 -> bf16 convert ----------------
__global__ void k_cvt(const float* __restrict__ src, __nv_bfloat16* __restrict__ dst, int n4) {
    int i = blockIdx.x * blockDim.x + threadIdx.x;
    if (i >= n4) return;
    float4 v = ((const float4*)src)[i];
    __nv_bfloat162 a = __floats2bfloat162_rn(v.x, v.y);
    __nv_bfloat162 b = __floats2bfloat162_rn(v.z, v.w);
    ((__nv_bfloat162*)dst)[i * 2]     = a;
    ((__nv_bfloat162*)dst)[i * 2 + 1] = b;
}

// ---------------- split-bf16 pack: mode 0 -> [hi|hi|lo], mode 1 -> [hi|lo|hi] ----------------
__global__ void k_pack3(const float* __restrict__ src, __nv_bfloat16* __restrict__ dst,
                        int K, int total, int mode) {
    int i = blockIdx.x * blockDim.x + threadIdx.x;
    if (i >= total) return;
    int r = i / K, k = i - r * K;
    float v = src[i];
    __nv_bfloat16 hi = __float2bfloat16(v);
    __nv_bfloat16 lo = __float2bfloat16(v - __bfloat162float(hi));
    __nv_bfloat16* row = dst + (size_t)r * 3 * K;
    row[k] = hi;
    if (mode == 0) { row[K + k] = hi; row[2 * K + k] = lo; }
    else           { row[K + k] = lo; row[2 * K + k] = hi; }
}

// ---------------- transpose h0: h1 init -> h1T parity 1, h2 init -> h2T parity 0 ----------------
__global__ void k_tr(const float* __restrict__ h0) {
    int i = blockIdx.x * blockDim.x + threadIdx.x;
    if (i >= 32768) return;
    int layer = i >> 14, rem = i & 16383;
    int J = rem >> 5, b = rem & 31;
    float v = h0[layer * 16384 + b * 512 + J];
    if (layer) g_h2T[rem] = v;            // parity 0
    else       g_h1T[16384 + rem] = v;    // parity 1
}

// ---------------- persistent 2-layer LSTM v3: ONE gridbar per step ----------------
__device__ __forceinline__ float sigf(float x) { return 1.0f / (1.0f + __expf(-x)); }
__device__ __forceinline__ float tanhff(float x) { return 1.0f - 2.0f / (__expf(2.0f * x) + 1.0f); }

__device__ __forceinline__ void gridbar(int tid) {
    __syncthreads();
    if (tid == 0) {
        __threadfence();
        unsigned gen = *(volatile unsigned*)&g_bargen;
        unsigned old = atomicAdd(&g_barcnt, 1u);
        if (old == NBLK - 1) {
            atomicExch(&g_barcnt, 0u);
            __threadfence();
            atomicAdd(&g_bargen, 1u);
        } else {
            while (*(volatile unsigned*)&g_bargen == gen) { }
        }
        __threadfence();
    }
    __syncthreads();
}

__global__ void __launch_bounds__(512, 1) k_persist(
    const float* __restrict__ Whh1, const float* __restrict__ Wih2,
    const float* __restrict__ Whh2,
    const float* __restrict__ bih, const float* __restrict__ bhh,
    const float* __restrict__ c0)
{
    extern __shared__ float sm[];
    float* wT1 = sm;                         // [512][16]   32 KB
    float* wT2 = sm + 512 * 16;              // [1024][16]  64 KB
    float* hs  = sm + 512 * 16 + 1024 * 16;  // [1024][32] 128 KB
    float* gpart = hs + 512 * 32;            // alias hs rows 512..639

    __shared__ float c1s[4][32], c2s[4][32], bsum[2][16];

    const int tid = threadIdx.x;
    const int bid = blockIdx.x;
    const int w = tid >> 5, l = tid & 31;
    const int rg = w >> 3;          // 0..1
    const int oct = w & 7;          // 0..7

    #pragma unroll 1
    for (int r = 0; r < 16; r++) {
        int g = r & 3, jj = r >> 2;
        int G = g * 512 + bid * 4 + jj;
        int k = tid;
        wT1[k * 16 + r]         = Whh1[(size_t)G * 512 + k];
        wT2[k * 16 + r]         = Wih2[(size_t)G * 512 + k];
        wT2[(512 + k) * 16 + r] = Whh2[(size_t)G * 512 + k];
    }
    if (tid < 32) {
        int layer = tid >> 4, r = tid & 15;
        int g = r & 3, jj = r >> 2;
        int G = layer * 2048 + g * 512 + bid * 4 + jj;
        bsum[layer][r] = bih[G] + bhh[G];
    }
    if (tid < 128) {
        int jj = tid >> 5, b = tid & 31, J = bid * 4 + jj;
        c1s[jj][b] = c0[b * 512 + J];
        c2s[jj][b] = c0[16384 + b * 512 + J];
    }
    // pre-stage: hs rows 0..511 = h1 init (h1T parity 1)
    {
        float4* dst4 = (float4*)hs;
        const float4* s1 = (const float4*)(g_h1T + 16384);
        #pragma unroll
        for (int j = 0; j < 8; j++) dst4[tid + j * 512] = s1[tid + j * 512];
    }
    __syncthreads();

    for (int t = 0; t < TT; t++) {
        const int pw1 = t & 1;          // h1T write parity this step
        const int ph2r = t & 1;         // h2T read parity (h2(t-1))
        const int ph2w = (t & 1) ^ 1;   // h2T write parity

        // ---- layer 1: from hs rows 0..511 (= h1(t-1)) ----
        {
            float a0 = 0.f, a1 = 0.f, a2 = 0.f, a3 = 0.f;
            float a4 = 0.f, a5 = 0.f, a6 = 0.f, a7 = 0.f;
            const float* wp = wT1 + rg * 8;
            const int k0 = oct * 64;
            #pragma unroll 8
            for (int k = k0; k < k0 + 64; k++) {
                float4 w0 = *(const float4*)(wp + k * 16);
                float4 w1 = *(const float4*)(wp + k * 16 + 4);
                float hv = hs[k * 32 + l];
                a0 += w0.x * hv; a1 += w0.y * hv; a2 += w0.z * hv; a3 += w0.w * hv;
                a4 += w1.x * hv; a5 += w1.y * hv; a6 += w1.z * hv; a7 += w1.w * hv;
            }
            float* gp = gpart + oct * 512 + rg * 8 * 32 + l;
            gp[0] = a0; gp[32] = a1; gp[64] = a2; gp[96] = a3;
            gp[128] = a4; gp[160] = a5; gp[192] = a6; gp[224] = a7;
        }
        __syncthreads();
        if (tid < 128) {
            int jj = tid >> 5, b = tid & 31, J = bid * 4 + jj;
            float gv[4];
            #pragma unroll
            for (int g = 0; g < 4; g++) {
                int r = jj * 4 + g;
                float s = bsum[0][r] + g_xw[(size_t)(g * 512 + J) * 1024 + t * 32 + b];
                #pragma unroll
                for (int o = 0; o < 8; o++) s += gpart[o * 512 + r * 32 + b];
                gv[g] = s;
            }
            float cn = sigf(gv[1]) * c1s[jj][b] + sigf(gv[0]) * tanhff(gv[2]);
            float hn = sigf(gv[3]) * tanhff(cn);
            c1s[jj][b] = cn;
            g_h1T[pw1 * 16384 + J * 32 + b] = hn;
        }
        gridbar(tid);

        // ---- stage: rows 0..511 <- h1T[pw1] (h1(t)); rows 512..1023 <- h2T[ph2r] (h2(t-1)) ----
        {
            float4* dst4 = (float4*)hs;
            const float4* s1 = (const float4*)(g_h1T + pw1 * 16384);
            const float4* s2 = (const float4*)(g_h2T + ph2r * 16384);
            #pragma unroll
            for (int j = 0; j < 8; j++)  dst4[tid + j * 512] = __ldcg(s1 + tid + j * 512);
            #pragma unroll
            for (int j = 0; j < 8; j++)  dst4[tid + (j + 8) * 512] = __ldcg(s2 + tid + j * 512);
        }
        __syncthreads();

        // ---- layer 2: from hs rows 0..1023 ----
        {
            float a0 = 0.f, a1 = 0.f, a2 = 0.f, a3 = 0.f;
            float a4 = 0.f, a5 = 0.f, a6 = 0.f, a7 = 0.f;
            const float* wp = wT2 + rg * 8;
            const int k0 = oct * 128;
            #pragma unroll 8
            for (int k = k0; k < k0 + 128; k++) {
                float4 w0 = *(const float4*)(wp + k * 16);
                float4 w1 = *(const float4*)(wp + k * 16 + 4);
                float hv = hs[k * 32 + l];
                a0 += w0.x * hv; a1 += w0.y * hv; a2 += w0.z * hv; a3 += w0.w * hv;
                a4 += w1.x * hv; a5 += w1.y * hv; a6 += w1.z * hv; a7 += w1.w * hv;
            }
            __syncthreads();   // all hs reads done before gpart alias overwrite
            float* gp = gpart + oct * 512 + rg * 8 * 32 + l;
            gp[0] = a0; gp[32] = a1; gp[64] = a2; gp[96] = a3;
            gp[128] = a4; gp[160] = a5; gp[192] = a6; gp[224] = a7;
        }
        __syncthreads();
        if (tid < 128) {
            int jj = tid >> 5, b = tid & 31, J = bid * 4 + jj;
            float gv[4];
            #pragma unroll
            for (int g = 0; g < 4; g++) {
                int r = jj * 4 + g;
                float s = bsum[1][r];
                #pragma unroll
                for (int o = 0; o < 8; o++) s += gpart[o * 512 + r * 32 + b];
                gv[g] = s;
            }
            float cn = sigf(gv[1]) * c2s[jj][b] + sigf(gv[0]) * tanhff(gv[2]);
            float hn = sigf(gv[3]) * tanhff(cn);
            c2s[jj][b] = cn;
            g_h2T[ph2w * 16384 + J * 32 + b] = hn;
            int row = t * 32 + b;
            g_out[(size_t)row * 512 + J] = hn;
            g_cat2[(size_t)row * 1024 + 512 + J] = hn;
            g_call[(size_t)row * 512 + J] = cn;
        }
        __syncthreads();   // epilogue gpart reads done before next step's gpart writes
        // NO second gridbar: parity buffers make next step's reads race-free
        // (hs rows 0..511 keep h1(t) for next step's layer 1)
    }

    if (tid < 128) {
        int jj = tid >> 5, b = tid & 31, J = bid * 4 + jj;
        g_c1f[b * 512 + J] = c1s[jj][b];
        g_c2f[b * 512 + J] = c2s[jj][b];
    }
}

// ---------------- generic tiled fp32 GEMM (attention path) ----------------
__global__ void k_gemm(int M, int N, int K,
                       const float* __restrict__ A, int lda, long long sA,
                       const float* __restrict__ B, int ldbn, int ldbk, long long sB,
                       const float* __restrict__ bias,
                       float* __restrict__ C, int ldc, long long sC, int act) {
    A += (size_t)blockIdx.z * sA;
    B += (size_t)blockIdx.z * sB;
    C += (size_t)blockIdx.z * sC;
    __shared__ float As[16][64];
    __shared__ float Bs[16][64];
    int tid = threadIdx.x;
    int tx = tid & 15, ty = tid >> 4;
    int m0 = blockIdx.y * 64, n0 = blockIdx.x * 64;
    int ar = tid >> 2, ak = (tid & 3) * 4;
    float acc[4][4] = {};

    for (int k0 = 0; k0 < K; k0 += 16) {
        float4 av = make_float4(0.f, 0.f, 0.f, 0.f);
        if (m0 + ar < M) av = *(const float4*)(A + (size_t)(m0 + ar) * lda + k0 + ak);
        As[ak + 0][ar] = av.x; As[ak + 1][ar] = av.y;
        As[ak + 2][ar] = av.z; As[ak + 3][ar] = av.w;
        if (ldbk == 1) {
            float4 bq = make_float4(0.f, 0.f, 0.f, 0.f);
            if (n0 + ar < N) bq = *(const float4*)(B + (size_t)(n0 + ar) * ldbn + k0 + ak);
            Bs[ak + 0][ar] = bq.x; Bs[ak + 1][ar] = bq.y;
            Bs[ak + 2][ar] = bq.z; Bs[ak + 3][ar] = bq.w;
        } else {
            #pragma unroll
            for (int e = tid; e < 1024; e += 256) {
                int n = e & 63, kk = e >> 6;
                float v = 0.f;
                if (n0 + n < N) v = B[(size_t)(n0 + n) * ldbn + (size_t)(k0 + kk) * ldbk];
                Bs[kk][n] = v;
            }
        }
        __syncthreads();
        #pragma unroll
        for (int kk = 0; kk < 16; kk++) {
            float4 a = *(const float4*)(&As[kk][ty * 4]);
            float4 bq = *(const float4*)(&Bs[kk][tx * 4]);
            acc[0][0] += a.x * bq.x; acc[0][1] += a.x * bq.y; acc[0][2] += a.x * bq.z; acc[0][3] += a.x * bq.w;
            acc[1][0] += a.y * bq.x; acc[1][1] += a.y * bq.y; acc[1][2] += a.y * bq.z; acc[1][3] += a.y * bq.w;
            acc[2][0] += a.z * bq.x; acc[2][1] += a.z * bq.y; acc[2][2] += a.z * bq.z; acc[2][3] += a.z * bq.w;
            acc[3][0] += a.w * bq.x; acc[3][1] += a.w * bq.y; acc[3][2] += a.w * bq.z; acc[3][3] += a.w * bq.w;
        }
        __syncthreads();
    }

    #pragma unroll
    for (int i = 0; i < 4; i++) {
        int m = m0 + ty * 4 + i;
        if (m >= M) continue;
        #pragma unroll
        for (int jc = 0; jc < 4; jc++) {
            int n = n0 + tx * 4 + jc;
            if (n >= N) continue;
            float v = acc[i][jc];
            if (bias) v += bias[n];
            if (act == 1) v = tanhf(v);
            C[(size_t)m * ldc + n] = v;
        }
    }
}

// ---------------- generalized bf16 HMMA GEMM ----------------
#define VPAD 72

__global__ void __launch_bounds__(256) k_hgemm(
    const __nv_bfloat16* __restrict__ A,   // [M, K] bf16 row-major
    const __nv_bfloat16* __restrict__ B,   // [>=nbound, K] bf16 row-major
    const float* __restrict__ bias,
    float* __restrict__ C,                 // [M, ldc] fp32
    int K, int ldc, int nbound, int act,
    float* __restrict__ sumpart, int nbx)
{
    __shared__ __nv_bfloat16 As[128 * VPAD];
    __shared__ __nv_bfloat16 Bs[128 * VPAD];
    __shared__ float srow[128 * 17];

    const int tid = threadIdx.x;
    const int wid = tid >> 5, lane = tid & 31;
    const int m0 = blockIdx.y * 128, n0 = blockIdx.x * 128;
    const int wr = wid >> 2, wc = wid & 3;

    float acc[4][4][4] = {};
    const uint32_t sA = smem_u32(As), sB = smem_u32(Bs);
    const int nkc = K >> 6;

    uint4 pa[4], pb[4];
    #pragma unroll
    for (int it = 0; it < 4; it++) {
        int idx = tid + it * 256;
        int row = idx >> 3, qv = idx & 7;
        pa[it] = *(const uint4*)(A + (size_t)(m0 + row) * K + qv * 8);
        int n = n0 + row;
        pb[it] = make_uint4(0u, 0u, 0u, 0u);
        if (n < nbound) pb[it] = *(const uint4*)(B + (size_t)n * K + qv * 8);
    }

    for (int kc = 0; kc < nkc; kc++) {
        #pragma unroll
        for (int it = 0; it < 4; it++) {
            int idx = tid + it * 256;
            int row = idx >> 3, qv = idx & 7;
            *(uint4*)(As + row * VPAD + qv * 8) = pa[it];
            *(uint4*)(Bs + row * VPAD + qv * 8) = pb[it];
        }
        __syncthreads();
        if (kc + 1 < nkc) {
            #pragma unroll
            for (int it = 0; it < 4; it++) {
                int idx = tid + it * 256;
                int row = idx >> 3, qv = idx & 7;
                pa[it] = *(const uint4*)(A + (size_t)(m0 + row) * K + (kc + 1) * 64 + qv * 8);
                int n = n0 + row;
                pb[it] = make_uint4(0u, 0u, 0u, 0u);
                if (n < nbound) pb[it] = *(const uint4*)(B + (size_t)n * K + (kc + 1) * 64 + qv * 8);
            }
        }

        #pragma unroll
        for (int ks = 0; ks < 4; ks++) {
            uint32_t af[4][4];
            uint32_t bf[4][2];
            #pragma unroll
            for (int fm = 0; fm < 4; fm++) {
                int row = wr * 64 + fm * 16 + (lane & 15);
                int col = ks * 16 + ((lane >> 4) << 3);
                uint32_t addr = sA + (row * VPAD + col) * 2;
                asm volatile("ldmatrix.sync.aligned.m8n8.x4.shared.b16 {%0,%1,%2,%3}, [%4];"
                    : "=r"(af[fm][0]), "=r"(af[fm][1]), "=r"(af[fm][2]), "=r"(af[fm][3])
                    : "r"(addr));
            }
            #pragma unroll
            for (int fn = 0; fn < 4; fn++) {
                int row = wc * 32 + fn * 8 + (lane & 7);
                int col = ks * 16 + (((lane >> 3) & 1) << 3);
                uint32_t addr = sB + (row * VPAD + col) * 2;
                asm volatile("ldmatrix.sync.aligned.m8n8.x2.shared.b16 {%0,%1}, [%2];"
                    : "=r"(bf[fn][0]), "=r"(bf[fn][1]) : "r"(addr));
            }
            #pragma unroll
            for (int fm = 0; fm < 4; fm++) {
                #pragma unroll
                for (int fn = 0; fn < 4; fn++) {
                    asm volatile(
                        "mma.sync.aligned.m16n8k16.row.col.f32.bf16.bf16.f32 "
                        "{%0,%1,%2,%3}, {%4,%5,%6,%7}, {%8,%9}, {%0,%1,%2,%3};"
                        : "+f"(acc[fm][fn][0]), "+f"(acc[fm][fn][1]),
                          "+f"(acc[fm][fn][2]), "+f"(acc[fm][fn][3])
                        : "r"(af[fm][0]), "r"(af[fm][1]), "r"(af[fm][2]), "r"(af[fm][3]),
                          "r"(bf[fn][0]), "r"(bf[fn][1]));
                }
            }
        }
        __syncthreads();
    }

    int gr = lane >> 2, gc = (lane & 3) * 2;
    int slot = wc * 4 + (lane & 3);
    #pragma unroll
    for (int fm = 0; fm < 4; fm++) {
        int lr0 = wr * 64 + fm * 16 + gr;
        int r0 = m0 + lr0;
        float* crow0 = C + (size_t)r0 * ldc;
        float* crow1 = C + (size_t)(r0 + 8) * ldc;
        float es0 = 0.f, es1 = 0.f;
        #pragma unroll
        for (int fn = 0; fn < 4; fn++) {
            int c = n0 + wc * 32 + fn * 8 + gc;
            if (c + 1 < nbound) {
                float b0 = bias ? bias[c] : 0.f, b1 = bias ? bias[c + 1] : 0.f;
                float v0 = acc[fm][fn][0] + b0, v1 = acc[fm][fn][1] + b1;
                float v2 = acc[fm][fn][2] + b0, v3 = acc[fm][fn][3] + b1;
                if (act == 1) { v0 = tanhf(v0); v1 = tanhf(v1); v2 = tanhf(v2); v3 = tanhf(v3); }
                crow0[c] = v0; crow0[c + 1] = v1;
                crow1[c] = v2; crow1[c + 1] = v3;
                if (sumpart) {
                    es0 += __expf(v0) + __expf(v1);
                    es1 += __expf(v2) + __expf(v3);
                }
            } else if (c < nbound) {
                float b0 = bias ? bias[c] : 0.f;
                float v0 = acc[fm][fn][0] + b0, v2 = acc[fm][fn][2] + b0;
                if (act == 1) { v0 = tanhf(v0); v2 = tanhf(v2); }
                crow0[c] = v0; crow1[c] = v2;
                if (sumpart) { es0 += __expf(v0); es1 += __expf(v2); }
            }
        }
        if (sumpart) {
            srow[lr0 * 17 + slot] = es0;
            srow[(lr0 + 8) * 17 + slot] = es1;
        }
    }
    if (sumpart) {
        __syncthreads();
        if (tid < 128) {
            float s = 0.f;
            #pragma unroll
            for (int i = 0; i < 16; i++) s += srow[tid * 17 + i];
            sumpart[(size_t)(m0 + tid) * nbx + blockIdx.x] = s;
        }
    }
}

// ---------------- row-sum reduce -> 1/sum ----------------
__global__ void k_rowsum() {
    int r = blockIdx.x, tid = threadIdx.x;
    __shared__ float red[128];
    float s = 0.f;
    for (int i = tid; i < NBX_V; i += 128) s += g_sumpart[(size_t)r * NBX_V + i];
    red[tid] = s; __syncthreads();
    for (int o = 64; o > 0; o >>= 1) { if (tid < o) red[tid] += red[tid + o]; __syncthreads(); }
    if (tid == 0) g_rinv[r] = 1.f / red[0];
}

// ---------------- attention softmax over S=400 ----------------
__global__ void k_attnsoftmax() {
    int r = blockIdx.x, tid = threadIdx.x;
    __shared__ float vals[SS];
    __shared__ float red[128];
    float m = -1e30f;
    for (int s = tid; s < SS; s += 128) { float v = g_attn[(size_t)r * SS + s]; vals[s] = v; m = fmaxf(m, v); }
    red[tid] = m; __syncthreads();
    for (int o = 64; o > 0; o >>= 1) { if (tid < o) red[tid] = fmaxf(red[tid], red[tid + o]); __syncthreads(); }
    m = red[0]; __syncthreads();
    float sum = 0.f;
    for (int s = tid; s < SS; s += 128) { float e = __expf(vals[s] - m); vals[s] = e; sum += e; }
    red[tid] = sum; __syncthreads();
    for (int o = 64; o > 0; o >>= 1) { if (tid < o) red[tid] += red[tid + o]; __syncthreads(); }
    float inv = 1.f / red[0];
    for (int s = tid; s < SS; s += 128) g_attn[(size_t)r * SS + s] = vals[s] * inv;
}

// ---------------- p_gen ----------------
__global__ void k_pgen(const float* __restrict__ Wg, const float* __restrict__ bg) {
    int warp = threadIdx.x >> 5, lane = threadIdx.x & 31;
    int r = blockIdx.x * 8 + warp;
    float acc = 0.f;
    for (int j = lane; j < 512; j += 32) {
        acc += g_hatt[(size_t)r * HH + j] * Wg[j]
             + g_out [(size_t)r * HH + j] * Wg[512 + j]
             + g_call[(size_t)r * HH + j] * Wg[1024 + j]
             + g_x   [(size_t)r * HH + j] * Wg[1536 + j];
    }
    for (int o = 16; o > 0; o >>= 1) acc += __shfl_down_sync(0xffffffffu, acc, o);
    if (lane == 0) g_pgen[r] = 1.f / (1.f + expf(-(acc + bg[0])));
}

// ---------------- base scores ----------------
__global__ void k_scores(float* __restrict__ out) {
    int r = blockIdx.y;
    int v0 = (blockIdx.x * blockDim.x + threadIdx.x) * 4;
    float pg = g_pgen[r], inv = g_rinv[r];
    float* orow = out + (size_t)r * EXTV;
    const float* lrow = g_logits + (size_t)r * VV;
    #pragma unroll
    for (int i = 0; i < 4; i++) {
        int v = v0 + i;
        if (v >= EXTV) return;
        float sc;
        if (v < VV) {
            float p = __expf(lrow[v]) * inv;
            sc = __logf(p * pg + 1e-10f);
        } else {
            sc = __logf(1e-10f);
        }
        orow[v] = sc;
    }
}

// ---------------- copy fixup (last-write-wins) ----------------
__global__ void k_fixup(const int* __restrict__ src, float* __restrict__ out) {
    int r = blockIdx.x, b = r & 31;
    __shared__ int sid[SS];
    int s = threadIdx.x;
    if (s < SS) sid[s] = src[s * BBATCH + b];
    __syncthreads();
    if (s >= SS) return;
    int v = sid[s];
    for (int s2 = s + 1; s2 < SS; s2++) if (sid[s2] == v) return;
    float pg = g_pgen[r];
    float a = g_attn[(size_t)r * SS + s];
    float pv = 0.f;
    if (v < VV) pv = __expf(g_logits[(size_t)r * VV + v]) * g_rinv[r];
    out[(size_t)r * EXTV + v] = __logf(pv * pg + a * (1.f - pg) + 1e-10f);
}

// ---------------- final h, c ----------------
__global__ void k_hc(float* __restrict__ out) {
    int i = blockIdx.x * blockDim.x + threadIdx.x;
    float* dst = out + (size_t)TB * EXTV;
    int b = i >> 9, J = i & 511;
    dst[i]          = g_h1T[16384 + J * 32 + b];   // final h1: parity 1 (t=31)
    dst[16384 + i]  = g_h2T[J * 32 + b];           // final h2: parity 0
    dst[32768 + i]  = g_c1f[i];
    dst[49152 + i]  = g_c2f[i];
}

// ---------------- launch ----------------
extern "C" void kernel_launch(void* const* d_in, const int* in_sizes, int n_in,
                              void* d_out, int out_size) {
    const int*   ids = (const int*)d_in[0];
    const int*   src = (const int*)d_in[1];
    const float* h0  = (const float*)d_in[2];
    const float* c0  = (const float*)d_in[3];
    const float* ctx = (const float*)d_in[4];
    int base = (in_sizes[5] <= 4) ? 6 : 5;
    const float* emb = (const float*)d_in[base + 0];
    const float* Wih = (const float*)d_in[base + 1];
    const float* bih = (const float*)d_in[base + 2];
    const float* Whh = (const float*)d_in[base + 3];
    const float* bhh = (const float*)d_in[base + 4];
    const float* Wa  = (const float*)d_in[base + 5];
    const float* ba  = (const float*)d_in[base + 6];
    const float* Wo  = (const float*)d_in[base + 7];
    const float* bo  = (const float*)d_in[base + 8];
    const float* Wv  = (const float*)d_in[base + 9];
    const float* bv  = (const float*)d_in[base + 10];
    const float* Wg  = (const float*)d_in[base + 11];
    const float* bg  = (const float*)d_in[base + 12];
    float* out = (float*)d_out;

    float *px, *pxw, *pout, *pgamma, *pattn, *pcat2, *phatt, *plogits, *psum;
    __nv_bfloat16 *phattb, *pwvb, *pwi1p, *pxp, *pcat2p, *pwop;
    cudaGetSymbolAddress((void**)&px,      g_x);
    cudaGetSymbolAddress((void**)&pxw,     g_xw);
    cudaGetSymbolAddress((void**)&pout,    g_out);
    cudaGetSymbolAddress((void**)&pgamma,  g_gamma);
    cudaGetSymbolAddress((void**)&pattn,   g_attn);
    cudaGetSymbolAddress((void**)&pcat2,   g_cat2);
    cudaGetSymbolAddress((void**)&phatt,   g_hatt);
    cudaGetSymbolAddress((void**)&plogits, g_logits);
    cudaGetSymbolAddress((void**)&psum,    g_sumpart);
    cudaGetSymbolAddress((void**)&phattb,  g_hattb);
    cudaGetSymbolAddress((void**)&pwvb,    g_wvb);
    cudaGetSymbolAddress((void**)&pwi1p,   g_wi1p);
    cudaGetSymbolAddress((void**)&pxp,     g_xp);
    cudaGetSymbolAddress((void**)&pcat2p,  g_cat2p);
    cudaGetSymbolAddress((void**)&pwop,    g_wop);

    const int SMEM_PERSIST = (512 * 16 + 1024 * 16 + 1024 * 32) * 4;  // 229376 B
    cudaFuncSetAttribute(k_persist, cudaFuncAttributeMaxDynamicSharedMemorySize, SMEM_PERSIST);

    // 1. embedding + weight converts/packs + h0 transpose
    k_embed<<<512, 256>>>(ids, emb);
    k_cvt<<<25000, 256>>>(Wv, pwvb, VV * HH / 4);
    k_pack3<<<4096, 256>>>(Wih, pwi1p, HH, 2048 * HH, 0);      // [hi|hi|lo]
    k_pack3<<<2048, 256>>>(px, pxp, HH, TB * HH, 1);           // [hi|lo|hi]
    k_pack3<<<2048, 256>>>(Wo, pwop, 2 * HH, HH * 2 * HH, 0);  // [hi|hi|lo]
    k_tr<<<64, 512>>>(h0);

    // 2. xw hoist via split-bf16 HMMA (K=1536, fp32-class accuracy)
    k_hgemm<<<dim3(8, 16), 256>>>(pwi1p, pxp, nullptr, pxw,
                                  3 * HH, TB, TB, 0, nullptr, 0);

    // 3. persistent 2-layer LSTM (1 gridbar/step, parity h buffers)
    k_persist<<<NBLK, 512, SMEM_PERSIST>>>(Whh, Wih + 2048 * 512, Whh + 2048 * 512,
                                           bih, bhh, c0);

    // 4. gamma = out @ Wa^T + ba (fp32)
    k_gemm<<<dim3(8, 16, 1), 256>>>(TB, HH, HH, pout, HH, 0,
                                    Wa, HH, 1, 0, ba, pgamma, HH, 0, 0);

    // 5. attn logits per b: gamma @ contexts[b]^T (fp32)
    k_gemm<<<dim3(7, 1, 32), 256>>>(BBATCH, SS, HH,
                                    pgamma, BBATCH * HH, HH,
                                    ctx, HH, 1, (long long)SS * HH,
                                    nullptr, pattn, BBATCH * SS, SS, 0);

    // 6. softmax over s
    k_attnsoftmax<<<TB, 128>>>();

    // 7. c_t = attn @ contexts[b] (fp32)
    k_gemm<<<dim3(8, 1, 32), 256>>>(BBATCH, HH, SS,
                                    pattn, BBATCH * SS, SS,
                                    ctx, 1, HH, (long long)SS * HH,
                                    nullptr, pcat2, BBATCH * 2 * HH, 2 * HH, 0);

    // 8. h_att = tanh(cat2 @ Wo^T + bo) via split-bf16 HMMA (K=3072)
    k_pack3<<<4096, 256>>>(pcat2, pcat2p, 2 * HH, TB * 2 * HH, 1);  // [hi|lo|hi]
    k_hgemm<<<dim3(4, 8), 256>>>(pcat2p, pwop, bo, phatt,
                                 3 * 2 * HH, HH, HH, 1, nullptr, 0);

    // 9. p_gen + h_att -> bf16
    k_pgen<<<128, 256>>>(Wg, bg);
    k_cvt<<<512, 256>>>(phatt, phattb, TB * HH / 4);

    // 10. vocab logits via bf16 HMMA with fused exp-sum partials
    k_hgemm<<<dim3(NBX_V, 8), 256>>>(phattb, pwvb, bv, plogits,
                                     HH, VV, VV, 0, psum, NBX_V);
    k_rowsum<<<TB, 128>>>();

    // 11. scores + copy fixup
    k_scores<<<dim3(49, TB, 1), 256>>>(out);
    k_fixup<<<TB, 512>>>(src, out);

    // 12. final h, c
    k_hc<<<64, 256>>>(out);
}

// round 12
// speedup vs baseline: 5.7507x; 1.0073x over previous
#include <cuda_runtime.h>
#include <cuda_bf16.h>
#include <cstdint>
#include <math.h>

#define TT 32
#define BBATCH 32
#define HH 512
#define SS 400
#define VV 50000
#define EXTV 50050
#define TB 1024  // TT*BBATCH
#define NBLK 128
#define NBX_V 391   // vocab n-tiles

// ---------------- scratch (static device arrays; no allocation) ----------------
__device__ float g_x[TB * HH];          // embedded inputs per (t,b)
__device__ float g_xw[2048 * TB];       // precomputed W_ih1 @ x^T : [gate_row][t*32+b]
__device__ float g_out[TB * HH];        // layer-2 h per step
__device__ float g_call[TB * HH];       // layer-2 c per step
__device__ float g_h1P[2 * HH * BBATCH];  // parity-buffered layer-1 h PAIR-PACKED [p][J/2][b][2]
__device__ float g_h2P[2 * HH * BBATCH];  // parity-buffered layer-2 h PAIR-PACKED
__device__ float g_c1f[BBATCH * HH];
__device__ float g_c2f[BBATCH * HH];
__device__ float g_gamma[TB * HH];
__device__ float g_attn[TB * SS];
__device__ float g_cat2[TB * 2 * HH];   // [c_t | out]
__device__ float g_hatt[TB * HH];
__device__ float g_pgen[TB];
__device__ float g_rinv[TB];
__device__ float g_sumpart[TB * NBX_V];
__device__ float g_logits[(size_t)TB * VV];          // 200 MB
__device__ __nv_bfloat16 g_hattb[TB * HH];
__device__ __nv_bfloat16 g_wvb[(size_t)VV * HH];     // bf16 Wv
__device__ __nv_bfloat16 g_wi1p[2048 * 3 * HH];      // split-packed W_ih1 [hi|hi|lo]
__device__ __nv_bfloat16 g_xp[TB * 3 * HH];          // split-packed x     [hi|lo|hi]
__device__ __nv_bfloat16 g_cat2p[TB * 3 * 2 * HH];   // split-packed cat2  [hi|lo|hi]
__device__ __nv_bfloat16 g_wop[HH * 3 * 2 * HH];     // split-packed Wo    [hi|hi|lo]
__device__ unsigned g_barcnt;
__device__ unsigned g_bargen;

__device__ __forceinline__ uint32_t smem_u32(const void* p) {
    uint32_t a;
    asm("{ .reg .u64 t; cvta.to.shared.u64 t, %1; cvt.u32.u64 %0, t; }" : "=r"(a) : "l"(p));
    return a;
}

#define FMA2(acc, w, h) \
    asm("fma.rn.f32x2 %0, %1, %2, %0;" : "+l"(acc) : "l"(w), "l"(h))

__device__ __forceinline__ float hadd2(unsigned long long a) {
    return __uint_as_float((unsigned)a) + __uint_as_float((unsigned)(a >> 32));
}

// ---------------- embedding ----------------
__global__ void k_embed(const int* __restrict__ ids, const float* __restrict__ emb) {
    int gi = blockIdx.x * blockDim.x + threadIdx.x;
    int r = gi >> 7, e4 = gi & 127;
    int id = ids[r];
    if (id >= VV) id = 1;   // UNK
    float4 v = *(const float4*)(emb + (size_t)id * HH + e4 * 4);
    *(float4*)(g_x + (size_t)r * HH + e4 * 4) = v;
}

// ---------------- fp32 -> bf16 convert ----------------
__global__ void k_cvt(const float* __restrict__ src, __nv_bfloat16* __restrict__ dst, int n4) {
    int i = blockIdx.x * blockDim.x + threadIdx.x;
    if (i >= n4) return;
    float4 v = ((const float4*)src)[i];
    __nv_bfloat162 a = __floats2bfloat162_rn(v.x, v.y);
    __nv_bfloat162 b = __floats2bfloat162_rn(v.z, v.w);
    ((__nv_bfloat162*)dst)[i * 2]     = a;
    ((__nv_bfloat162*)dst)[i * 2 + 1] = b;
}

// ---------------- split-bf16 pack: mode 0 -> [hi|hi|lo], mode 1 -> [hi|lo|hi] ----------------
__global__ void k_pack3(const float* __restrict__ src, __nv_bfloat16* __restrict__ dst,
                        int K, int total, int mode) {
    int i = blockIdx.x * blockDim.x + threadIdx.x;
    if (i >= total) return;
    int r = i / K, k = i - r * K;
    float v = src[i];
    __nv_bfloat16 hi = __float2bfloat16(v);
    __nv_bfloat16 lo = __float2bfloat16(v - __bfloat162float(hi));
    __nv_bfloat16* row = dst + (size_t)r * 3 * K;
    row[k] = hi;
    if (mode == 0) { row[K + k] = hi; row[2 * K + k] = lo; }
    else           { row[K + k] = lo; row[2 * K + k] = hi; }
}

// ---------------- transpose h0 into pair-packed parity buffers ----------------
__global__ void k_tr(const float* __restrict__ h0) {
    int i = blockIdx.x * blockDim.x + threadIdx.x;
    if (i >= 32768) return;
    int layer = i >> 14, rem = i & 16383;
    int J = rem >> 5, b = rem & 31;
    float v = h0[layer * 16384 + b * 512 + J];
    int idx = (J >> 1) * 64 + b * 2 + (J & 1);
    if (layer) g_h2P[idx] = v;            // parity 0
    else       g_h1P[16384 + idx] = v;    // parity 1
}

// ---------------- persistent 2-layer LSTM v4: f32x2 packed FMA ----------------
__device__ __forceinline__ float sigf(float x) { return 1.0f / (1.0f + __expf(-x)); }
__device__ __forceinline__ float tanhff(float x) { return 1.0f - 2.0f / (__expf(2.0f * x) + 1.0f); }

__device__ __forceinline__ void gridbar(int tid) {
    __syncthreads();
    if (tid == 0) {
        __threadfence();
        unsigned gen = *(volatile unsigned*)&g_bargen;
        unsigned old = atomicAdd(&g_barcnt, 1u);
        if (old == NBLK - 1) {
            atomicExch(&g_barcnt, 0u);
            __threadfence();
            atomicAdd(&g_bargen, 1u);
        } else {
            while (*(volatile unsigned*)&g_bargen == gen) { }
        }
        __threadfence();
    }
    __syncthreads();
}

// smem weight layout: [kp][16 rows][2] floats. h layout: [kp][32 b][2] floats.
__global__ void __launch_bounds__(512, 1) k_persist(
    const float* __restrict__ Whh1, const float* __restrict__ Wih2,
    const float* __restrict__ Whh2,
    const float* __restrict__ bih, const float* __restrict__ bhh,
    const float* __restrict__ c0)
{
    extern __shared__ float sm[];
    float* wT1 = sm;                         // [256 kp][16][2]   32 KB
    float* wT2 = sm + 512 * 16;              // [512 kp][16][2]   64 KB
    float* hs  = sm + 512 * 16 + 1024 * 16;  // [512 kp][32][2]  128 KB
    float* gpart = hs + 16384;               // alias kp 256..319 (layer-2-only region)

    __shared__ float c1s[4][32], c2s[4][32], bsum[2][16];

    const int tid = threadIdx.x;
    const int bid = blockIdx.x;
    const int w = tid >> 5, l = tid & 31;
    const int rg = w >> 3;          // 0..1
    const int oct = w & 7;          // 0..7

    // ---- one-time: weight slices into smem (pair-interleaved) ----
    #pragma unroll 1
    for (int r = 0; r < 16; r++) {
        int g = r & 3, jj = r >> 2;
        int G = g * 512 + bid * 4 + jj;
        int k = tid;  // 0..511
        int kp = k >> 1, kq = k & 1;
        wT1[kp * 32 + r * 2 + kq]          = Whh1[(size_t)G * 512 + k];
        wT2[kp * 32 + r * 2 + kq]          = Wih2[(size_t)G * 512 + k];
        wT2[(256 + kp) * 32 + r * 2 + kq]  = Whh2[(size_t)G * 512 + k];
    }
    if (tid < 32) {
        int layer = tid >> 4, r = tid & 15;
        int g = r & 3, jj = r >> 2;
        int G = layer * 2048 + g * 512 + bid * 4 + jj;
        bsum[layer][r] = bih[G] + bhh[G];
    }
    if (tid < 128) {
        int jj = tid >> 5, b = tid & 31, J = bid * 4 + jj;
        c1s[jj][b] = c0[b * 512 + J];
        c2s[jj][b] = c0[16384 + b * 512 + J];
    }
    // pre-stage: hs kp 0..255 = h1 init (parity 1), straight copy (pair layout matches)
    {
        float4* dst4 = (float4*)hs;
        const float4* s1 = (const float4*)(g_h1P + 16384);
        #pragma unroll
        for (int j = 0; j < 8; j++) dst4[tid + j * 512] = s1[tid + j * 512];
    }
    __syncthreads();

    for (int t = 0; t < TT; t++) {
        const int pw1 = t & 1;
        const int ph2r = t & 1;
        const int ph2w = (t & 1) ^ 1;

        // ---- layer 1: kp in [oct*32, oct*32+32) ----
        {
            unsigned long long a0 = 0, a1 = 0, a2 = 0, a3 = 0, a4 = 0, a5 = 0, a6 = 0, a7 = 0;
            const float* wp = wT1 + rg * 16;
            const int kp0 = oct * 32;
            #pragma unroll 8
            for (int kp = kp0; kp < kp0 + 32; kp++) {
                const float* wk = wp + kp * 32;
                ulonglong2 w01 = *(const ulonglong2*)(wk);
                ulonglong2 w23 = *(const ulonglong2*)(wk + 4);
                ulonglong2 w45 = *(const ulonglong2*)(wk + 8);
                ulonglong2 w67 = *(const ulonglong2*)(wk + 12);
                unsigned long long hp = *(const unsigned long long*)(hs + kp * 64 + l * 2);
                FMA2(a0, w01.x, hp); FMA2(a1, w01.y, hp);
                FMA2(a2, w23.x, hp); FMA2(a3, w23.y, hp);
                FMA2(a4, w45.x, hp); FMA2(a5, w45.y, hp);
                FMA2(a6, w67.x, hp); FMA2(a7, w67.y, hp);
            }
            float* gp = gpart + oct * 512 + rg * 8 * 32 + l;
            gp[0] = hadd2(a0);   gp[32] = hadd2(a1);  gp[64] = hadd2(a2);  gp[96] = hadd2(a3);
            gp[128] = hadd2(a4); gp[160] = hadd2(a5); gp[192] = hadd2(a6); gp[224] = hadd2(a7);
        }
        __syncthreads();
        if (tid < 128) {
            int jj = tid >> 5, b = tid & 31, J = bid * 4 + jj;
            float gv[4];
            #pragma unroll
            for (int g = 0; g < 4; g++) {
                int r = jj * 4 + g;
                float s = bsum[0][r] + g_xw[(size_t)(g * 512 + J) * 1024 + t * 32 + b];
                #pragma unroll
                for (int o = 0; o < 8; o++) s += gpart[o * 512 + r * 32 + b];
                gv[g] = s;
            }
            float cn = sigf(gv[1]) * c1s[jj][b] + sigf(gv[0]) * tanhff(gv[2]);
            float hn = sigf(gv[3]) * tanhff(cn);
            c1s[jj][b] = cn;
            g_h1P[pw1 * 16384 + (J >> 1) * 64 + b * 2 + (J & 1)] = hn;
        }
        gridbar(tid);

        // ---- stage: kp 0..255 <- h1P[pw1]; kp 256..511 <- h2P[ph2r] ----
        {
            float4* dst4 = (float4*)hs;
            const float4* s1 = (const float4*)(g_h1P + pw1 * 16384);
            const float4* s2 = (const float4*)(g_h2P + ph2r * 16384);
            #pragma unroll
            for (int j = 0; j < 8; j++)  dst4[tid + j * 512] = __ldcg(s1 + tid + j * 512);
            #pragma unroll
            for (int j = 0; j < 8; j++)  dst4[tid + (j + 8) * 512] = __ldcg(s2 + tid + j * 512);
        }
        __syncthreads();

        // ---- layer 2: kp in [oct*64, oct*64+64) over 512 pairs ----
        {
            unsigned long long a0 = 0, a1 = 0, a2 = 0, a3 = 0, a4 = 0, a5 = 0, a6 = 0, a7 = 0;
            const float* wp = wT2 + rg * 16;
            const int kp0 = oct * 64;
            #pragma unroll 8
            for (int kp = kp0; kp < kp0 + 64; kp++) {
                const float* wk = wp + kp * 32;
                ulonglong2 w01 = *(const ulonglong2*)(wk);
                ulonglong2 w23 = *(const ulonglong2*)(wk + 4);
                ulonglong2 w45 = *(const ulonglong2*)(wk + 8);
                ulonglong2 w67 = *(const ulonglong2*)(wk + 12);
                unsigned long long hp = *(const unsigned long long*)(hs + kp * 64 + l * 2);
                FMA2(a0, w01.x, hp); FMA2(a1, w01.y, hp);
                FMA2(a2, w23.x, hp); FMA2(a3, w23.y, hp);
                FMA2(a4, w45.x, hp); FMA2(a5, w45.y, hp);
                FMA2(a6, w67.x, hp); FMA2(a7, w67.y, hp);
            }
            __syncthreads();   // all hs reads done before gpart alias overwrite
            float* gp = gpart + oct * 512 + rg * 8 * 32 + l;
            gp[0] = hadd2(a0);   gp[32] = hadd2(a1);  gp[64] = hadd2(a2);  gp[96] = hadd2(a3);
            gp[128] = hadd2(a4); gp[160] = hadd2(a5); gp[192] = hadd2(a6); gp[224] = hadd2(a7);
        }
        __syncthreads();
        if (tid < 128) {
            int jj = tid >> 5, b = tid & 31, J = bid * 4 + jj;
            float gv[4];
            #pragma unroll
            for (int g = 0; g < 4; g++) {
                int r = jj * 4 + g;
                float s = bsum[1][r];
                #pragma unroll
                for (int o = 0; o < 8; o++) s += gpart[o * 512 + r * 32 + b];
                gv[g] = s;
            }
            float cn = sigf(gv[1]) * c2s[jj][b] + sigf(gv[0]) * tanhff(gv[2]);
            float hn = sigf(gv[3]) * tanhff(cn);
            c2s[jj][b] = cn;
            g_h2P[ph2w * 16384 + (J >> 1) * 64 + b * 2 + (J & 1)] = hn;
            int row = t * 32 + b;
            g_out[(size_t)row * 512 + J] = hn;
            g_cat2[(size_t)row * 1024 + 512 + J] = hn;
            g_call[(size_t)row * 512 + J] = cn;
        }
        __syncthreads();
        // hs kp 0..255 keep h1(t) for next step's layer 1
    }

    if (tid < 128) {
        int jj = tid >> 5, b = tid & 31, J = bid * 4 + jj;
        g_c1f[b * 512 + J] = c1s[jj][b];
        g_c2f[b * 512 + J] = c2s[jj][b];
    }
}

// ---------------- generic tiled fp32 GEMM (attention path) ----------------
__global__ void k_gemm(int M, int N, int K,
                       const float* __restrict__ A, int lda, long long sA,
                       const float* __restrict__ B, int ldbn, int ldbk, long long sB,
                       const float* __restrict__ bias,
                       float* __restrict__ C, int ldc, long long sC, int act) {
    A += (size_t)blockIdx.z * sA;
    B += (size_t)blockIdx.z * sB;
    C += (size_t)blockIdx.z * sC;
    __shared__ float As[16][64];
    __shared__ float Bs[16][64];
    int tid = threadIdx.x;
    int tx = tid & 15, ty = tid >> 4;
    int m0 = blockIdx.y * 64, n0 = blockIdx.x * 64;
    int ar = tid >> 2, ak = (tid & 3) * 4;
    float acc[4][4] = {};

    for (int k0 = 0; k0 < K; k0 += 16) {
        float4 av = make_float4(0.f, 0.f, 0.f, 0.f);
        if (m0 + ar < M) av = *(const float4*)(A + (size_t)(m0 + ar) * lda + k0 + ak);
        As[ak + 0][ar] = av.x; As[ak + 1][ar] = av.y;
        As[ak + 2][ar] = av.z; As[ak + 3][ar] = av.w;
        if (ldbk == 1) {
            float4 bq = make_float4(0.f, 0.f, 0.f, 0.f);
            if (n0 + ar < N) bq = *(const float4*)(B + (size_t)(n0 + ar) * ldbn + k0 + ak);
            Bs[ak + 0][ar] = bq.x; Bs[ak + 1][ar] = bq.y;
            Bs[ak + 2][ar] = bq.z; Bs[ak + 3][ar] = bq.w;
        } else {
            #pragma unroll
            for (int e = tid; e < 1024; e += 256) {
                int n = e & 63, kk = e >> 6;
                float v = 0.f;
                if (n0 + n < N) v = B[(size_t)(n0 + n) * ldbn + (size_t)(k0 + kk) * ldbk];
                Bs[kk][n] = v;
            }
        }
        __syncthreads();
        #pragma unroll
        for (int kk = 0; kk < 16; kk++) {
            float4 a = *(const float4*)(&As[kk][ty * 4]);
            float4 bq = *(const float4*)(&Bs[kk][tx * 4]);
            acc[0][0] += a.x * bq.x; acc[0][1] += a.x * bq.y; acc[0][2] += a.x * bq.z; acc[0][3] += a.x * bq.w;
            acc[1][0] += a.y * bq.x; acc[1][1] += a.y * bq.y; acc[1][2] += a.y * bq.z; acc[1][3] += a.y * bq.w;
            acc[2][0] += a.z * bq.x; acc[2][1] += a.z * bq.y; acc[2][2] += a.z * bq.z; acc[2][3] += a.z * bq.w;
            acc[3][0] += a.w * bq.x; acc[3][1] += a.w * bq.y; acc[3][2] += a.w * bq.z; acc[3][3] += a.w * bq.w;
        }
        __syncthreads();
    }

    #pragma unroll
    for (int i = 0; i < 4; i++) {
        int m = m0 + ty * 4 + i;
        if (m >= M) continue;
        #pragma unroll
        for (int jc = 0; jc < 4; jc++) {
            int n = n0 + tx * 4 + jc;
            if (n >= N) continue;
            float v = acc[i][jc];
            if (bias) v += bias[n];
            if (act == 1) v = tanhf(v);
            C[(size_t)m * ldc + n] = v;
        }
    }
}

// ---------------- generalized bf16 HMMA GEMM ----------------
#define VPAD 72

__global__ void __launch_bounds__(256) k_hgemm(
    const __nv_bfloat16* __restrict__ A,   // [M, K] bf16 row-major
    const __nv_bfloat16* __restrict__ B,   // [>=nbound, K] bf16 row-major
    const float* __restrict__ bias,
    float* __restrict__ C,                 // [M, ldc] fp32
    int K, int ldc, int nbound, int act,
    float* __restrict__ sumpart, int nbx,
    __nv_bfloat16* __restrict__ bf16out)   // optional bf16 copy of C
{
    __shared__ __nv_bfloat16 As[128 * VPAD];
    __shared__ __nv_bfloat16 Bs[128 * VPAD];
    __shared__ float srow[128 * 17];

    const int tid = threadIdx.x;
    const int wid = tid >> 5, lane = tid & 31;
    const int m0 = blockIdx.y * 128, n0 = blockIdx.x * 128;
    const int wr = wid >> 2, wc = wid & 3;

    float acc[4][4][4] = {};
    const uint32_t sA = smem_u32(As), sB = smem_u32(Bs);
    const int nkc = K >> 6;

    uint4 pa[4], pb[4];
    #pragma unroll
    for (int it = 0; it < 4; it++) {
        int idx = tid + it * 256;
        int row = idx >> 3, qv = idx & 7;
        pa[it] = *(const uint4*)(A + (size_t)(m0 + row) * K + qv * 8);
        int n = n0 + row;
        pb[it] = make_uint4(0u, 0u, 0u, 0u);
        if (n < nbound) pb[it] = *(const uint4*)(B + (size_t)n * K + qv * 8);
    }

    for (int kc = 0; kc < nkc; kc++) {
        #pragma unroll
        for (int it = 0; it < 4; it++) {
            int idx = tid + it * 256;
            int row = idx >> 3, qv = idx & 7;
            *(uint4*)(As + row * VPAD + qv * 8) = pa[it];
            *(uint4*)(Bs + row * VPAD + qv * 8) = pb[it];
        }
        __syncthreads();
        if (kc + 1 < nkc) {
            #pragma unroll
            for (int it = 0; it < 4; it++) {
                int idx = tid + it * 256;
                int row = idx >> 3, qv = idx & 7;
                pa[it] = *(const uint4*)(A + (size_t)(m0 + row) * K + (kc + 1) * 64 + qv * 8);
                int n = n0 + row;
                pb[it] = make_uint4(0u, 0u, 0u, 0u);
                if (n < nbound) pb[it] = *(const uint4*)(B + (size_t)n * K + (kc + 1) * 64 + qv * 8);
            }
        }

        #pragma unroll
        for (int ks = 0; ks < 4; ks++) {
            uint32_t af[4][4];
            uint32_t bf[4][2];
            #pragma unroll
            for (int fm = 0; fm < 4; fm++) {
                int row = wr * 64 + fm * 16 + (lane & 15);
                int col = ks * 16 + ((lane >> 4) << 3);
                uint32_t addr = sA + (row * VPAD + col) * 2;
                asm volatile("ldmatrix.sync.aligned.m8n8.x4.shared.b16 {%0,%1,%2,%3}, [%4];"
                    : "=r"(af[fm][0]), "=r"(af[fm][1]), "=r"(af[fm][2]), "=r"(af[fm][3])
                    : "r"(addr));
            }
            #pragma unroll
            for (int fn = 0; fn < 4; fn++) {
                int row = wc * 32 + fn * 8 + (lane & 7);
                int col = ks * 16 + (((lane >> 3) & 1) << 3);
                uint32_t addr = sB + (row * VPAD + col) * 2;
                asm volatile("ldmatrix.sync.aligned.m8n8.x2.shared.b16 {%0,%1}, [%2];"
                    : "=r"(bf[fn][0]), "=r"(bf[fn][1]) : "r"(addr));
            }
            #pragma unroll
            for (int fm = 0; fm < 4; fm++) {
                #pragma unroll
                for (int fn = 0; fn < 4; fn++) {
                    asm volatile(
                        "mma.sync.aligned.m16n8k16.row.col.f32.bf16.bf16.f32 "
                        "{%0,%1,%2,%3}, {%4,%5,%6,%7}, {%8,%9}, {%0,%1,%2,%3};"
                        : "+f"(acc[fm][fn][0]), "+f"(acc[fm][fn][1]),
                          "+f"(acc[fm][fn][2]), "+f"(acc[fm][fn][3])
                        : "r"(af[fm][0]), "r"(af[fm][1]), "r"(af[fm][2]), "r"(af[fm][3]),
                          "r"(bf[fn][0]), "r"(bf[fn][1]));
                }
            }
        }
        __syncthreads();
    }

    int gr = lane >> 2, gc = (lane & 3) * 2;
    int slot = wc * 4 + (lane & 3);
    #pragma unroll
    for (int fm = 0; fm < 4; fm++) {
        int lr0 = wr * 64 + fm * 16 + gr;
        int r0 = m0 + lr0;
        float* crow0 = C + (size_t)r0 * ldc;
        float* crow1 = C + (size_t)(r0 + 8) * ldc;
        float es0 = 0.f, es1 = 0.f;
        #pragma unroll
        for (int fn = 0; fn < 4; fn++) {
            int c = n0 + wc * 32 + fn * 8 + gc;
            if (c + 1 < nbound) {
                float b0 = bias ? bias[c] : 0.f, b1 = bias ? bias[c + 1] : 0.f;
                float v0 = acc[fm][fn][0] + b0, v1 = acc[fm][fn][1] + b1;
                float v2 = acc[fm][fn][2] + b0, v3 = acc[fm][fn][3] + b1;
                if (act == 1) { v0 = tanhf(v0); v1 = tanhf(v1); v2 = tanhf(v2); v3 = tanhf(v3); }
                crow0[c] = v0; crow0[c + 1] = v1;
                crow1[c] = v2; crow1[c + 1] = v3;
                if (bf16out) {
                    bf16out[(size_t)r0 * ldc + c]           = __float2bfloat16(v0);
                    bf16out[(size_t)r0 * ldc + c + 1]       = __float2bfloat16(v1);
                    bf16out[(size_t)(r0 + 8) * ldc + c]     = __float2bfloat16(v2);
                    bf16out[(size_t)(r0 + 8) * ldc + c + 1] = __float2bfloat16(v3);
                }
                if (sumpart) {
                    es0 += __expf(v0) + __expf(v1);
                    es1 += __expf(v2) + __expf(v3);
                }
            } else if (c < nbound) {
                float b0 = bias ? bias[c] : 0.f;
                float v0 = acc[fm][fn][0] + b0, v2 = acc[fm][fn][2] + b0;
                if (act == 1) { v0 = tanhf(v0); v2 = tanhf(v2); }
                crow0[c] = v0; crow1[c] = v2;
                if (bf16out) {
                    bf16out[(size_t)r0 * ldc + c]       = __float2bfloat16(v0);
                    bf16out[(size_t)(r0 + 8) * ldc + c] = __float2bfloat16(v2);
                }
                if (sumpart) { es0 += __expf(v0); es1 += __expf(v2); }
            }
        }
        if (sumpart) {
            srow[lr0 * 17 + slot] = es0;
            srow[(lr0 + 8) * 17 + slot] = es1;
        }
    }
    if (sumpart) {
        __syncthreads();
        if (tid < 128) {
            float s = 0.f;
            #pragma unroll
            for (int i = 0; i < 16; i++) s += srow[tid * 17 + i];
            sumpart[(size_t)(m0 + tid) * nbx + blockIdx.x] = s;
        }
    }
}

// ---------------- row-sum reduce -> 1/sum ----------------
__global__ void k_rowsum() {
    int r = blockIdx.x, tid = threadIdx.x;
    __shared__ float red[128];
    float s = 0.f;
    for (int i = tid; i < NBX_V; i += 128) s += g_sumpart[(size_t)r * NBX_V + i];
    red[tid] = s; __syncthreads();
    for (int o = 64; o > 0; o >>= 1) { if (tid < o) red[tid] += red[tid + o]; __syncthreads(); }
    if (tid == 0) g_rinv[r] = 1.f / red[0];
}

// ---------------- attention softmax over S=400 ----------------
__global__ void k_attnsoftmax() {
    int r = blockIdx.x, tid = threadIdx.x;
    __shared__ float vals[SS];
    __shared__ float red[128];
    float m = -1e30f;
    for (int s = tid; s < SS; s += 128) { float v = g_attn[(size_t)r * SS + s]; vals[s] = v; m = fmaxf(m, v); }
    red[tid] = m; __syncthreads();
    for (int o = 64; o > 0; o >>= 1) { if (tid < o) red[tid] = fmaxf(red[tid], red[tid + o]); __syncthreads(); }
    m = red[0]; __syncthreads();
    float sum = 0.f;
    for (int s = tid; s < SS; s += 128) { float e = __expf(vals[s] - m); vals[s] = e; sum += e; }
    red[tid] = sum; __syncthreads();
    for (int o = 64; o > 0; o >>= 1) { if (tid < o) red[tid] += red[tid + o]; __syncthreads(); }
    float inv = 1.f / red[0];
    for (int s = tid; s < SS; s += 128) g_attn[(size_t)r * SS + s] = vals[s] * inv;
}

// ---------------- p_gen ----------------
__global__ void k_pgen(const float* __restrict__ Wg, const float* __restrict__ bg) {
    int warp = threadIdx.x >> 5, lane = threadIdx.x & 31;
    int r = blockIdx.x * 8 + warp;
    float acc = 0.f;
    for (int j = lane; j < 512; j += 32) {
        acc += g_hatt[(size_t)r * HH + j] * Wg[j]
             + g_out [(size_t)r * HH + j] * Wg[512 + j]
             + g_call[(size_t)r * HH + j] * Wg[1024 + j]
             + g_x   [(size_t)r * HH + j] * Wg[1536 + j];
    }
    for (int o = 16; o > 0; o >>= 1) acc += __shfl_down_sync(0xffffffffu, acc, o);
    if (lane == 0) g_pgen[r] = 1.f / (1.f + expf(-(acc + bg[0])));
}

// ---------------- base scores ----------------
__global__ void k_scores(float* __restrict__ out) {
    int r = blockIdx.y;
    int v0 = (blockIdx.x * blockDim.x + threadIdx.x) * 4;
    float pg = g_pgen[r], inv = g_rinv[r];
    float* orow = out + (size_t)r * EXTV;
    const float* lrow = g_logits + (size_t)r * VV;
    #pragma unroll
    for (int i = 0; i < 4; i++) {
        int v = v0 + i;
        if (v >= EXTV) return;
        float sc;
        if (v < VV) {
            float p = __expf(lrow[v]) * inv;
            sc = __logf(p * pg + 1e-10f);
        } else {
            sc = __logf(1e-10f);
        }
        orow[v] = sc;
    }
}

// ---------------- copy fixup (last-write-wins) ----------------
__global__ void k_fixup(const int* __restrict__ src, float* __restrict__ out) {
    int r = blockIdx.x, b = r & 31;
    __shared__ int sid[SS];
    int s = threadIdx.x;
    if (s < SS) sid[s] = src[s * BBATCH + b];
    __syncthreads();
    if (s >= SS) return;
    int v = sid[s];
    for (int s2 = s + 1; s2 < SS; s2++) if (sid[s2] == v) return;
    float pg = g_pgen[r];
    float a = g_attn[(size_t)r * SS + s];
    float pv = 0.f;
    if (v < VV) pv = __expf(g_logits[(size_t)r * VV + v]) * g_rinv[r];
    out[(size_t)r * EXTV + v] = __logf(pv * pg + a * (1.f - pg) + 1e-10f);
}

// ---------------- final h, c ----------------
__global__ void k_hc(float* __restrict__ out) {
    int i = blockIdx.x * blockDim.x + threadIdx.x;
    float* dst = out + (size_t)TB * EXTV;
    int b = i >> 9, J = i & 511;
    int idx = (J >> 1) * 64 + b * 2 + (J & 1);
    dst[i]          = g_h1P[16384 + idx];   // final h1: parity 1 (t=31)
    dst[16384 + i]  = g_h2P[idx];           // final h2: parity 0
    dst[32768 + i]  = g_c1f[i];
    dst[49152 + i]  = g_c2f[i];
}

// ---------------- launch ----------------
extern "C" void kernel_launch(void* const* d_in, const int* in_sizes, int n_in,
                              void* d_out, int out_size) {
    const int*   ids = (const int*)d_in[0];
    const int*   src = (const int*)d_in[1];
    const float* h0  = (const float*)d_in[2];
    const float* c0  = (const float*)d_in[3];
    const float* ctx = (const float*)d_in[4];
    int base = (in_sizes[5] <= 4) ? 6 : 5;
    const float* emb = (const float*)d_in[base + 0];
    const float* Wih = (const float*)d_in[base + 1];
    const float* bih = (const float*)d_in[base + 2];
    const float* Whh = (const float*)d_in[base + 3];
    const float* bhh = (const float*)d_in[base + 4];
    const float* Wa  = (const float*)d_in[base + 5];
    const float* ba  = (const float*)d_in[base + 6];
    const float* Wo  = (const float*)d_in[base + 7];
    const float* bo  = (const float*)d_in[base + 8];
    const float* Wv  = (const float*)d_in[base + 9];
    const float* bv  = (const float*)d_in[base + 10];
    const float* Wg  = (const float*)d_in[base + 11];
    const float* bg  = (const float*)d_in[base + 12];
    float* out = (float*)d_out;

    float *px, *pxw, *pout, *pgamma, *pattn, *pcat2, *phatt, *plogits, *psum;
    __nv_bfloat16 *phattb, *pwvb, *pwi1p, *pxp, *pcat2p, *pwop;
    cudaGetSymbolAddress((void**)&px,      g_x);
    cudaGetSymbolAddress((void**)&pxw,     g_xw);
    cudaGetSymbolAddress((void**)&pout,    g_out);
    cudaGetSymbolAddress((void**)&pgamma,  g_gamma);
    cudaGetSymbolAddress((void**)&pattn,   g_attn);
    cudaGetSymbolAddress((void**)&pcat2,   g_cat2);
    cudaGetSymbolAddress((void**)&phatt,   g_hatt);
    cudaGetSymbolAddress((void**)&plogits, g_logits);
    cudaGetSymbolAddress((void**)&psum,    g_sumpart);
    cudaGetSymbolAddress((void**)&phattb,  g_hattb);
    cudaGetSymbolAddress((void**)&pwvb,    g_wvb);
    cudaGetSymbolAddress((void**)&pwi1p,   g_wi1p);
    cudaGetSymbolAddress((void**)&pxp,     g_xp);
    cudaGetSymbolAddress((void**)&pcat2p,  g_cat2p);
    cudaGetSymbolAddress((void**)&pwop,    g_wop);

    const int SMEM_PERSIST = (512 * 16 + 1024 * 16 + 1024 * 32) * 4;  // 229376 B
    cudaFuncSetAttribute(k_persist, cudaFuncAttributeMaxDynamicSharedMemorySize, SMEM_PERSIST);

    // 1. embedding + weight converts/packs + h0 transpose
    k_embed<<<512, 256>>>(ids, emb);
    k_cvt<<<25000, 256>>>(Wv, pwvb, VV * HH / 4);
    k_pack3<<<4096, 256>>>(Wih, pwi1p, HH, 2048 * HH, 0);      // [hi|hi|lo]
    k_pack3<<<2048, 256>>>(px, pxp, HH, TB * HH, 1);           // [hi|lo|hi]
    k_pack3<<<2048, 256>>>(Wo, pwop, 2 * HH, HH * 2 * HH, 0);  // [hi|hi|lo]
    k_tr<<<64, 512>>>(h0);

    // 2. xw hoist via split-bf16 HMMA (K=1536, fp32-class accuracy)
    k_hgemm<<<dim3(8, 16), 256>>>(pwi1p, pxp, nullptr, pxw,
                                  3 * HH, TB, TB, 0, nullptr, 0, nullptr);

    // 3. persistent 2-layer LSTM (f32x2 packed FMA, 1 gridbar/step)
    k_persist<<<NBLK, 512, SMEM_PERSIST>>>(Whh, Wih + 2048 * 512, Whh + 2048 * 512,
                                           bih, bhh, c0);

    // 4. gamma = out @ Wa^T + ba (fp32)
    k_gemm<<<dim3(8, 16, 1), 256>>>(TB, HH, HH, pout, HH, 0,
                                    Wa, HH, 1, 0, ba, pgamma, HH, 0, 0);

    // 5. attn logits per b: gamma @ contexts[b]^T (fp32)
    k_gemm<<<dim3(7, 1, 32), 256>>>(BBATCH, SS, HH,
                                    pgamma, BBATCH * HH, HH,
                                    ctx, HH, 1, (long long)SS * HH,
                                    nullptr, pattn, BBATCH * SS, SS, 0);

    // 6. softmax over s
    k_attnsoftmax<<<TB, 128>>>();

    // 7. c_t = attn @ contexts[b] (fp32)
    k_gemm<<<dim3(8, 1, 32), 256>>>(BBATCH, HH, SS,
                                    pattn, BBATCH * SS, SS,
                                    ctx, 1, HH, (long long)SS * HH,
                                    nullptr, pcat2, BBATCH * 2 * HH, 2 * HH, 0);

    // 8. h_att = tanh(cat2 @ Wo^T + bo) via split-bf16 HMMA; bf16 copy fused
    k_pack3<<<4096, 256>>>(pcat2, pcat2p, 2 * HH, TB * 2 * HH, 1);  // [hi|lo|hi]
    k_hgemm<<<dim3(4, 8), 256>>>(pcat2p, pwop, bo, phatt,
                                 3 * 2 * HH, HH, HH, 1, nullptr, 0, phattb);

    // 9. p_gen
    k_pgen<<<128, 256>>>(Wg, bg);

    // 10. vocab logits via bf16 HMMA with fused exp-sum partials
    k_hgemm<<<dim3(NBX_V, 8), 256>>>(phattb, pwvb, bv, plogits,
                                     HH, VV, VV, 0, psum, NBX_V, nullptr);
    k_rowsum<<<TB, 128>>>();

    // 11. scores + copy fixup
    k_scores<<<dim3(49, TB, 1), 256>>>(out);
    k_fixup<<<TB, 512>>>(src, out);

    // 12. final h, c
    k_hc<<<64, 256>>>(out);
}